// round 1
// baseline (speedup 1.0000x reference)
#include <cuda_runtime.h>
#include <cuda_bf16.h>
#include <math.h>

#define Bv 4
#define Nv 1024
#define Dv 512
#define Hv 8
#define DHv 64
#define TCv 512
#define ABv 16

// ---------------- scratch (static device allocations; no cudaMalloc) -------
__device__ float g_scale[Bv * Dv];
__device__ float g_shift[Bv * Dv];
__device__ float g_xn[(size_t)Bv * Nv * Dv];                // 8 MB
__device__ float g_q[(size_t)Bv * Hv * Nv * DHv];           // 8 MB
__device__ float g_k[(size_t)Bv * Hv * Nv * DHv];           // 8 MB
__device__ float g_v[(size_t)Bv * Hv * Nv * DHv];           // 8 MB
__device__ float g_sim[(size_t)Bv * Hv * Nv * Nv];          // 128 MB
__device__ float g_att[(size_t)Bv * Nv * Hv * DHv];         // 8 MB

// ---------------- K1: FiLM params: t = silu(time) @ Wt^T + bt --------------
__global__ void film_kernel(const float* __restrict__ time,
                            const float* __restrict__ Wt,
                            const float* __restrict__ bt) {
    int b = blockIdx.x;
    __shared__ float st[TCv];
    for (int i = threadIdx.x; i < TCv; i += blockDim.x) {
        float v = time[b * TCv + i];
        st[i] = v / (1.f + __expf(-v));
    }
    __syncthreads();
    for (int o = threadIdx.x; o < 2 * Dv; o += blockDim.x) {
        const float* w = Wt + (size_t)o * TCv;
        float acc = bt[o];
        #pragma unroll 8
        for (int t = 0; t < TCv; t++) acc = fmaf(st[t], w[t], acc);
        if (o < Dv) g_scale[b * Dv + o] = acc;
        else        g_shift[b * Dv + (o - Dv)] = acc;
    }
}

// ---------------- K2: LayerNorm + FiLM + seq mask -> g_xn ------------------
__global__ void ln_film_kernel(const float* __restrict__ x,
                               const float* __restrict__ seq_mask,
                               const float* __restrict__ gamma) {
    int row = blockIdx.x;                 // b*N + n
    int b = row >> 10;
    const float* xr = x + (size_t)row * Dv;
    int tid = threadIdx.x;                // blockDim = 128
    float s = 0.f, ss = 0.f;
    #pragma unroll
    for (int u = 0; u < 4; u++) {
        float v = xr[tid + u * 128];
        s += v; ss += v * v;
    }
    #pragma unroll
    for (int o = 16; o > 0; o >>= 1) {
        s  += __shfl_xor_sync(~0u, s, o);
        ss += __shfl_xor_sync(~0u, ss, o);
    }
    __shared__ float shs[4], shss[4];
    if ((tid & 31) == 0) { shs[tid >> 5] = s; shss[tid >> 5] = ss; }
    __syncthreads();
    s  = shs[0] + shs[1] + shs[2] + shs[3];
    ss = shss[0] + shss[1] + shss[2] + shss[3];
    float mu  = s * (1.f / Dv);
    float var = ss * (1.f / Dv) - mu * mu;
    float inv = rsqrtf(var + 1e-5f);
    float m = seq_mask[row];
    float* out = g_xn + (size_t)row * Dv;
    #pragma unroll
    for (int u = 0; u < 4; u++) {
        int d = tid + u * 128;
        float v = (xr[d] - mu) * inv * gamma[d];
        out[d] = (v * (g_scale[b * Dv + d] + 1.f) + g_shift[b * Dv + d]) * m;
    }
}

// ---------------- K3: QKV projections (tiled fp32 GEMM) --------------------
// global cols 0..511: q = xn @ Wq^T ; 512..1023: k ; 1024..1535: v (x @ Wkv^T)
__global__ void qkv_kernel(const float* __restrict__ x,
                           const float* __restrict__ Wq,
                           const float* __restrict__ Wkv) {
    int c0 = blockIdx.x * 64;     // 24 col tiles
    int m0 = blockIdx.y * 64;     // 64 row tiles
    int seg = c0 >> 9;            // 0:q 1:k 2:v
    const float* A = (seg == 0) ? g_xn : x;
    const float* W = (seg == 0) ? (Wq + (size_t)c0 * Dv)
                                : (Wkv + (size_t)(c0 - 512) * Dv);
    __shared__ float As[16][65], Ws[16][65];
    int tid = threadIdx.x;
    int tx = tid & 15, ty = tid >> 4;
    int lr = tid >> 2, lc = (tid & 3) << 2;
    float acc[4][4] = {};
    for (int kk = 0; kk < Dv; kk += 16) {
        float4 aa = *(const float4*)(A + (size_t)(m0 + lr) * Dv + kk + lc);
        As[lc + 0][lr] = aa.x; As[lc + 1][lr] = aa.y;
        As[lc + 2][lr] = aa.z; As[lc + 3][lr] = aa.w;
        float4 wa = *(const float4*)(W + (size_t)lr * Dv + kk + lc);
        Ws[lc + 0][lr] = wa.x; Ws[lc + 1][lr] = wa.y;
        Ws[lc + 2][lr] = wa.z; Ws[lc + 3][lr] = wa.w;
        __syncthreads();
        #pragma unroll
        for (int t = 0; t < 16; t++) {
            float af[4], bf[4];
            #pragma unroll
            for (int u = 0; u < 4; u++) { af[u] = As[t][ty * 4 + u]; bf[u] = Ws[t][tx * 4 + u]; }
            #pragma unroll
            for (int i = 0; i < 4; i++)
                #pragma unroll
                for (int j = 0; j < 4; j++) acc[i][j] = fmaf(af[i], bf[j], acc[i][j]);
        }
        __syncthreads();
    }
    float* dst = (seg == 0) ? g_q : (seg == 1) ? g_k : g_v;
    #pragma unroll
    for (int i = 0; i < 4; i++) {
        int row = m0 + ty * 4 + i;
        int b = row >> 10, n = row & 1023;
        #pragma unroll
        for (int j = 0; j < 4; j++) {
            int gl = (c0 & 511) + tx * 4 + j;
            int h = gl >> 6, dh = gl & 63;
            dst[(((size_t)b * Hv + h) * Nv + n) * DHv + dh] = acc[i][j];
        }
    }
}

// ---------------- K4: bias projection + mask penalty -> g_sim --------------
__global__ void bias_kernel(const float* __restrict__ ab,
                            const float* __restrict__ seq_mask,
                            const float* __restrict__ Wb,
                            const float* __restrict__ bb) {
    __shared__ float wb[Hv * ABv];
    __shared__ float sbb[Hv];
    if (threadIdx.x < Hv * ABv) wb[threadIdx.x] = Wb[threadIdx.x];
    if (threadIdx.x < Hv) sbb[threadIdx.x] = bb[threadIdx.x];
    __syncthreads();
    size_t idx = (size_t)blockIdx.x * blockDim.x + threadIdx.x;
    if (idx >= (size_t)Bv * Nv * Nv) return;
    int j = (int)(idx & (Nv - 1));
    int i = (int)((idx >> 10) & (Nv - 1));
    int b = (int)(idx >> 20);
    const float* p = ab + ((size_t)b * ABv * Nv + i) * Nv + j;
    float a[ABv];
    #pragma unroll
    for (int aa = 0; aa < ABv; aa++) a[aa] = p[(size_t)aa * Nv * Nv];
    float pen = -(1.f - seq_mask[b * Nv + i] * seq_mask[b * Nv + j]) * 1e6f;
    #pragma unroll
    for (int h = 0; h < Hv; h++) {
        float acc = sbb[h];
        #pragma unroll
        for (int aa = 0; aa < ABv; aa++) acc = fmaf(a[aa], wb[h * ABv + aa], acc);
        g_sim[(((size_t)b * Hv + h) * Nv + i) * Nv + j] = acc + pen;
    }
}

// ---------------- K5: sim += scale * q @ k^T -------------------------------
__global__ void qk_kernel() {
    int bh = blockIdx.z;
    int i0 = blockIdx.y * 64, j0 = blockIdx.x * 64;
    const float* q = g_q + (size_t)bh * Nv * DHv;
    const float* k = g_k + (size_t)bh * Nv * DHv;
    __shared__ float Qs[16][65], Ks[16][65];
    int tid = threadIdx.x;
    int tx = tid & 15, ty = tid >> 4;
    int lr = tid >> 2, lc = (tid & 3) << 2;
    float acc[4][4] = {};
    for (int kk = 0; kk < DHv; kk += 16) {
        float4 qa = *(const float4*)(q + (size_t)(i0 + lr) * DHv + kk + lc);
        Qs[lc + 0][lr] = qa.x; Qs[lc + 1][lr] = qa.y;
        Qs[lc + 2][lr] = qa.z; Qs[lc + 3][lr] = qa.w;
        float4 ka = *(const float4*)(k + (size_t)(j0 + lr) * DHv + kk + lc);
        Ks[lc + 0][lr] = ka.x; Ks[lc + 1][lr] = ka.y;
        Ks[lc + 2][lr] = ka.z; Ks[lc + 3][lr] = ka.w;
        __syncthreads();
        #pragma unroll
        for (int t = 0; t < 16; t++) {
            float af[4], bf[4];
            #pragma unroll
            for (int u = 0; u < 4; u++) { af[u] = Qs[t][ty * 4 + u]; bf[u] = Ks[t][tx * 4 + u]; }
            #pragma unroll
            for (int i = 0; i < 4; i++)
                #pragma unroll
                for (int j = 0; j < 4; j++) acc[i][j] = fmaf(af[i], bf[j], acc[i][j]);
        }
        __syncthreads();
    }
    float* simp = g_sim + ((size_t)bh * Nv + i0) * Nv + j0;
    const float sc = 0.125f;  // DH^-0.5
    #pragma unroll
    for (int i = 0; i < 4; i++)
        #pragma unroll
        for (int j = 0; j < 4; j++) {
            size_t o = (size_t)(ty * 4 + i) * Nv + tx * 4 + j;
            simp[o] += acc[i][j] * sc;
        }
}

// ---------------- K6: row softmax in place ---------------------------------
__global__ void softmax_kernel() {
    size_t row = blockIdx.x;
    float* p = g_sim + row * Nv;
    int tid = threadIdx.x;  // 256
    float vals[4];
    float mx = -3.4e38f;
    #pragma unroll
    for (int u = 0; u < 4; u++) { vals[u] = p[tid + u * 256]; mx = fmaxf(mx, vals[u]); }
    #pragma unroll
    for (int o = 16; o > 0; o >>= 1) mx = fmaxf(mx, __shfl_xor_sync(~0u, mx, o));
    __shared__ float sh[8];
    if ((tid & 31) == 0) sh[tid >> 5] = mx;
    __syncthreads();
    mx = sh[0];
    #pragma unroll
    for (int w = 1; w < 8; w++) mx = fmaxf(mx, sh[w]);
    float sum = 0.f;
    #pragma unroll
    for (int u = 0; u < 4; u++) { vals[u] = __expf(vals[u] - mx); sum += vals[u]; }
    #pragma unroll
    for (int o = 16; o > 0; o >>= 1) sum += __shfl_xor_sync(~0u, sum, o);
    __shared__ float sh2[8];
    if ((tid & 31) == 0) sh2[tid >> 5] = sum;
    __syncthreads();
    sum = sh2[0] + sh2[1] + sh2[2] + sh2[3] + sh2[4] + sh2[5] + sh2[6] + sh2[7];
    float inv = 1.f / sum;
    #pragma unroll
    for (int u = 0; u < 4; u++) p[tid + u * 256] = vals[u] * inv;
}

// ---------------- K7: out = attn @ v ---------------------------------------
__global__ void av_kernel() {
    int bh = blockIdx.y;
    int i0 = blockIdx.x * 64;
    int b = bh >> 3, h = bh & 7;
    const float* attn = g_sim + (size_t)bh * Nv * Nv;
    const float* v = g_v + (size_t)bh * Nv * DHv;
    __shared__ float As[16][65], Vs[16][64];
    int tid = threadIdx.x;
    int tx = tid & 15, ty = tid >> 4;
    int lr = tid >> 2, lc = (tid & 3) << 2;
    int vr = tid >> 4, vc = (tid & 15) << 2;
    float acc[4][4] = {};
    for (int kk = 0; kk < Nv; kk += 16) {
        float4 aa = *(const float4*)(attn + (size_t)(i0 + lr) * Nv + kk + lc);
        As[lc + 0][lr] = aa.x; As[lc + 1][lr] = aa.y;
        As[lc + 2][lr] = aa.z; As[lc + 3][lr] = aa.w;
        *(float4*)&Vs[vr][vc] = *(const float4*)(v + (size_t)(kk + vr) * DHv + vc);
        __syncthreads();
        #pragma unroll
        for (int t = 0; t < 16; t++) {
            float af[4], bf[4];
            #pragma unroll
            for (int u = 0; u < 4; u++) { af[u] = As[t][ty * 4 + u]; bf[u] = Vs[t][tx * 4 + u]; }
            #pragma unroll
            for (int i = 0; i < 4; i++)
                #pragma unroll
                for (int j = 0; j < 4; j++) acc[i][j] = fmaf(af[i], bf[j], acc[i][j]);
        }
        __syncthreads();
    }
    #pragma unroll
    for (int i = 0; i < 4; i++) {
        int n = i0 + ty * 4 + i;
        #pragma unroll
        for (int j = 0; j < 4; j++) {
            int dh = tx * 4 + j;
            g_att[((size_t)b * Nv + n) * (Hv * DHv) + h * DHv + dh] = acc[i][j];
        }
    }
}

// ---------------- K8: final out = att @ Wo^T, * seq_mask -------------------
__global__ void out_kernel(const float* __restrict__ Wo,
                           const float* __restrict__ seq_mask,
                           float* __restrict__ out) {
    int c0 = blockIdx.x * 64;   // 8 tiles
    int m0 = blockIdx.y * 64;   // 64 tiles
    __shared__ float As[16][65], Ws[16][65];
    int tid = threadIdx.x;
    int tx = tid & 15, ty = tid >> 4;
    int lr = tid >> 2, lc = (tid & 3) << 2;
    float acc[4][4] = {};
    const int K = Hv * DHv;  // 512
    for (int kk = 0; kk < K; kk += 16) {
        float4 aa = *(const float4*)(g_att + (size_t)(m0 + lr) * K + kk + lc);
        As[lc + 0][lr] = aa.x; As[lc + 1][lr] = aa.y;
        As[lc + 2][lr] = aa.z; As[lc + 3][lr] = aa.w;
        float4 wa = *(const float4*)(Wo + (size_t)(c0 + lr) * K + kk + lc);
        Ws[lc + 0][lr] = wa.x; Ws[lc + 1][lr] = wa.y;
        Ws[lc + 2][lr] = wa.z; Ws[lc + 3][lr] = wa.w;
        __syncthreads();
        #pragma unroll
        for (int t = 0; t < 16; t++) {
            float af[4], bf[4];
            #pragma unroll
            for (int u = 0; u < 4; u++) { af[u] = As[t][ty * 4 + u]; bf[u] = Ws[t][tx * 4 + u]; }
            #pragma unroll
            for (int i = 0; i < 4; i++)
                #pragma unroll
                for (int j = 0; j < 4; j++) acc[i][j] = fmaf(af[i], bf[j], acc[i][j]);
        }
        __syncthreads();
    }
    #pragma unroll
    for (int i = 0; i < 4; i++) {
        int row = m0 + ty * 4 + i;
        float m = seq_mask[row];
        #pragma unroll
        for (int j = 0; j < 4; j++)
            out[(size_t)row * Dv + c0 + tx * 4 + j] = acc[i][j] * m;
    }
}

// ---------------- launch ---------------------------------------------------
extern "C" void kernel_launch(void* const* d_in, const int* in_sizes, int n_in,
                              void* d_out, int out_size) {
    const float* x        = (const float*)d_in[0];
    const float* time_in  = (const float*)d_in[1];
    const float* ab       = (const float*)d_in[2];
    const float* seq_mask = (const float*)d_in[3];
    const float* gamma    = (const float*)d_in[4];
    const float* Wt       = (const float*)d_in[5];
    const float* bt       = (const float*)d_in[6];
    const float* Wq       = (const float*)d_in[7];
    const float* Wkv      = (const float*)d_in[8];
    const float* Wo       = (const float*)d_in[9];
    const float* Wb       = (const float*)d_in[10];
    const float* bb       = (const float*)d_in[11];
    float* out = (float*)d_out;

    film_kernel<<<Bv, 256>>>(time_in, Wt, bt);
    ln_film_kernel<<<Bv * Nv, 128>>>(x, seq_mask, gamma);
    qkv_kernel<<<dim3(24, 64), 256>>>(x, Wq, Wkv);
    bias_kernel<<<(Bv * Nv * Nv) / 256, 256>>>(ab, seq_mask, Wb, bb);
    qk_kernel<<<dim3(16, 16, Bv * Hv), 256>>>();
    softmax_kernel<<<Bv * Hv * Nv, 256>>>();
    av_kernel<<<dim3(16, Bv * Hv), 256>>>();
    out_kernel<<<dim3(8, 64), 256>>>(Wo, seq_mask, out);
}

// round 2
// speedup vs baseline: 1.2458x; 1.2458x over previous
#include <cuda_runtime.h>
#include <cuda_bf16.h>
#include <math.h>

#define Bv 4
#define Nv 1024
#define Dv 512
#define Hv 8
#define DHv 64
#define TCv 512
#define ABv 16

// ---------------- scratch -------------------------------------------------
__device__ float g_scale[Bv * Dv];
__device__ float g_shift[Bv * Dv];
__device__ float g_xn[(size_t)Bv * Nv * Dv];                // 8 MB
__device__ float g_q[(size_t)Bv * Hv * Nv * DHv];           // 8 MB (pre-scaled)
__device__ float g_k[(size_t)Bv * Hv * Nv * DHv];           // 8 MB
__device__ float g_v[(size_t)Bv * Hv * Nv * DHv];           // 8 MB
__device__ float g_sim[(size_t)Bv * Hv * Nv * Nv];          // 128 MB
__device__ float g_att[(size_t)Bv * Nv * Hv * DHv];         // 8 MB

// ---------------- f32x2 helpers -------------------------------------------
__device__ __forceinline__ unsigned long long dup2(float v) {
    unsigned long long r;
    asm("mov.b64 %0, {%1, %1};" : "=l"(r) : "f"(v));
    return r;
}
__device__ __forceinline__ void ffma2(unsigned long long& acc,
                                      unsigned long long a,
                                      unsigned long long b) {
    asm("fma.rn.f32x2 %0, %1, %2, %0;" : "+l"(acc) : "l"(a), "l"(b));
}
__device__ __forceinline__ void fmul2(unsigned long long& acc, unsigned long long a) {
    asm("mul.rn.f32x2 %0, %0, %1;" : "+l"(acc) : "l"(a));
}
__device__ __forceinline__ float2 unp2(unsigned long long v) {
    float2 f;
    asm("mov.b64 {%0, %1}, %2;" : "=f"(f.x), "=f"(f.y) : "l"(v));
    return f;
}

// ---------------- K1: FiLM params ------------------------------------------
__global__ void film_kernel(const float* __restrict__ time,
                            const float* __restrict__ Wt,
                            const float* __restrict__ bt) {
    int b = blockIdx.x;
    int o = blockIdx.y * 128 + threadIdx.x;   // 0..1023
    __shared__ float st[TCv];
    for (int i = threadIdx.x; i < TCv; i += 128) {
        float v = time[b * TCv + i];
        st[i] = v / (1.f + __expf(-v));
    }
    __syncthreads();
    const float* w = Wt + (size_t)o * TCv;
    float acc = bt[o];
    #pragma unroll 8
    for (int t = 0; t < TCv; t++) acc = fmaf(st[t], w[t], acc);
    if (o < Dv) g_scale[b * Dv + o] = acc;
    else        g_shift[b * Dv + (o - Dv)] = acc;
}

// ---------------- K2: LayerNorm + FiLM + seq mask -> g_xn ------------------
__global__ void ln_film_kernel(const float* __restrict__ x,
                               const float* __restrict__ seq_mask,
                               const float* __restrict__ gamma) {
    int row = blockIdx.x;
    int b = row >> 10;
    const float* xr = x + (size_t)row * Dv;
    int tid = threadIdx.x;                // 128
    float s = 0.f, ss = 0.f;
    #pragma unroll
    for (int u = 0; u < 4; u++) {
        float v = xr[tid + u * 128];
        s += v; ss += v * v;
    }
    #pragma unroll
    for (int o = 16; o > 0; o >>= 1) {
        s  += __shfl_xor_sync(~0u, s, o);
        ss += __shfl_xor_sync(~0u, ss, o);
    }
    __shared__ float shs[4], shss[4];
    if ((tid & 31) == 0) { shs[tid >> 5] = s; shss[tid >> 5] = ss; }
    __syncthreads();
    s  = shs[0] + shs[1] + shs[2] + shs[3];
    ss = shss[0] + shss[1] + shss[2] + shss[3];
    float mu  = s * (1.f / Dv);
    float var = ss * (1.f / Dv) - mu * mu;
    float inv = rsqrtf(var + 1e-5f);
    float m = seq_mask[row];
    float* out = g_xn + (size_t)row * Dv;
    #pragma unroll
    for (int u = 0; u < 4; u++) {
        int d = tid + u * 128;
        float v = (xr[d] - mu) * inv * gamma[d];
        out[d] = (v * (g_scale[b * Dv + d] + 1.f) + g_shift[b * Dv + d]) * m;
    }
}

// ---------------- K3: QKV projections (f32x2 GEMM) -------------------------
__global__ void qkv_kernel(const float* __restrict__ x,
                           const float* __restrict__ Wq,
                           const float* __restrict__ Wkv) {
    int c0 = blockIdx.x * 64;     // 24 col tiles (0..1535)
    int m0 = blockIdx.y * 64;
    int seg = c0 >> 9;            // 0:q 1:k 2:v
    const float* A = (seg == 0) ? g_xn : x;
    const float* W = (seg == 0) ? (Wq + (size_t)c0 * Dv)
                                : (Wkv + (size_t)(c0 - 512) * Dv);
    __shared__ float As[16 * 68], Ws[16 * 68];
    int tid = threadIdx.x;
    int tx = tid & 15, ty = tid >> 4;
    int lr = tid >> 2, lc = (tid & 3) << 2;
    unsigned long long acc2[4][2] = {};
    for (int kk = 0; kk < Dv; kk += 16) {
        float4 aa = *(const float4*)(A + (size_t)(m0 + lr) * Dv + kk + lc);
        As[(lc + 0) * 68 + lr] = aa.x; As[(lc + 1) * 68 + lr] = aa.y;
        As[(lc + 2) * 68 + lr] = aa.z; As[(lc + 3) * 68 + lr] = aa.w;
        float4 wa = *(const float4*)(W + (size_t)lr * Dv + kk + lc);
        Ws[(lc + 0) * 68 + lr] = wa.x; Ws[(lc + 1) * 68 + lr] = wa.y;
        Ws[(lc + 2) * 68 + lr] = wa.z; Ws[(lc + 3) * 68 + lr] = wa.w;
        __syncthreads();
        #pragma unroll
        for (int t = 0; t < 16; t++) {
            float4 af = *(const float4*)&As[t * 68 + ty * 4];
            ulonglong2 bp = *(const ulonglong2*)&Ws[t * 68 + tx * 4];
            unsigned long long a0 = dup2(af.x), a1 = dup2(af.y),
                               a2v = dup2(af.z), a3 = dup2(af.w);
            ffma2(acc2[0][0], a0, bp.x); ffma2(acc2[0][1], a0, bp.y);
            ffma2(acc2[1][0], a1, bp.x); ffma2(acc2[1][1], a1, bp.y);
            ffma2(acc2[2][0], a2v, bp.x); ffma2(acc2[2][1], a2v, bp.y);
            ffma2(acc2[3][0], a3, bp.x); ffma2(acc2[3][1], a3, bp.y);
        }
        __syncthreads();
    }
    float* dst = (seg == 0) ? g_q : (seg == 1) ? g_k : g_v;
    float qs = (seg == 0) ? 0.125f : 1.0f;
    #pragma unroll
    for (int i = 0; i < 4; i++) {
        int row = m0 + ty * 4 + i;
        int b = row >> 10, n = row & 1023;
        float2 lo = unp2(acc2[i][0]), hi = unp2(acc2[i][1]);
        float vals[4] = {lo.x * qs, lo.y * qs, hi.x * qs, hi.y * qs};
        #pragma unroll
        for (int j = 0; j < 4; j++) {
            int gl = (c0 & 511) + tx * 4 + j;
            int h = gl >> 6, dh = gl & 63;
            dst[(((size_t)b * Hv + h) * Nv + n) * DHv + dh] = vals[j];
        }
    }
}

// ---------------- K4: fused QK (all heads) + bias proj + pen -> sim --------
// grid (16 j, 16 i, 4 b), 256 threads, dynamic smem 174080 B
__global__ void qk_bias_kernel(const float* __restrict__ ab,
                               const float* __restrict__ seq_mask,
                               const float* __restrict__ Wb,
                               const float* __restrict__ bb) {
    extern __shared__ float sm[];
    float* S8 = sm;                     // 8 * 64 * 68
    float* Qt = sm + 8 * 64 * 68;       // 64 * 68  [k][i]
    float* Kt = Qt + 64 * 68;           // 64 * 68  [k][j]
    __shared__ float wb[Hv * ABv];
    __shared__ float sbb[Hv];

    int tid = threadIdx.x;
    int j0 = blockIdx.x * 64, i0 = blockIdx.y * 64, b = blockIdx.z;
    if (tid < Hv * ABv) wb[tid] = Wb[tid];
    if (tid < Hv) sbb[tid] = bb[tid];

    int tx = tid & 15, ty = tid >> 4;

    for (int h = 0; h < Hv; h++) {
        const float* qp = g_q + ((size_t)(b * Hv + h) * Nv + i0) * DHv;
        const float* kp = g_k + ((size_t)(b * Hv + h) * Nv + j0) * DHv;
        #pragma unroll
        for (int u = 0; u < 4; u++) {
            int idx = u * 256 + tid;
            int r = idx >> 4, c4 = (idx & 15) << 2;
            float4 qa = *(const float4*)(qp + r * 64 + c4);
            Qt[(c4 + 0) * 68 + r] = qa.x; Qt[(c4 + 1) * 68 + r] = qa.y;
            Qt[(c4 + 2) * 68 + r] = qa.z; Qt[(c4 + 3) * 68 + r] = qa.w;
            float4 ka = *(const float4*)(kp + r * 64 + c4);
            Kt[(c4 + 0) * 68 + r] = ka.x; Kt[(c4 + 1) * 68 + r] = ka.y;
            Kt[(c4 + 2) * 68 + r] = ka.z; Kt[(c4 + 3) * 68 + r] = ka.w;
        }
        __syncthreads();
        unsigned long long acc2[4][2] = {};
        #pragma unroll 8
        for (int k = 0; k < 64; k++) {
            float4 af = *(const float4*)&Qt[k * 68 + ty * 4];
            ulonglong2 bp = *(const ulonglong2*)&Kt[k * 68 + tx * 4];
            unsigned long long a0 = dup2(af.x), a1 = dup2(af.y),
                               a2v = dup2(af.z), a3 = dup2(af.w);
            ffma2(acc2[0][0], a0, bp.x); ffma2(acc2[0][1], a0, bp.y);
            ffma2(acc2[1][0], a1, bp.x); ffma2(acc2[1][1], a1, bp.y);
            ffma2(acc2[2][0], a2v, bp.x); ffma2(acc2[2][1], a2v, bp.y);
            ffma2(acc2[3][0], a3, bp.x); ffma2(acc2[3][1], a3, bp.y);
        }
        #pragma unroll
        for (int i = 0; i < 4; i++) {
            float2 lo = unp2(acc2[i][0]), hi = unp2(acc2[i][1]);
            *(float4*)&S8[h * 4352 + (ty * 4 + i) * 68 + tx * 4] =
                make_float4(lo.x, lo.y, hi.x, hi.y);
        }
        __syncthreads();
    }

    // phase 2: bias projection + penalty + write sim
    #pragma unroll 4
    for (int u = 0; u < 16; u++) {
        int pos = u * 256 + tid;
        int i = pos >> 6, j = pos & 63;
        float smi = seq_mask[b * Nv + i0 + i];
        float smj = seq_mask[b * Nv + j0 + j];
        float pen = -(1.f - smi * smj) * 1e6f;
        float a[ABv];
        const float* p = ab + ((size_t)b * ABv * Nv + (i0 + i)) * Nv + j0 + j;
        #pragma unroll
        for (int aa = 0; aa < ABv; aa++) a[aa] = p[(size_t)aa * Nv * Nv];
        #pragma unroll
        for (int h = 0; h < Hv; h++) {
            float acc = sbb[h] + pen + S8[h * 4352 + i * 68 + j];
            #pragma unroll
            for (int aa = 0; aa < ABv; aa++) acc = fmaf(a[aa], wb[h * ABv + aa], acc);
            g_sim[(((size_t)b * Hv + h) * Nv + i0 + i) * Nv + j0 + j] = acc;
        }
    }
}

// ---------------- K5: fused flash softmax + AV -> g_att --------------------
// grid (16 i-tiles, 32 bh), 256 threads
__global__ void flash_av_kernel() {
    __shared__ float Pt[64 * 68];   // [j][i] transposed
    __shared__ float Vs[64 * 68];   // [j][d]
    __shared__ float m_sh[64], l_sh[64], al_sh[64];
    int tid = threadIdx.x;
    int i0 = blockIdx.x * 64;
    int bh = blockIdx.y;
    int b = bh >> 3, h = bh & 7;
    const float* sim = g_sim + ((size_t)bh * Nv + i0) * Nv;
    const float* v = g_v + (size_t)bh * Nv * DHv;
    if (tid < 64) { m_sh[tid] = -3.0e38f; l_sh[tid] = 0.f; }
    int tx = tid & 15, ty = tid >> 4;
    unsigned long long accO[4][2] = {};

    for (int jt = 0; jt < 16; jt++) {
        int j0 = jt * 64;
        __syncthreads();
        #pragma unroll
        for (int u = 0; u < 4; u++) {
            int idx = u * 256 + tid;
            int r = idx >> 4, c4 = (idx & 15) << 2;
            float4 sv = *(const float4*)(sim + (size_t)r * Nv + j0 + c4);
            Pt[(c4 + 0) * 68 + r] = sv.x; Pt[(c4 + 1) * 68 + r] = sv.y;
            Pt[(c4 + 2) * 68 + r] = sv.z; Pt[(c4 + 3) * 68 + r] = sv.w;
            float4 vv = *(const float4*)(v + (size_t)(j0 + r) * DHv + c4);
            *(float4*)&Vs[r * 68 + c4] = vv;
        }
        __syncthreads();
        if (tid < 64) {
            float mx = -3.0e38f;
            #pragma unroll 8
            for (int j = 0; j < 64; j++) mx = fmaxf(mx, Pt[j * 68 + tid]);
            float mo = m_sh[tid];
            float mn = fmaxf(mo, mx);
            float al = __expf(mo - mn);
            m_sh[tid] = mn; al_sh[tid] = al;
            l_sh[tid] *= al;
        }
        __syncthreads();
        // rescale O
        #pragma unroll
        for (int i = 0; i < 4; i++) {
            unsigned long long a2 = dup2(al_sh[ty * 4 + i]);
            fmul2(accO[i][0], a2); fmul2(accO[i][1], a2);
        }
        // exponentiate in place
        #pragma unroll
        for (int u = 0; u < 16; u++) {
            int idx = u * 256 + tid;
            int jj = idx >> 6, rr = idx & 63;
            Pt[jj * 68 + rr] = __expf(Pt[jj * 68 + rr] - m_sh[rr]);
        }
        __syncthreads();
        if (tid < 64) {
            float s = 0.f;
            #pragma unroll 8
            for (int j = 0; j < 64; j++) s += Pt[j * 68 + tid];
            l_sh[tid] += s;
        }
        #pragma unroll 8
        for (int k = 0; k < 64; k++) {
            float4 af = *(const float4*)&Pt[k * 68 + ty * 4];
            ulonglong2 bp = *(const ulonglong2*)&Vs[k * 68 + tx * 4];
            unsigned long long a0 = dup2(af.x), a1 = dup2(af.y),
                               a2v = dup2(af.z), a3 = dup2(af.w);
            ffma2(accO[0][0], a0, bp.x); ffma2(accO[0][1], a0, bp.y);
            ffma2(accO[1][0], a1, bp.x); ffma2(accO[1][1], a1, bp.y);
            ffma2(accO[2][0], a2v, bp.x); ffma2(accO[2][1], a2v, bp.y);
            ffma2(accO[3][0], a3, bp.x); ffma2(accO[3][1], a3, bp.y);
        }
    }
    __syncthreads();
    #pragma unroll
    for (int i = 0; i < 4; i++) {
        int row = ty * 4 + i;
        float inv = 1.f / l_sh[row];
        float2 lo = unp2(accO[i][0]), hi = unp2(accO[i][1]);
        *(float4*)&g_att[((size_t)(b * Nv) + i0 + row) * (Hv * DHv) + h * DHv + tx * 4] =
            make_float4(lo.x * inv, lo.y * inv, hi.x * inv, hi.y * inv);
    }
}

// ---------------- K6: final out = att @ Wo^T, * seq_mask -------------------
__global__ void out_kernel(const float* __restrict__ Wo,
                           const float* __restrict__ seq_mask,
                           float* __restrict__ out) {
    int c0 = blockIdx.x * 64;
    int m0 = blockIdx.y * 64;
    __shared__ float As[16 * 68], Ws[16 * 68];
    int tid = threadIdx.x;
    int tx = tid & 15, ty = tid >> 4;
    int lr = tid >> 2, lc = (tid & 3) << 2;
    unsigned long long acc2[4][2] = {};
    const int K = Hv * DHv;
    for (int kk = 0; kk < K; kk += 16) {
        float4 aa = *(const float4*)(g_att + (size_t)(m0 + lr) * K + kk + lc);
        As[(lc + 0) * 68 + lr] = aa.x; As[(lc + 1) * 68 + lr] = aa.y;
        As[(lc + 2) * 68 + lr] = aa.z; As[(lc + 3) * 68 + lr] = aa.w;
        float4 wa = *(const float4*)(Wo + (size_t)(c0 + lr) * K + kk + lc);
        Ws[(lc + 0) * 68 + lr] = wa.x; Ws[(lc + 1) * 68 + lr] = wa.y;
        Ws[(lc + 2) * 68 + lr] = wa.z; Ws[(lc + 3) * 68 + lr] = wa.w;
        __syncthreads();
        #pragma unroll
        for (int t = 0; t < 16; t++) {
            float4 af = *(const float4*)&As[t * 68 + ty * 4];
            ulonglong2 bp = *(const ulonglong2*)&Ws[t * 68 + tx * 4];
            unsigned long long a0 = dup2(af.x), a1 = dup2(af.y),
                               a2v = dup2(af.z), a3 = dup2(af.w);
            ffma2(acc2[0][0], a0, bp.x); ffma2(acc2[0][1], a0, bp.y);
            ffma2(acc2[1][0], a1, bp.x); ffma2(acc2[1][1], a1, bp.y);
            ffma2(acc2[2][0], a2v, bp.x); ffma2(acc2[2][1], a2v, bp.y);
            ffma2(acc2[3][0], a3, bp.x); ffma2(acc2[3][1], a3, bp.y);
        }
        __syncthreads();
    }
    #pragma unroll
    for (int i = 0; i < 4; i++) {
        int row = m0 + ty * 4 + i;
        float m = seq_mask[row];
        float2 lo = unp2(acc2[i][0]), hi = unp2(acc2[i][1]);
        *(float4*)&out[(size_t)row * Dv + c0 + tx * 4] =
            make_float4(lo.x * m, lo.y * m, hi.x * m, hi.y * m);
    }
}

// ---------------- launch ---------------------------------------------------
extern "C" void kernel_launch(void* const* d_in, const int* in_sizes, int n_in,
                              void* d_out, int out_size) {
    const float* x        = (const float*)d_in[0];
    const float* time_in  = (const float*)d_in[1];
    const float* ab       = (const float*)d_in[2];
    const float* seq_mask = (const float*)d_in[3];
    const float* gamma    = (const float*)d_in[4];
    const float* Wt       = (const float*)d_in[5];
    const float* bt       = (const float*)d_in[6];
    const float* Wq       = (const float*)d_in[7];
    const float* Wkv      = (const float*)d_in[8];
    const float* Wo       = (const float*)d_in[9];
    const float* Wb       = (const float*)d_in[10];
    const float* bb       = (const float*)d_in[11];
    float* out = (float*)d_out;

    static bool attr_set = false;
    if (!attr_set) {
        cudaFuncSetAttribute(qk_bias_kernel,
                             cudaFuncAttributeMaxDynamicSharedMemorySize, 174080);
        attr_set = true;
    }

    film_kernel<<<dim3(Bv, 8), 128>>>(time_in, Wt, bt);
    ln_film_kernel<<<Bv * Nv, 128>>>(x, seq_mask, gamma);
    qkv_kernel<<<dim3(24, 64), 256>>>(x, Wq, Wkv);
    qk_bias_kernel<<<dim3(16, 16, Bv), 256, 174080>>>(ab, seq_mask, Wb, bb);
    flash_av_kernel<<<dim3(16, 32), 256>>>();
    out_kernel<<<dim3(8, 64), 256>>>(Wo, seq_mask, out);
}

// round 3
// speedup vs baseline: 1.6411x; 1.3173x over previous
#include <cuda_runtime.h>
#include <cuda_bf16.h>
#include <math.h>

#define Bv 4
#define Nv 1024
#define Dv 512
#define Hv 8
#define DHv 64
#define TCv 512
#define ABv 16

// ---------------- scratch -------------------------------------------------
__device__ float g_scale[Bv * Dv];
__device__ float g_shift[Bv * Dv];
__device__ float g_xn[(size_t)Bv * Nv * Dv];
__device__ float g_q[(size_t)Bv * Hv * Nv * DHv];   // pre-scaled by DH^-0.5
__device__ float g_k[(size_t)Bv * Hv * Nv * DHv];
__device__ float g_v[(size_t)Bv * Hv * Nv * DHv];
__device__ float g_sim[(size_t)Bv * Hv * Nv * Nv];  // bias + penalty only
__device__ float g_att[(size_t)Bv * Nv * Hv * DHv];

// ---------------- f32x2 helpers -------------------------------------------
__device__ __forceinline__ unsigned long long dup2(float v) {
    unsigned long long r;
    asm("mov.b64 %0, {%1, %1};" : "=l"(r) : "f"(v));
    return r;
}
__device__ __forceinline__ void ffma2(unsigned long long& acc,
                                      unsigned long long a,
                                      unsigned long long b) {
    asm("fma.rn.f32x2 %0, %1, %2, %0;" : "+l"(acc) : "l"(a), "l"(b));
}
__device__ __forceinline__ void fmul2(unsigned long long& acc, unsigned long long a) {
    asm("mul.rn.f32x2 %0, %0, %1;" : "+l"(acc) : "l"(a));
}
__device__ __forceinline__ float2 unp2(unsigned long long v) {
    float2 f;
    asm("mov.b64 {%0, %1}, %2;" : "=f"(f.x), "=f"(f.y) : "l"(v));
    return f;
}

// ---------------- K1: FiLM params ------------------------------------------
__global__ void film_kernel(const float* __restrict__ time,
                            const float* __restrict__ Wt,
                            const float* __restrict__ bt) {
    int b = blockIdx.x;
    int o = blockIdx.y * 128 + threadIdx.x;
    __shared__ float st[TCv];
    for (int i = threadIdx.x; i < TCv; i += 128) {
        float v = time[b * TCv + i];
        st[i] = v / (1.f + __expf(-v));
    }
    __syncthreads();
    const float* w = Wt + (size_t)o * TCv;
    float acc = bt[o];
    #pragma unroll 8
    for (int t = 0; t < TCv; t++) acc = fmaf(st[t], w[t], acc);
    if (o < Dv) g_scale[b * Dv + o] = acc;
    else        g_shift[b * Dv + (o - Dv)] = acc;
}

// ---------------- K2: LayerNorm + FiLM + seq mask -> g_xn ------------------
__global__ void ln_film_kernel(const float* __restrict__ x,
                               const float* __restrict__ seq_mask,
                               const float* __restrict__ gamma) {
    int row = blockIdx.x;
    int b = row >> 10;
    const float* xr = x + (size_t)row * Dv;
    int tid = threadIdx.x;
    float s = 0.f, ss = 0.f;
    #pragma unroll
    for (int u = 0; u < 4; u++) {
        float v = xr[tid + u * 128];
        s += v; ss += v * v;
    }
    #pragma unroll
    for (int o = 16; o > 0; o >>= 1) {
        s  += __shfl_xor_sync(~0u, s, o);
        ss += __shfl_xor_sync(~0u, ss, o);
    }
    __shared__ float shs[4], shss[4];
    if ((tid & 31) == 0) { shs[tid >> 5] = s; shss[tid >> 5] = ss; }
    __syncthreads();
    s  = shs[0] + shs[1] + shs[2] + shs[3];
    ss = shss[0] + shss[1] + shss[2] + shss[3];
    float mu  = s * (1.f / Dv);
    float var = ss * (1.f / Dv) - mu * mu;
    float inv = rsqrtf(var + 1e-5f);
    float m = seq_mask[row];
    float* out = g_xn + (size_t)row * Dv;
    #pragma unroll
    for (int u = 0; u < 4; u++) {
        int d = tid + u * 128;
        float v = (xr[d] - mu) * inv * gamma[d];
        out[d] = (v * (g_scale[b * Dv + d] + 1.f) + g_shift[b * Dv + d]) * m;
    }
}

// ---------------- K3: QKV projections (128x128 f32x2 GEMM) -----------------
// Row stride in smem: 136 floats; cols 0..63 at [n], 64..127 at [68+n-64].
__global__ __launch_bounds__(256) void qkv_kernel(const float* __restrict__ x,
                                                  const float* __restrict__ Wq,
                                                  const float* __restrict__ Wkv) {
    int c0 = blockIdx.x * 128;    // 0..1535
    int m0 = blockIdx.y * 128;
    int seg = c0 >> 9;            // 0:q 1:k 2:v
    const float* A = (seg == 0) ? g_xn : x;
    const float* W = (seg == 0) ? (Wq + (size_t)c0 * Dv)
                                : (Wkv + (size_t)(c0 - 512) * Dv);
    extern __shared__ float sm[];
    float* As = sm;              // [16][136]
    float* Ws = sm + 16 * 136;   // [16][136]
    int tid = threadIdx.x;
    int tx = tid & 15, ty = tid >> 4;
    int fr = tid >> 2, fc = (tid & 3) << 2;   // fill: row 0..63, col*4
    unsigned long long acc[8][4] = {};        // [mi 0..7][npair 0..3]

    for (int kk = 0; kk < Dv; kk += 16) {
        #pragma unroll
        for (int half = 0; half < 2; half++) {
            int r = half * 64 + fr;
            int ro = (r < 64) ? r : (r + 4);
            float4 av = *(const float4*)(A + (size_t)(m0 + r) * Dv + kk + fc);
            As[(fc + 0) * 136 + ro] = av.x; As[(fc + 1) * 136 + ro] = av.y;
            As[(fc + 2) * 136 + ro] = av.z; As[(fc + 3) * 136 + ro] = av.w;
            float4 wv = *(const float4*)(W + (size_t)r * Dv + kk + fc);
            Ws[(fc + 0) * 136 + ro] = wv.x; Ws[(fc + 1) * 136 + ro] = wv.y;
            Ws[(fc + 2) * 136 + ro] = wv.z; Ws[(fc + 3) * 136 + ro] = wv.w;
        }
        __syncthreads();
        #pragma unroll
        for (int t = 0; t < 16; t++) {
            float4 af0 = *(const float4*)&As[t * 136 + ty * 4];
            float4 af1 = *(const float4*)&As[t * 136 + 68 + ty * 4];
            ulonglong2 b0 = *(const ulonglong2*)&Ws[t * 136 + tx * 4];
            ulonglong2 b1 = *(const ulonglong2*)&Ws[t * 136 + 68 + tx * 4];
            unsigned long long a[8] = {dup2(af0.x), dup2(af0.y), dup2(af0.z), dup2(af0.w),
                                       dup2(af1.x), dup2(af1.y), dup2(af1.z), dup2(af1.w)};
            #pragma unroll
            for (int i = 0; i < 8; i++) {
                ffma2(acc[i][0], a[i], b0.x); ffma2(acc[i][1], a[i], b0.y);
                ffma2(acc[i][2], a[i], b1.x); ffma2(acc[i][3], a[i], b1.y);
            }
        }
        __syncthreads();
    }
    float* dst = (seg == 0) ? g_q : (seg == 1) ? g_k : g_v;
    float qs = (seg == 0) ? 0.125f : 1.0f;
    #pragma unroll
    for (int i = 0; i < 8; i++) {
        int row = m0 + ((i < 4) ? (ty * 4 + i) : (64 + ty * 4 + i - 4));
        int b = row >> 10, n = row & 1023;
        #pragma unroll
        for (int nh = 0; nh < 2; nh++) {
            float2 lo = unp2(acc[i][nh * 2 + 0]);
            float2 hi = unp2(acc[i][nh * 2 + 1]);
            int gl = (c0 & 511) + nh * 64 + tx * 4;
            int h = gl >> 6, dh = gl & 63;
            *(float4*)&dst[(((size_t)b * Hv + h) * Nv + n) * DHv + dh] =
                make_float4(lo.x * qs, lo.y * qs, hi.x * qs, hi.y * qs);
        }
    }
}

// ---------------- K4: bias projection + mask penalty -> g_sim --------------
__global__ void bias_kernel(const float* __restrict__ ab,
                            const float* __restrict__ seq_mask,
                            const float* __restrict__ Wb,
                            const float* __restrict__ bb) {
    __shared__ float wb[Hv * ABv];
    __shared__ float sbb[Hv];
    if (threadIdx.x < Hv * ABv) wb[threadIdx.x] = Wb[threadIdx.x];
    if (threadIdx.x < Hv) sbb[threadIdx.x] = bb[threadIdx.x];
    __syncthreads();
    size_t idx = (size_t)blockIdx.x * blockDim.x + threadIdx.x;
    int j = (int)(idx & (Nv - 1));
    int i = (int)((idx >> 10) & (Nv - 1));
    int b = (int)(idx >> 20);
    const float* p = ab + ((size_t)b * ABv * Nv + i) * Nv + j;
    float a[ABv];
    #pragma unroll
    for (int aa = 0; aa < ABv; aa++) a[aa] = p[(size_t)aa * Nv * Nv];
    float pen = -(1.f - seq_mask[b * Nv + i] * seq_mask[b * Nv + j]) * 1e6f;
    #pragma unroll
    for (int h = 0; h < Hv; h++) {
        float acc = sbb[h] + pen;
        #pragma unroll
        for (int aa = 0; aa < ABv; aa++) acc = fmaf(a[aa], wb[h * ABv + aa], acc);
        g_sim[(((size_t)b * Hv + h) * Nv + i) * Nv + j] = acc;
    }
}

// ---------------- K5: fused flash QK + softmax + AV ------------------------
// grid (16 i-tiles, 8 h, 4 b), 256 threads, 52224 B dynamic smem
__global__ __launch_bounds__(256) void flash_kernel() {
    extern __shared__ float sm[];
    float* Qt = sm;              // [k][i] 64x68
    float* Kt = sm + 64 * 68;    // [k][j] 64x68, later aliased by Pt [j][i]
    float* Vs = sm + 2 * 64 * 68;// [j][d] 64x68
    int tid = threadIdx.x;
    int tx = tid & 15, ty = tid >> 4;
    int i0 = blockIdx.x * 64;
    int h = blockIdx.y, b = blockIdx.z;
    int bh = b * Hv + h;
    const float* qp = g_q + ((size_t)bh * Nv + i0) * DHv;
    const float* kp = g_k + (size_t)bh * Nv * DHv;
    const float* vp = g_v + (size_t)bh * Nv * DHv;
    const float* simp = g_sim + (size_t)bh * Nv * Nv;

    // load Q tile transposed (once)
    #pragma unroll
    for (int u = 0; u < 4; u++) {
        int idx = u * 256 + tid;
        int r = idx >> 4, c4 = (idx & 15) << 2;
        float4 qa = *(const float4*)(qp + r * DHv + c4);
        Qt[(c4 + 0) * 68 + r] = qa.x; Qt[(c4 + 1) * 68 + r] = qa.y;
        Qt[(c4 + 2) * 68 + r] = qa.z; Qt[(c4 + 3) * 68 + r] = qa.w;
    }

    float m_run[4], l_run[4];
    #pragma unroll
    for (int u = 0; u < 4; u++) { m_run[u] = -3.0e38f; l_run[u] = 0.f; }
    unsigned long long accO[4][2] = {};

    for (int jt = 0; jt < 16; jt++) {
        int j0 = jt * 64;
        __syncthreads();   // protect Kt(=Pt)/Vs from previous iteration reads
        #pragma unroll
        for (int u = 0; u < 4; u++) {
            int idx = u * 256 + tid;
            int r = idx >> 4, c4 = (idx & 15) << 2;
            float4 ka = *(const float4*)(kp + (size_t)(j0 + r) * DHv + c4);
            Kt[(c4 + 0) * 68 + r] = ka.x; Kt[(c4 + 1) * 68 + r] = ka.y;
            Kt[(c4 + 2) * 68 + r] = ka.z; Kt[(c4 + 3) * 68 + r] = ka.w;
            float4 vv = *(const float4*)(vp + (size_t)(j0 + r) * DHv + c4);
            *(float4*)&Vs[r * 68 + c4] = vv;
        }
        __syncthreads();
        // ---- QK ----
        unsigned long long accS[4][2] = {};
        #pragma unroll 8
        for (int k = 0; k < 64; k++) {
            float4 af = *(const float4*)&Qt[k * 68 + ty * 4];
            ulonglong2 bp = *(const ulonglong2*)&Kt[k * 68 + tx * 4];
            unsigned long long a0 = dup2(af.x), a1 = dup2(af.y),
                               a2 = dup2(af.z), a3 = dup2(af.w);
            ffma2(accS[0][0], a0, bp.x); ffma2(accS[0][1], a0, bp.y);
            ffma2(accS[1][0], a1, bp.x); ffma2(accS[1][1], a1, bp.y);
            ffma2(accS[2][0], a2, bp.x); ffma2(accS[2][1], a2, bp.y);
            ffma2(accS[3][0], a3, bp.x); ffma2(accS[3][1], a3, bp.y);
        }
        // ---- add bias tile + online softmax ----
        float p[4][4], alpha[4];
        #pragma unroll
        for (int u = 0; u < 4; u++) {
            float2 lo = unp2(accS[u][0]), hi = unp2(accS[u][1]);
            float4 bias = *(const float4*)(simp + (size_t)(i0 + ty * 4 + u) * Nv + j0 + tx * 4);
            p[u][0] = lo.x + bias.x; p[u][1] = lo.y + bias.y;
            p[u][2] = hi.x + bias.z; p[u][3] = hi.y + bias.w;
            float mx = fmaxf(fmaxf(p[u][0], p[u][1]), fmaxf(p[u][2], p[u][3]));
            #pragma unroll
            for (int o = 1; o < 16; o <<= 1) mx = fmaxf(mx, __shfl_xor_sync(~0u, mx, o));
            float mn = fmaxf(m_run[u], mx);
            alpha[u] = __expf(m_run[u] - mn);
            m_run[u] = mn;
            float sum = 0.f;
            #pragma unroll
            for (int v = 0; v < 4; v++) { p[u][v] = __expf(p[u][v] - mn); sum += p[u][v]; }
            #pragma unroll
            for (int o = 1; o < 16; o <<= 1) sum += __shfl_xor_sync(~0u, sum, o);
            l_run[u] = l_run[u] * alpha[u] + sum;
            unsigned long long ad = dup2(alpha[u]);
            fmul2(accO[u][0], ad); fmul2(accO[u][1], ad);
        }
        __syncthreads();   // all QK reads of Kt done before Pt overwrite
        float* Pt = Kt;    // [j][i]
        #pragma unroll
        for (int u = 0; u < 4; u++)
            #pragma unroll
            for (int v = 0; v < 4; v++)
                Pt[(tx * 4 + v) * 68 + ty * 4 + u] = p[u][v];
        __syncthreads();
        // ---- AV ----
        #pragma unroll 8
        for (int jj = 0; jj < 64; jj++) {
            float4 af = *(const float4*)&Pt[jj * 68 + ty * 4];
            ulonglong2 bp = *(const ulonglong2*)&Vs[jj * 68 + tx * 4];
            unsigned long long a0 = dup2(af.x), a1 = dup2(af.y),
                               a2 = dup2(af.z), a3 = dup2(af.w);
            ffma2(accO[0][0], a0, bp.x); ffma2(accO[0][1], a0, bp.y);
            ffma2(accO[1][0], a1, bp.x); ffma2(accO[1][1], a1, bp.y);
            ffma2(accO[2][0], a2, bp.x); ffma2(accO[2][1], a2, bp.y);
            ffma2(accO[3][0], a3, bp.x); ffma2(accO[3][1], a3, bp.y);
        }
    }
    #pragma unroll
    for (int u = 0; u < 4; u++) {
        float inv = 1.f / l_run[u];
        float2 lo = unp2(accO[u][0]), hi = unp2(accO[u][1]);
        *(float4*)&g_att[((size_t)b * Nv + i0 + ty * 4 + u) * (Hv * DHv) + h * DHv + tx * 4] =
            make_float4(lo.x * inv, lo.y * inv, hi.x * inv, hi.y * inv);
    }
}

// ---------------- K6: final out = att @ Wo^T, * seq_mask -------------------
__global__ __launch_bounds__(256) void out_kernel(const float* __restrict__ Wo,
                                                  const float* __restrict__ seq_mask,
                                                  float* __restrict__ out) {
    int c0 = blockIdx.x * 128;    // 4 tiles
    int m0 = blockIdx.y * 128;
    extern __shared__ float sm[];
    float* As = sm;
    float* Ws = sm + 16 * 136;
    int tid = threadIdx.x;
    int tx = tid & 15, ty = tid >> 4;
    int fr = tid >> 2, fc = (tid & 3) << 2;
    unsigned long long acc[8][4] = {};
    const int K = Hv * DHv;
    for (int kk = 0; kk < K; kk += 16) {
        #pragma unroll
        for (int half = 0; half < 2; half++) {
            int r = half * 64 + fr;
            int ro = (r < 64) ? r : (r + 4);
            float4 av = *(const float4*)(g_att + (size_t)(m0 + r) * K + kk + fc);
            As[(fc + 0) * 136 + ro] = av.x; As[(fc + 1) * 136 + ro] = av.y;
            As[(fc + 2) * 136 + ro] = av.z; As[(fc + 3) * 136 + ro] = av.w;
            float4 wv = *(const float4*)(Wo + (size_t)(c0 + r) * K + kk + fc);
            Ws[(fc + 0) * 136 + ro] = wv.x; Ws[(fc + 1) * 136 + ro] = wv.y;
            Ws[(fc + 2) * 136 + ro] = wv.z; Ws[(fc + 3) * 136 + ro] = wv.w;
        }
        __syncthreads();
        #pragma unroll
        for (int t = 0; t < 16; t++) {
            float4 af0 = *(const float4*)&As[t * 136 + ty * 4];
            float4 af1 = *(const float4*)&As[t * 136 + 68 + ty * 4];
            ulonglong2 b0 = *(const ulonglong2*)&Ws[t * 136 + tx * 4];
            ulonglong2 b1 = *(const ulonglong2*)&Ws[t * 136 + 68 + tx * 4];
            unsigned long long a[8] = {dup2(af0.x), dup2(af0.y), dup2(af0.z), dup2(af0.w),
                                       dup2(af1.x), dup2(af1.y), dup2(af1.z), dup2(af1.w)};
            #pragma unroll
            for (int i = 0; i < 8; i++) {
                ffma2(acc[i][0], a[i], b0.x); ffma2(acc[i][1], a[i], b0.y);
                ffma2(acc[i][2], a[i], b1.x); ffma2(acc[i][3], a[i], b1.y);
            }
        }
        __syncthreads();
    }
    #pragma unroll
    for (int i = 0; i < 8; i++) {
        int row = m0 + ((i < 4) ? (ty * 4 + i) : (64 + ty * 4 + i - 4));
        float m = seq_mask[row];
        #pragma unroll
        for (int nh = 0; nh < 2; nh++) {
            float2 lo = unp2(acc[i][nh * 2 + 0]);
            float2 hi = unp2(acc[i][nh * 2 + 1]);
            *(float4*)&out[(size_t)row * Dv + c0 + nh * 64 + tx * 4] =
                make_float4(lo.x * m, lo.y * m, hi.x * m, hi.y * m);
        }
    }
}

// ---------------- launch ---------------------------------------------------
extern "C" void kernel_launch(void* const* d_in, const int* in_sizes, int n_in,
                              void* d_out, int out_size) {
    const float* x        = (const float*)d_in[0];
    const float* time_in  = (const float*)d_in[1];
    const float* ab       = (const float*)d_in[2];
    const float* seq_mask = (const float*)d_in[3];
    const float* gamma    = (const float*)d_in[4];
    const float* Wt       = (const float*)d_in[5];
    const float* bt       = (const float*)d_in[6];
    const float* Wq       = (const float*)d_in[7];
    const float* Wkv      = (const float*)d_in[8];
    const float* Wo       = (const float*)d_in[9];
    const float* Wb       = (const float*)d_in[10];
    const float* bb       = (const float*)d_in[11];
    float* out = (float*)d_out;

    static bool attr_set = false;
    if (!attr_set) {
        cudaFuncSetAttribute(flash_kernel,
                             cudaFuncAttributeMaxDynamicSharedMemorySize, 52224);
        attr_set = true;
    }

    film_kernel<<<dim3(Bv, 8), 128>>>(time_in, Wt, bt);
    ln_film_kernel<<<Bv * Nv, 128>>>(x, seq_mask, gamma);
    qkv_kernel<<<dim3(12, 32), 256, 17408>>>(x, Wq, Wkv);
    bias_kernel<<<(Bv * Nv * Nv) / 256, 256>>>(ab, seq_mask, Wb, bb);
    flash_kernel<<<dim3(16, Hv, Bv), 256, 52224>>>();
    out_kernel<<<dim3(4, 32), 256, 17408>>>(Wo, seq_mask, out);
}

// round 5
// speedup vs baseline: 1.8513x; 1.1281x over previous
#include <cuda_runtime.h>
#include <cuda_bf16.h>
#include <math.h>

#define Bv 4
#define Nv 1024
#define Dv 512
#define Hv 8
#define DHv 64
#define TCv 512
#define ABv 16

// ---------------- scratch -------------------------------------------------
__device__ float g_scale[Bv * Dv];
__device__ float g_shift[Bv * Dv];
__device__ float g_xn[(size_t)Bv * Nv * Dv];
__device__ float g_q[(size_t)Bv * Hv * Nv * DHv];   // pre-scaled by DH^-0.5
__device__ float g_k[(size_t)Bv * Hv * Nv * DHv];
__device__ float g_v[(size_t)Bv * Hv * Nv * DHv];
__device__ float g_sim[(size_t)Bv * Hv * Nv * Nv];  // bias + penalty only
__device__ float g_att[(size_t)Bv * Nv * Hv * DHv];

// ---------------- f32x2 helpers -------------------------------------------
__device__ __forceinline__ unsigned long long dup2(float v) {
    unsigned long long r;
    asm("mov.b64 %0, {%1, %1};" : "=l"(r) : "f"(v));
    return r;
}
__device__ __forceinline__ void ffma2(unsigned long long& acc,
                                      unsigned long long a,
                                      unsigned long long b) {
    asm("fma.rn.f32x2 %0, %1, %2, %0;" : "+l"(acc) : "l"(a), "l"(b));
}
__device__ __forceinline__ void fmul2(unsigned long long& acc, unsigned long long a) {
    asm("mul.rn.f32x2 %0, %0, %1;" : "+l"(acc) : "l"(a));
}
__device__ __forceinline__ float2 unp2(unsigned long long v) {
    float2 f;
    asm("mov.b64 {%0, %1}, %2;" : "=f"(f.x), "=f"(f.y) : "l"(v));
    return f;
}

// ---------------- K1: FiLM params ------------------------------------------
__global__ void film_kernel(const float* __restrict__ time,
                            const float* __restrict__ Wt,
                            const float* __restrict__ bt) {
    int b = blockIdx.x;
    int o = blockIdx.y * 128 + threadIdx.x;
    __shared__ float st[TCv];
    for (int i = threadIdx.x; i < TCv; i += 128) {
        float v = time[b * TCv + i];
        st[i] = v / (1.f + __expf(-v));
    }
    __syncthreads();
    const float* w = Wt + (size_t)o * TCv;
    float acc = bt[o];
    #pragma unroll 8
    for (int t = 0; t < TCv; t++) acc = fmaf(st[t], w[t], acc);
    if (o < Dv) g_scale[b * Dv + o] = acc;
    else        g_shift[b * Dv + (o - Dv)] = acc;
}

// ---------------- K2: LayerNorm + FiLM + seq mask -> g_xn ------------------
__global__ void ln_film_kernel(const float* __restrict__ x,
                               const float* __restrict__ seq_mask,
                               const float* __restrict__ gamma) {
    int row = blockIdx.x;
    int b = row >> 10;
    const float* xr = x + (size_t)row * Dv;
    int tid = threadIdx.x;
    float s = 0.f, ss = 0.f;
    #pragma unroll
    for (int u = 0; u < 4; u++) {
        float v = xr[tid + u * 128];
        s += v; ss += v * v;
    }
    #pragma unroll
    for (int o = 16; o > 0; o >>= 1) {
        s  += __shfl_xor_sync(~0u, s, o);
        ss += __shfl_xor_sync(~0u, ss, o);
    }
    __shared__ float shs[4], shss[4];
    if ((tid & 31) == 0) { shs[tid >> 5] = s; shss[tid >> 5] = ss; }
    __syncthreads();
    s  = shs[0] + shs[1] + shs[2] + shs[3];
    ss = shss[0] + shss[1] + shss[2] + shss[3];
    float mu  = s * (1.f / Dv);
    float var = ss * (1.f / Dv) - mu * mu;
    float inv = rsqrtf(var + 1e-5f);
    float m = seq_mask[row];
    float* out = g_xn + (size_t)row * Dv;
    #pragma unroll
    for (int u = 0; u < 4; u++) {
        int d = tid + u * 128;
        float v = (xr[d] - mu) * inv * gamma[d];
        out[d] = (v * (g_scale[b * Dv + d] + 1.f) + g_shift[b * Dv + d]) * m;
    }
}

// ---------------- K3: QKV projections (128x128 f32x2 GEMM) -----------------
__global__ __launch_bounds__(256) void qkv_kernel(const float* __restrict__ x,
                                                  const float* __restrict__ Wq,
                                                  const float* __restrict__ Wkv) {
    int c0 = blockIdx.x * 128;
    int m0 = blockIdx.y * 128;
    int seg = c0 >> 9;            // 0:q 1:k 2:v
    const float* A = (seg == 0) ? g_xn : x;
    const float* W = (seg == 0) ? (Wq + (size_t)c0 * Dv)
                                : (Wkv + (size_t)(c0 - 512) * Dv);
    extern __shared__ float sm[];
    float* As = sm;              // [16][136]
    float* Ws = sm + 16 * 136;
    int tid = threadIdx.x;
    int tx = tid & 15, ty = tid >> 4;
    int fr = tid >> 2, fc = (tid & 3) << 2;
    unsigned long long acc[8][4] = {};

    for (int kk = 0; kk < Dv; kk += 16) {
        #pragma unroll
        for (int half = 0; half < 2; half++) {
            int r = half * 64 + fr;
            int ro = (r < 64) ? r : (r + 4);
            float4 av = *(const float4*)(A + (size_t)(m0 + r) * Dv + kk + fc);
            As[(fc + 0) * 136 + ro] = av.x; As[(fc + 1) * 136 + ro] = av.y;
            As[(fc + 2) * 136 + ro] = av.z; As[(fc + 3) * 136 + ro] = av.w;
            float4 wv = *(const float4*)(W + (size_t)r * Dv + kk + fc);
            Ws[(fc + 0) * 136 + ro] = wv.x; Ws[(fc + 1) * 136 + ro] = wv.y;
            Ws[(fc + 2) * 136 + ro] = wv.z; Ws[(fc + 3) * 136 + ro] = wv.w;
        }
        __syncthreads();
        #pragma unroll
        for (int t = 0; t < 16; t++) {
            float4 af0 = *(const float4*)&As[t * 136 + ty * 4];
            float4 af1 = *(const float4*)&As[t * 136 + 68 + ty * 4];
            ulonglong2 b0 = *(const ulonglong2*)&Ws[t * 136 + tx * 4];
            ulonglong2 b1 = *(const ulonglong2*)&Ws[t * 136 + 68 + tx * 4];
            unsigned long long a[8] = {dup2(af0.x), dup2(af0.y), dup2(af0.z), dup2(af0.w),
                                       dup2(af1.x), dup2(af1.y), dup2(af1.z), dup2(af1.w)};
            #pragma unroll
            for (int i = 0; i < 8; i++) {
                ffma2(acc[i][0], a[i], b0.x); ffma2(acc[i][1], a[i], b0.y);
                ffma2(acc[i][2], a[i], b1.x); ffma2(acc[i][3], a[i], b1.y);
            }
        }
        __syncthreads();
    }
    float* dst = (seg == 0) ? g_q : (seg == 1) ? g_k : g_v;
    float qs = (seg == 0) ? 0.125f : 1.0f;
    #pragma unroll
    for (int i = 0; i < 8; i++) {
        int row = m0 + ((i < 4) ? (ty * 4 + i) : (64 + ty * 4 + i - 4));
        int b = row >> 10, n = row & 1023;
        #pragma unroll
        for (int nh = 0; nh < 2; nh++) {
            float2 lo = unp2(acc[i][nh * 2 + 0]);
            float2 hi = unp2(acc[i][nh * 2 + 1]);
            int gl = (c0 & 511) + nh * 64 + tx * 4;
            int h = gl >> 6, dh = gl & 63;
            *(float4*)&dst[(((size_t)b * Hv + h) * Nv + n) * DHv + dh] =
                make_float4(lo.x * qs, lo.y * qs, hi.x * qs, hi.y * qs);
        }
    }
}

// ---------------- K4: bias projection + mask penalty -> g_sim (float2) -----
__global__ void bias_kernel(const float* __restrict__ ab,
                            const float* __restrict__ seq_mask,
                            const float* __restrict__ Wb,
                            const float* __restrict__ bb) {
    __shared__ float wb[Hv * ABv];
    __shared__ float sbb[Hv];
    if (threadIdx.x < Hv * ABv) wb[threadIdx.x] = Wb[threadIdx.x];
    if (threadIdx.x < Hv) sbb[threadIdx.x] = bb[threadIdx.x];
    __syncthreads();
    size_t idx = (size_t)blockIdx.x * blockDim.x + threadIdx.x;  // 2M total
    int j = (int)(idx & 511) << 1;
    int i = (int)((idx >> 9) & 1023);
    int b = (int)(idx >> 19);
    const float* p = ab + ((size_t)b * ABv * Nv + i) * Nv + j;
    float2 a[ABv];
    #pragma unroll
    for (int aa = 0; aa < ABv; aa++) a[aa] = *(const float2*)(p + (size_t)aa * Nv * Nv);
    float smi = seq_mask[b * Nv + i];
    float2 smj = *(const float2*)&seq_mask[b * Nv + j];
    float pen0 = -(1.f - smi * smj.x) * 1e6f;
    float pen1 = -(1.f - smi * smj.y) * 1e6f;
    #pragma unroll
    for (int h = 0; h < Hv; h++) {
        float ax = sbb[h] + pen0, ay = sbb[h] + pen1;
        #pragma unroll
        for (int aa = 0; aa < ABv; aa++) {
            ax = fmaf(a[aa].x, wb[h * ABv + aa], ax);
            ay = fmaf(a[aa].y, wb[h * ABv + aa], ay);
        }
        *(float2*)&g_sim[(((size_t)b * Hv + h) * Nv + i) * Nv + j] = make_float2(ax, ay);
    }
}

// ---------------- K5: fused flash QK + softmax + AV ------------------------
// 128 threads. i-tile 64, j-tile 128. 8x8 microtile QK, 8x4 AV.
// smem: Qt[64k][68i] | KtP: K^T[64k][136j] (XOR-swizzled), aliased by P[64i][136j]
//       Vs[128j][68d].  Total 87040 B.
__global__ __launch_bounds__(128) void flash_kernel() {
    extern __shared__ float sm[];
    float* Qt  = sm;                       // 64*68
    float* KtP = sm + 64 * 68;             // 64*136
    float* Vs  = sm + 64 * 68 + 64 * 136;  // 128*68
    int tid = threadIdx.x;
    int tx = tid & 15, ty = tid >> 4;      // ty 0..7
    int i0 = blockIdx.x * 64;
    int h = blockIdx.y, b = blockIdx.z;
    int bh = b * Hv + h;
    const float* qp = g_q + ((size_t)bh * Nv + i0) * DHv;
    const float* kp = g_k + (size_t)bh * Nv * DHv;
    const float* vp = g_v + (size_t)bh * Nv * DHv;
    const float* simp = g_sim + ((size_t)bh * Nv + i0) * Nv;

    int ir[8];
    #pragma unroll
    for (int u = 0; u < 4; u++) { ir[u] = ty * 4 + u; ir[u + 4] = 32 + ty * 4 + u; }

    // Q load transposed (once): Qt[k][i]
    #pragma unroll
    for (int u = 0; u < 8; u++) {
        int idx = u * 128 + tid;
        int r = idx >> 4, c4 = (idx & 15) << 2;
        float4 qa = *(const float4*)(qp + r * DHv + c4);
        Qt[(c4 + 0) * 68 + r] = qa.x; Qt[(c4 + 1) * 68 + r] = qa.y;
        Qt[(c4 + 2) * 68 + r] = qa.z; Qt[(c4 + 3) * 68 + r] = qa.w;
    }

    float m_run[8], l_run[8];
    #pragma unroll
    for (int u = 0; u < 8; u++) { m_run[u] = -3.0e38f; l_run[u] = 0.f; }
    unsigned long long accO[8][2] = {};

    for (int jt = 0; jt < 8; jt++) {
        int j0 = jt * 128;
        __syncthreads();    // previous AV done; KtP/Vs free
        // K transposed+swizzled: KtP[k][ j ^ (k&28) ]; V straight copy
        #pragma unroll
        for (int u = 0; u < 16; u++) {
            int idx = u * 128 + tid;
            int r = idx >> 4, c4 = (idx & 15) << 2;   // r: j 0..127, c4: k
            float4 ka = *(const float4*)(kp + (size_t)(j0 + r) * DHv + c4);
            int js = r ^ (c4 & 28);                   // (c4+w)&28 == c4&28 for w<4
            KtP[(c4 + 0) * 136 + js] = ka.x; KtP[(c4 + 1) * 136 + js] = ka.y;
            KtP[(c4 + 2) * 136 + js] = ka.z; KtP[(c4 + 3) * 136 + js] = ka.w;
            float4 vv = *(const float4*)(vp + (size_t)(j0 + r) * DHv + c4);
            *(float4*)&Vs[r * 68 + c4] = vv;
        }
        // prefetch bias tile into regs (latency hidden under QK)
        float4 biasA[8], biasB[8];
        #pragma unroll
        for (int u = 0; u < 8; u++) {
            biasA[u] = *(const float4*)(simp + (size_t)ir[u] * Nv + j0 + tx * 4);
            biasB[u] = *(const float4*)(simp + (size_t)ir[u] * Nv + j0 + 64 + tx * 4);
        }
        __syncthreads();
        // ---- QK: S[64i][128j] ----
        unsigned long long accS[8][4] = {};
        #pragma unroll 8
        for (int k = 0; k < 64; k++) {
            float4 a0f = *(const float4*)&Qt[k * 68 + ty * 4];
            float4 a1f = *(const float4*)&Qt[k * 68 + 32 + ty * 4];
            int sw = (k & 28);
            ulonglong2 b0 = *(const ulonglong2*)&KtP[k * 136 + ((tx * 4) ^ sw)];
            ulonglong2 b1 = *(const ulonglong2*)&KtP[k * 136 + 64 + ((tx * 4) ^ sw)];
            unsigned long long a[8] = {dup2(a0f.x), dup2(a0f.y), dup2(a0f.z), dup2(a0f.w),
                                       dup2(a1f.x), dup2(a1f.y), dup2(a1f.z), dup2(a1f.w)};
            #pragma unroll
            for (int u = 0; u < 8; u++) {
                ffma2(accS[u][0], a[u], b0.x); ffma2(accS[u][1], a[u], b0.y);
                ffma2(accS[u][2], a[u], b1.x); ffma2(accS[u][3], a[u], b1.y);
            }
        }
        // ---- bias add + online softmax (row reduce over 16 tx lanes) ----
        float pr[8][8];
        #pragma unroll
        for (int u = 0; u < 8; u++) {
            float2 s0 = unp2(accS[u][0]), s1 = unp2(accS[u][1]);
            float2 s2 = unp2(accS[u][2]), s3 = unp2(accS[u][3]);
            pr[u][0] = s0.x + biasA[u].x; pr[u][1] = s0.y + biasA[u].y;
            pr[u][2] = s1.x + biasA[u].z; pr[u][3] = s1.y + biasA[u].w;
            pr[u][4] = s2.x + biasB[u].x; pr[u][5] = s2.y + biasB[u].y;
            pr[u][6] = s3.x + biasB[u].z; pr[u][7] = s3.y + biasB[u].w;
            float mx = pr[u][0];
            #pragma unroll
            for (int v = 1; v < 8; v++) mx = fmaxf(mx, pr[u][v]);
            #pragma unroll
            for (int o = 1; o < 16; o <<= 1) mx = fmaxf(mx, __shfl_xor_sync(~0u, mx, o));
            float mn = fmaxf(m_run[u], mx);
            float alpha = __expf(m_run[u] - mn);
            m_run[u] = mn;
            float sum = 0.f;
            #pragma unroll
            for (int v = 0; v < 8; v++) { pr[u][v] = __expf(pr[u][v] - mn); sum += pr[u][v]; }
            #pragma unroll
            for (int o = 1; o < 16; o <<= 1) sum += __shfl_xor_sync(~0u, sum, o);
            l_run[u] = l_run[u] * alpha + sum;
            unsigned long long ad = dup2(alpha);
            fmul2(accO[u][0], ad); fmul2(accO[u][1], ad);
        }
        __syncthreads();    // all QK reads of KtP done
        // ---- write P row-major [i][136] (conflict-free STS.128) ----
        #pragma unroll
        for (int u = 0; u < 8; u++) {
            *(float4*)&KtP[ir[u] * 136 + tx * 4] =
                make_float4(pr[u][0], pr[u][1], pr[u][2], pr[u][3]);
            *(float4*)&KtP[ir[u] * 136 + 64 + tx * 4] =
                make_float4(pr[u][4], pr[u][5], pr[u][6], pr[u][7]);
        }
        __syncthreads();
        // ---- AV: O[64i][64d] += P[i][j] * V[j][d] ----
        #pragma unroll 4
        for (int j = 0; j < 128; j++) {
            ulonglong2 bp = *(const ulonglong2*)&Vs[j * 68 + tx * 4];
            #pragma unroll
            for (int u = 0; u < 8; u++) {
                unsigned long long a = dup2(KtP[ir[u] * 136 + j]);
                ffma2(accO[u][0], a, bp.x); ffma2(accO[u][1], a, bp.y);
            }
        }
    }
    #pragma unroll
    for (int u = 0; u < 8; u++) {
        float inv = 1.f / l_run[u];
        float2 lo = unp2(accO[u][0]), hi = unp2(accO[u][1]);
        *(float4*)&g_att[((size_t)b * Nv + i0 + ir[u]) * (Hv * DHv) + h * DHv + tx * 4] =
            make_float4(lo.x * inv, lo.y * inv, hi.x * inv, hi.y * inv);
    }
}

// ---------------- K6: final out = att @ Wo^T, * seq_mask -------------------
__global__ __launch_bounds__(256) void out_kernel(const float* __restrict__ Wo,
                                                  const float* __restrict__ seq_mask,
                                                  float* __restrict__ out) {
    int c0 = blockIdx.x * 128;
    int m0 = blockIdx.y * 128;
    extern __shared__ float sm[];
    float* As = sm;
    float* Ws = sm + 16 * 136;
    int tid = threadIdx.x;
    int tx = tid & 15, ty = tid >> 4;
    int fr = tid >> 2, fc = (tid & 3) << 2;
    unsigned long long acc[8][4] = {};
    const int K = Hv * DHv;
    for (int kk = 0; kk < K; kk += 16) {
        #pragma unroll
        for (int half = 0; half < 2; half++) {
            int r = half * 64 + fr;
            int ro = (r < 64) ? r : (r + 4);
            float4 av = *(const float4*)(g_att + (size_t)(m0 + r) * K + kk + fc);
            As[(fc + 0) * 136 + ro] = av.x; As[(fc + 1) * 136 + ro] = av.y;
            As[(fc + 2) * 136 + ro] = av.z; As[(fc + 3) * 136 + ro] = av.w;
            float4 wv = *(const float4*)(Wo + (size_t)(c0 + r) * K + kk + fc);
            Ws[(fc + 0) * 136 + ro] = wv.x; Ws[(fc + 1) * 136 + ro] = wv.y;
            Ws[(fc + 2) * 136 + ro] = wv.z; Ws[(fc + 3) * 136 + ro] = wv.w;
        }
        __syncthreads();
        #pragma unroll
        for (int t = 0; t < 16; t++) {
            float4 af0 = *(const float4*)&As[t * 136 + ty * 4];
            float4 af1 = *(const float4*)&As[t * 136 + 68 + ty * 4];
            ulonglong2 b0 = *(const ulonglong2*)&Ws[t * 136 + tx * 4];
            ulonglong2 b1 = *(const ulonglong2*)&Ws[t * 136 + 68 + tx * 4];
            unsigned long long a[8] = {dup2(af0.x), dup2(af0.y), dup2(af0.z), dup2(af0.w),
                                       dup2(af1.x), dup2(af1.y), dup2(af1.z), dup2(af1.w)};
            #pragma unroll
            for (int i = 0; i < 8; i++) {
                ffma2(acc[i][0], a[i], b0.x); ffma2(acc[i][1], a[i], b0.y);
                ffma2(acc[i][2], a[i], b1.x); ffma2(acc[i][3], a[i], b1.y);
            }
        }
        __syncthreads();
    }
    #pragma unroll
    for (int i = 0; i < 8; i++) {
        int row = m0 + ((i < 4) ? (ty * 4 + i) : (64 + ty * 4 + i - 4));
        float m = seq_mask[row];
        #pragma unroll
        for (int nh = 0; nh < 2; nh++) {
            float2 lo = unp2(acc[i][nh * 2 + 0]);
            float2 hi = unp2(acc[i][nh * 2 + 1]);
            *(float4*)&out[(size_t)row * Dv + c0 + nh * 64 + tx * 4] =
                make_float4(lo.x * m, lo.y * m, hi.x * m, hi.y * m);
        }
    }
}

// ---------------- launch ---------------------------------------------------
extern "C" void kernel_launch(void* const* d_in, const int* in_sizes, int n_in,
                              void* d_out, int out_size) {
    const float* x        = (const float*)d_in[0];
    const float* time_in  = (const float*)d_in[1];
    const float* ab       = (const float*)d_in[2];
    const float* seq_mask = (const float*)d_in[3];
    const float* gamma    = (const float*)d_in[4];
    const float* Wt       = (const float*)d_in[5];
    const float* bt       = (const float*)d_in[6];
    const float* Wq       = (const float*)d_in[7];
    const float* Wkv      = (const float*)d_in[8];
    const float* Wo       = (const float*)d_in[9];
    const float* Wb       = (const float*)d_in[10];
    const float* bb       = (const float*)d_in[11];
    float* out = (float*)d_out;

    static bool attr_set = false;
    if (!attr_set) {
        cudaFuncSetAttribute(flash_kernel,
                             cudaFuncAttributeMaxDynamicSharedMemorySize, 87040);
        attr_set = true;
    }

    film_kernel<<<dim3(Bv, 8), 128>>>(time_in, Wt, bt);
    ln_film_kernel<<<Bv * Nv, 128>>>(x, seq_mask, gamma);
    qkv_kernel<<<dim3(12, 32), 256, 17408>>>(x, Wq, Wkv);
    bias_kernel<<<(Bv * Nv * Nv / 2) / 256, 256>>>(ab, seq_mask, Wb, bb);
    flash_kernel<<<dim3(16, Hv, Bv), 128, 87040>>>();
    out_kernel<<<dim3(4, 32), 256, 17408>>>(Wo, seq_mask, out);
}

// round 6
// speedup vs baseline: 2.8706x; 1.5506x over previous
#include <cuda_runtime.h>
#include <cuda_bf16.h>
#include <math.h>

#define Bv 4
#define Nv 1024
#define Dv 512
#define Hv 8
#define DHv 64
#define TCv 512
#define ABv 16

// ---------------- scratch -------------------------------------------------
__device__ float g_scale[Bv * Dv];
__device__ float g_shift[Bv * Dv];
__device__ float g_xn[(size_t)Bv * Nv * Dv];
__device__ float g_q[(size_t)Bv * Hv * Nv * DHv];   // pre-scaled by DH^-0.5
__device__ float g_k[(size_t)Bv * Hv * Nv * DHv];
__device__ float g_v[(size_t)Bv * Hv * Nv * DHv];
__device__ float g_sim[(size_t)Bv * Hv * Nv * Nv];  // bias + penalty only
__device__ float g_att[(size_t)Bv * Nv * Hv * DHv];

// ---------------- tf32 mma helpers -----------------------------------------
__device__ __forceinline__ unsigned f2tf(float f) {
    unsigned r; asm("cvt.rna.tf32.f32 %0, %1;" : "=r"(r) : "f"(f)); return r;
}
__device__ __forceinline__ void mma8(float* c, const unsigned* a, const unsigned* b) {
    asm volatile("mma.sync.aligned.m16n8k8.row.col.f32.tf32.tf32.f32 "
        "{%0,%1,%2,%3}, {%4,%5,%6,%7}, {%8,%9}, {%0,%1,%2,%3};"
        : "+f"(c[0]), "+f"(c[1]), "+f"(c[2]), "+f"(c[3])
        : "r"(a[0]), "r"(a[1]), "r"(a[2]), "r"(a[3]), "r"(b[0]), "r"(b[1]));
}

// ---------------- K1: FiLM params ------------------------------------------
__global__ void film_kernel(const float* __restrict__ time,
                            const float* __restrict__ Wt,
                            const float* __restrict__ bt) {
    int b = blockIdx.x;
    int o = blockIdx.y * 128 + threadIdx.x;
    __shared__ float st[TCv];
    for (int i = threadIdx.x; i < TCv; i += 128) {
        float v = time[b * TCv + i];
        st[i] = v / (1.f + __expf(-v));
    }
    __syncthreads();
    const float* w = Wt + (size_t)o * TCv;
    float acc = bt[o];
    #pragma unroll 8
    for (int t = 0; t < TCv; t++) acc = fmaf(st[t], w[t], acc);
    if (o < Dv) g_scale[b * Dv + o] = acc;
    else        g_shift[b * Dv + (o - Dv)] = acc;
}

// ---------------- K2: LayerNorm + FiLM + seq mask -> g_xn ------------------
__global__ void ln_film_kernel(const float* __restrict__ x,
                               const float* __restrict__ seq_mask,
                               const float* __restrict__ gamma) {
    int row = blockIdx.x;
    int b = row >> 10;
    const float* xr = x + (size_t)row * Dv;
    int tid = threadIdx.x;
    float s = 0.f, ss = 0.f;
    #pragma unroll
    for (int u = 0; u < 4; u++) {
        float v = xr[tid + u * 128];
        s += v; ss += v * v;
    }
    #pragma unroll
    for (int o = 16; o > 0; o >>= 1) {
        s  += __shfl_xor_sync(~0u, s, o);
        ss += __shfl_xor_sync(~0u, ss, o);
    }
    __shared__ float shs[4], shss[4];
    if ((tid & 31) == 0) { shs[tid >> 5] = s; shss[tid >> 5] = ss; }
    __syncthreads();
    s  = shs[0] + shs[1] + shs[2] + shs[3];
    ss = shss[0] + shss[1] + shss[2] + shss[3];
    float mu  = s * (1.f / Dv);
    float var = ss * (1.f / Dv) - mu * mu;
    float inv = rsqrtf(var + 1e-5f);
    float m = seq_mask[row];
    float* out = g_xn + (size_t)row * Dv;
    #pragma unroll
    for (int u = 0; u < 4; u++) {
        int d = tid + u * 128;
        float v = (xr[d] - mu) * inv * gamma[d];
        out[d] = (v * (g_scale[b * Dv + d] + 1.f) + g_shift[b * Dv + d]) * m;
    }
}

// ---------------- K3: QKV projections (tf32 mma, 128x128 tile) -------------
__global__ __launch_bounds__(256) void qkv_kernel(const float* __restrict__ x,
                                                  const float* __restrict__ Wq,
                                                  const float* __restrict__ Wkv) {
    int c0 = blockIdx.x * 128;
    int m0 = blockIdx.y * 128;
    int seg = c0 >> 9;            // 0:q 1:k 2:v
    const float* A = (seg == 0) ? g_xn : x;
    const float* W = (seg == 0) ? (Wq + (size_t)c0 * Dv)
                                : (Wkv + (size_t)(c0 - 512) * Dv);
    __shared__ unsigned As[128 * 20], Ws[128 * 20];
    int tid = threadIdx.x;
    int lane = tid & 31, w = tid >> 5;
    int wm = w & 3, wn = w >> 2;
    int r = lane >> 2, cc = lane & 3;
    float acc[2][8][4] = {};

    for (int kk = 0; kk < Dv; kk += 16) {
        __syncthreads();
        #pragma unroll
        for (int u = 0; u < 2; u++) {
            int idx = u * 256 + tid;
            int rr = idx >> 2, c4 = (idx & 3) << 2;
            float4 av = *(const float4*)(A + (size_t)(m0 + rr) * Dv + kk + c4);
            *(uint4*)&As[rr * 20 + c4] =
                make_uint4(f2tf(av.x), f2tf(av.y), f2tf(av.z), f2tf(av.w));
            float4 wv = *(const float4*)(W + (size_t)rr * Dv + kk + c4);
            *(uint4*)&Ws[rr * 20 + c4] =
                make_uint4(f2tf(wv.x), f2tf(wv.y), f2tf(wv.z), f2tf(wv.w));
        }
        __syncthreads();
        #pragma unroll
        for (int ks = 0; ks < 16; ks += 8) {
            unsigned a[2][4];
            #pragma unroll
            for (int f = 0; f < 2; f++) {
                int rb = (wm * 32 + f * 16 + r) * 20 + ks + cc;
                a[f][0] = As[rb];          a[f][1] = As[rb + 160];
                a[f][2] = As[rb + 4];      a[f][3] = As[rb + 164];
            }
            #pragma unroll
            for (int nt = 0; nt < 8; nt++) {
                int nb = (wn * 64 + nt * 8 + r) * 20 + ks + cc;
                unsigned b2[2] = {Ws[nb], Ws[nb + 4]};
                mma8(acc[0][nt], a[0], b2);
                mma8(acc[1][nt], a[1], b2);
            }
        }
    }
    float* dst = (seg == 0) ? g_q : (seg == 1) ? g_k : g_v;
    float qs = (seg == 0) ? 0.125f : 1.0f;
    int colbase = (c0 & 511) + wn * 64;
    int h = colbase >> 6;
    #pragma unroll
    for (int f = 0; f < 2; f++) {
        int row0 = m0 + wm * 32 + f * 16 + r;
        int b0i = row0 >> 10, n0 = row0 & 1023;
        int row1 = row0 + 8;
        int b1i = row1 >> 10, n1 = row1 & 1023;
        #pragma unroll
        for (int nt = 0; nt < 8; nt++) {
            int dh = nt * 8 + 2 * cc;
            *(float2*)&dst[(((size_t)b0i * Hv + h) * Nv + n0) * DHv + dh] =
                make_float2(acc[f][nt][0] * qs, acc[f][nt][1] * qs);
            *(float2*)&dst[(((size_t)b1i * Hv + h) * Nv + n1) * DHv + dh] =
                make_float2(acc[f][nt][2] * qs, acc[f][nt][3] * qs);
        }
    }
}

// ---------------- K4: bias projection + mask penalty -> g_sim (float2) -----
__global__ void bias_kernel(const float* __restrict__ ab,
                            const float* __restrict__ seq_mask,
                            const float* __restrict__ Wb,
                            const float* __restrict__ bb) {
    __shared__ float wb[Hv * ABv];
    __shared__ float sbb[Hv];
    if (threadIdx.x < Hv * ABv) wb[threadIdx.x] = Wb[threadIdx.x];
    if (threadIdx.x < Hv) sbb[threadIdx.x] = bb[threadIdx.x];
    __syncthreads();
    size_t idx = (size_t)blockIdx.x * blockDim.x + threadIdx.x;
    int j = (int)(idx & 511) << 1;
    int i = (int)((idx >> 9) & 1023);
    int b = (int)(idx >> 19);
    const float* p = ab + ((size_t)b * ABv * Nv + i) * Nv + j;
    float2 a[ABv];
    #pragma unroll
    for (int aa = 0; aa < ABv; aa++) a[aa] = *(const float2*)(p + (size_t)aa * Nv * Nv);
    float smi = seq_mask[b * Nv + i];
    float2 smj = *(const float2*)&seq_mask[b * Nv + j];
    float pen0 = -(1.f - smi * smj.x) * 1e6f;
    float pen1 = -(1.f - smi * smj.y) * 1e6f;
    #pragma unroll
    for (int h = 0; h < Hv; h++) {
        float ax = sbb[h] + pen0, ay = sbb[h] + pen1;
        #pragma unroll
        for (int aa = 0; aa < ABv; aa++) {
            ax = fmaf(a[aa].x, wb[h * ABv + aa], ax);
            ay = fmaf(a[aa].y, wb[h * ABv + aa], ay);
        }
        *(float2*)&g_sim[(((size_t)b * Hv + h) * Nv + i) * Nv + j] = make_float2(ax, ay);
    }
}

// ---------------- K5: fused flash QK + softmax + AV (tf32 mma) --------------
// 128 threads / 4 warps; i-tile 64 (16 rows per warp), j-tile 64.
// smem stride 72 -> all fragment patterns (8r+c mod 32) conflict-free.
__global__ __launch_bounds__(128) void flash_kernel() {
    extern __shared__ unsigned usm[];
    unsigned* Qs = usm;                // [64][72] Q (tf32)
    unsigned* Ks = usm + 64 * 72;      // [64][72] K (tf32), aliased by P
    unsigned* Vs = usm + 2 * 64 * 72;  // [64][72] V (tf32)
    int tid = threadIdx.x;
    int lane = tid & 31, w = tid >> 5;
    int w16 = w * 16;
    int r = lane >> 2, cc = lane & 3;
    int i0 = blockIdx.x * 64;
    int h = blockIdx.y, b = blockIdx.z;
    int bh = b * Hv + h;
    const float* qp = g_q + ((size_t)bh * Nv + i0) * DHv;
    const float* kp = g_k + (size_t)bh * Nv * DHv;
    const float* vp = g_v + (size_t)bh * Nv * DHv;
    const float* simp = g_sim + ((size_t)bh * Nv + i0) * Nv;

    // Q fill (once)
    #pragma unroll
    for (int u = 0; u < 8; u++) {
        int idx = u * 128 + tid;
        int rr = idx >> 4, c4 = (idx & 15) << 2;
        float4 qa = *(const float4*)(qp + rr * DHv + c4);
        *(uint4*)&Qs[rr * 72 + c4] =
            make_uint4(f2tf(qa.x), f2tf(qa.y), f2tf(qa.z), f2tf(qa.w));
    }

    float m_run[2] = {-3.0e38f, -3.0e38f};
    float l_run[2] = {0.f, 0.f};
    float accO[8][4] = {};

    for (int jt = 0; jt < 16; jt++) {
        int j0 = jt * 64;
        __syncthreads();   // prior AV reads of Ks(P)/Vs done
        #pragma unroll
        for (int u = 0; u < 8; u++) {
            int idx = u * 128 + tid;
            int rr = idx >> 4, c4 = (idx & 15) << 2;
            float4 ka = *(const float4*)(kp + (size_t)(j0 + rr) * DHv + c4);
            *(uint4*)&Ks[rr * 72 + c4] =
                make_uint4(f2tf(ka.x), f2tf(ka.y), f2tf(ka.z), f2tf(ka.w));
            float4 vv = *(const float4*)(vp + (size_t)(j0 + rr) * DHv + c4);
            *(uint4*)&Vs[rr * 72 + c4] =
                make_uint4(f2tf(vv.x), f2tf(vv.y), f2tf(vv.z), f2tf(vv.w));
        }
        // bias prefetch (C-fragment layout), latency hidden under QK
        float2 bias0[8], bias1[8];
        #pragma unroll
        for (int nt = 0; nt < 8; nt++) {
            bias0[nt] = *(const float2*)(simp + (size_t)(w16 + r) * Nv + j0 + nt * 8 + 2 * cc);
            bias1[nt] = *(const float2*)(simp + (size_t)(w16 + r + 8) * Nv + j0 + nt * 8 + 2 * cc);
        }
        __syncthreads();
        // ---- QK ----
        float accS[8][4] = {};
        #pragma unroll
        for (int ks = 0; ks < 64; ks += 8) {
            unsigned a[4];
            int rb = (w16 + r) * 72 + ks + cc;
            a[0] = Qs[rb];       a[1] = Qs[rb + 8 * 72];
            a[2] = Qs[rb + 4];   a[3] = Qs[rb + 8 * 72 + 4];
            #pragma unroll
            for (int nt = 0; nt < 8; nt++) {
                int nb = (nt * 8 + r) * 72 + ks + cc;
                unsigned b2[2] = {Ks[nb], Ks[nb + 4]};
                mma8(accS[nt], a, b2);
            }
        }
        // ---- bias add + online softmax (rows r, r+8; 4-lane shfl reduce) --
        float mx0 = -3.0e38f, mx1 = -3.0e38f;
        #pragma unroll
        for (int nt = 0; nt < 8; nt++) {
            accS[nt][0] += bias0[nt].x; accS[nt][1] += bias0[nt].y;
            accS[nt][2] += bias1[nt].x; accS[nt][3] += bias1[nt].y;
            mx0 = fmaxf(mx0, fmaxf(accS[nt][0], accS[nt][1]));
            mx1 = fmaxf(mx1, fmaxf(accS[nt][2], accS[nt][3]));
        }
        mx0 = fmaxf(mx0, __shfl_xor_sync(~0u, mx0, 1));
        mx0 = fmaxf(mx0, __shfl_xor_sync(~0u, mx0, 2));
        mx1 = fmaxf(mx1, __shfl_xor_sync(~0u, mx1, 1));
        mx1 = fmaxf(mx1, __shfl_xor_sync(~0u, mx1, 2));
        float nm0 = fmaxf(m_run[0], mx0), nm1 = fmaxf(m_run[1], mx1);
        float al0 = __expf(m_run[0] - nm0), al1 = __expf(m_run[1] - nm1);
        m_run[0] = nm0; m_run[1] = nm1;
        float s0 = 0.f, s1 = 0.f;
        #pragma unroll
        for (int nt = 0; nt < 8; nt++) {
            accS[nt][0] = __expf(accS[nt][0] - nm0); s0 += accS[nt][0];
            accS[nt][1] = __expf(accS[nt][1] - nm0); s0 += accS[nt][1];
            accS[nt][2] = __expf(accS[nt][2] - nm1); s1 += accS[nt][2];
            accS[nt][3] = __expf(accS[nt][3] - nm1); s1 += accS[nt][3];
        }
        s0 += __shfl_xor_sync(~0u, s0, 1); s0 += __shfl_xor_sync(~0u, s0, 2);
        s1 += __shfl_xor_sync(~0u, s1, 1); s1 += __shfl_xor_sync(~0u, s1, 2);
        l_run[0] = l_run[0] * al0 + s0;
        l_run[1] = l_run[1] * al1 + s1;
        #pragma unroll
        for (int nt = 0; nt < 8; nt++) {
            accO[nt][0] *= al0; accO[nt][1] *= al0;
            accO[nt][2] *= al1; accO[nt][3] *= al1;
        }
        __syncthreads();   // all QK reads of Ks done -> reuse as P
        unsigned* P = Ks;
        #pragma unroll
        for (int nt = 0; nt < 8; nt++) {
            *(uint2*)&P[(w16 + r) * 72 + nt * 8 + 2 * cc] =
                make_uint2(f2tf(accS[nt][0]), f2tf(accS[nt][1]));
            *(uint2*)&P[(w16 + r + 8) * 72 + nt * 8 + 2 * cc] =
                make_uint2(f2tf(accS[nt][2]), f2tf(accS[nt][3]));
        }
        __syncwarp();      // P rows are warp-private; order STS->LDS in-warp
        // ---- AV ----
        #pragma unroll
        for (int ks = 0; ks < 64; ks += 8) {
            unsigned a[4];
            int rb = (w16 + r) * 72 + ks + cc;
            a[0] = P[rb];       a[1] = P[rb + 8 * 72];
            a[2] = P[rb + 4];   a[3] = P[rb + 8 * 72 + 4];
            #pragma unroll
            for (int nt = 0; nt < 8; nt++) {
                unsigned b2[2] = {Vs[(ks + cc) * 72 + nt * 8 + r],
                                  Vs[(ks + cc + 4) * 72 + nt * 8 + r]};
                mma8(accO[nt], a, b2);
            }
        }
    }
    float inv0 = 1.f / l_run[0], inv1 = 1.f / l_run[1];
    #pragma unroll
    for (int nt = 0; nt < 8; nt++) {
        int dh = nt * 8 + 2 * cc;
        *(float2*)&g_att[((size_t)b * Nv + i0 + w16 + r) * (Hv * DHv) + h * DHv + dh] =
            make_float2(accO[nt][0] * inv0, accO[nt][1] * inv0);
        *(float2*)&g_att[((size_t)b * Nv + i0 + w16 + r + 8) * (Hv * DHv) + h * DHv + dh] =
            make_float2(accO[nt][2] * inv1, accO[nt][3] * inv1);
    }
}

// ---------------- K6: final out = att @ Wo^T, * seq_mask (tf32 mma) --------
__global__ __launch_bounds__(256) void out_kernel(const float* __restrict__ Wo,
                                                  const float* __restrict__ seq_mask,
                                                  float* __restrict__ out) {
    int c0 = blockIdx.x * 128;
    int m0 = blockIdx.y * 128;
    const float* W = Wo + (size_t)c0 * (Hv * DHv);
    __shared__ unsigned As[128 * 20], Ws[128 * 20];
    int tid = threadIdx.x;
    int lane = tid & 31, w = tid >> 5;
    int wm = w & 3, wn = w >> 2;
    int r = lane >> 2, cc = lane & 3;
    float acc[2][8][4] = {};
    const int K = Hv * DHv;

    for (int kk = 0; kk < K; kk += 16) {
        __syncthreads();
        #pragma unroll
        for (int u = 0; u < 2; u++) {
            int idx = u * 256 + tid;
            int rr = idx >> 2, c4 = (idx & 3) << 2;
            float4 av = *(const float4*)(g_att + (size_t)(m0 + rr) * K + kk + c4);
            *(uint4*)&As[rr * 20 + c4] =
                make_uint4(f2tf(av.x), f2tf(av.y), f2tf(av.z), f2tf(av.w));
            float4 wv = *(const float4*)(W + (size_t)rr * K + kk + c4);
            *(uint4*)&Ws[rr * 20 + c4] =
                make_uint4(f2tf(wv.x), f2tf(wv.y), f2tf(wv.z), f2tf(wv.w));
        }
        __syncthreads();
        #pragma unroll
        for (int ks = 0; ks < 16; ks += 8) {
            unsigned a[2][4];
            #pragma unroll
            for (int f = 0; f < 2; f++) {
                int rb = (wm * 32 + f * 16 + r) * 20 + ks + cc;
                a[f][0] = As[rb];          a[f][1] = As[rb + 160];
                a[f][2] = As[rb + 4];      a[f][3] = As[rb + 164];
            }
            #pragma unroll
            for (int nt = 0; nt < 8; nt++) {
                int nb = (wn * 64 + nt * 8 + r) * 20 + ks + cc;
                unsigned b2[2] = {Ws[nb], Ws[nb + 4]};
                mma8(acc[0][nt], a[0], b2);
                mma8(acc[1][nt], a[1], b2);
            }
        }
    }
    #pragma unroll
    for (int f = 0; f < 2; f++) {
        int row0 = m0 + wm * 32 + f * 16 + r;
        float mk0 = seq_mask[row0];
        float mk1 = seq_mask[row0 + 8];
        #pragma unroll
        for (int nt = 0; nt < 8; nt++) {
            int col = c0 + wn * 64 + nt * 8 + 2 * cc;
            *(float2*)&out[(size_t)row0 * Dv + col] =
                make_float2(acc[f][nt][0] * mk0, acc[f][nt][1] * mk0);
            *(float2*)&out[(size_t)(row0 + 8) * Dv + col] =
                make_float2(acc[f][nt][2] * mk1, acc[f][nt][3] * mk1);
        }
    }
}

// ---------------- launch ---------------------------------------------------
extern "C" void kernel_launch(void* const* d_in, const int* in_sizes, int n_in,
                              void* d_out, int out_size) {
    const float* x        = (const float*)d_in[0];
    const float* time_in  = (const float*)d_in[1];
    const float* ab       = (const float*)d_in[2];
    const float* seq_mask = (const float*)d_in[3];
    const float* gamma    = (const float*)d_in[4];
    const float* Wt       = (const float*)d_in[5];
    const float* bt       = (const float*)d_in[6];
    const float* Wq       = (const float*)d_in[7];
    const float* Wkv      = (const float*)d_in[8];
    const float* Wo       = (const float*)d_in[9];
    const float* Wb       = (const float*)d_in[10];
    const float* bb       = (const float*)d_in[11];
    float* out = (float*)d_out;

    static bool attr_set = false;
    if (!attr_set) {
        cudaFuncSetAttribute(flash_kernel,
                             cudaFuncAttributeMaxDynamicSharedMemorySize, 55296);
        attr_set = true;
    }

    film_kernel<<<dim3(Bv, 8), 128>>>(time_in, Wt, bt);
    ln_film_kernel<<<Bv * Nv, 128>>>(x, seq_mask, gamma);
    qkv_kernel<<<dim3(12, 32), 256>>>(x, Wq, Wkv);
    bias_kernel<<<(Bv * Nv * Nv / 2) / 256, 256>>>(ab, seq_mask, Wb, bb);
    flash_kernel<<<dim3(16, Hv, Bv), 128, 55296>>>();
    out_kernel<<<dim3(4, 32), 256>>>(Wo, seq_mask, out);
}

// round 7
// speedup vs baseline: 3.9850x; 1.3882x over previous
#include <cuda_runtime.h>
#include <cuda_fp16.h>
#include <math.h>

#define Bv 4
#define Nv 1024
#define Dv 512
#define Hv 8
#define DHv 64
#define TCv 512
#define ABv 16

// ---------------- scratch -------------------------------------------------
__device__ float g_scale[Bv * Dv];
__device__ float g_shift[Bv * Dv];
__device__ float g_xn[(size_t)Bv * Nv * Dv];
__device__ __half g_qh[(size_t)Bv * Hv * Nv * DHv];   // pre-scaled by DH^-0.5
__device__ __half g_kh[(size_t)Bv * Hv * Nv * DHv];
__device__ __half g_vh[(size_t)Bv * Hv * Nv * DHv];
__device__ float g_sim[(size_t)Bv * Hv * Nv * Nv];    // bias + penalty (fp32)
__device__ float g_att[(size_t)Bv * Nv * Hv * DHv];

// ---------------- helpers ---------------------------------------------------
__device__ __forceinline__ unsigned sptr(const void* p) {
    return (unsigned)__cvta_generic_to_shared(p);
}
__device__ __forceinline__ unsigned cvt2h2(float lo, float hi) {
    __half2 h = __floats2half2_rn(lo, hi);
    return *reinterpret_cast<unsigned*>(&h);
}
// swizzled half index within a [rows][64] half tile (128B rows, 16B chunks)
__device__ __forceinline__ int swzi(int r, int c) {
    return (r << 6) + ((((c >> 3) ^ (r & 7))) << 3) + (c & 7);
}
__device__ __forceinline__ void mma16(float* c, const unsigned* a, const unsigned* b) {
    asm volatile("mma.sync.aligned.m16n8k16.row.col.f32.f16.f16.f32 "
        "{%0,%1,%2,%3}, {%4,%5,%6,%7}, {%8,%9}, {%0,%1,%2,%3};"
        : "+f"(c[0]), "+f"(c[1]), "+f"(c[2]), "+f"(c[3])
        : "r"(a[0]), "r"(a[1]), "r"(a[2]), "r"(a[3]), "r"(b[0]), "r"(b[1]));
}
__device__ __forceinline__ void ldsm4(unsigned& r0, unsigned& r1, unsigned& r2,
                                      unsigned& r3, unsigned addr) {
    asm volatile("ldmatrix.sync.aligned.m8n8.x4.shared.b16 {%0,%1,%2,%3}, [%4];"
        : "=r"(r0), "=r"(r1), "=r"(r2), "=r"(r3) : "r"(addr));
}
__device__ __forceinline__ void ldsm4t(unsigned& r0, unsigned& r1, unsigned& r2,
                                       unsigned& r3, unsigned addr) {
    asm volatile("ldmatrix.sync.aligned.m8n8.x4.trans.shared.b16 {%0,%1,%2,%3}, [%4];"
        : "=r"(r0), "=r"(r1), "=r"(r2), "=r"(r3) : "r"(addr));
}

// ---------------- K1: FiLM params ------------------------------------------
__global__ void film_kernel(const float* __restrict__ time,
                            const float* __restrict__ Wt,
                            const float* __restrict__ bt) {
    int b = blockIdx.x;
    int o = blockIdx.y * 128 + threadIdx.x;
    __shared__ float st[TCv];
    for (int i = threadIdx.x; i < TCv; i += 128) {
        float v = time[b * TCv + i];
        st[i] = v / (1.f + __expf(-v));
    }
    __syncthreads();
    const float* w = Wt + (size_t)o * TCv;
    float acc = bt[o];
    #pragma unroll 8
    for (int t = 0; t < TCv; t++) acc = fmaf(st[t], w[t], acc);
    if (o < Dv) g_scale[b * Dv + o] = acc;
    else        g_shift[b * Dv + (o - Dv)] = acc;
}

// ---------------- K2: LayerNorm + FiLM + seq mask -> g_xn ------------------
__global__ void ln_film_kernel(const float* __restrict__ x,
                               const float* __restrict__ seq_mask,
                               const float* __restrict__ gamma) {
    int row = blockIdx.x;
    int b = row >> 10;
    const float* xr = x + (size_t)row * Dv;
    int tid = threadIdx.x;
    float s = 0.f, ss = 0.f;
    #pragma unroll
    for (int u = 0; u < 4; u++) {
        float v = xr[tid + u * 128];
        s += v; ss += v * v;
    }
    #pragma unroll
    for (int o = 16; o > 0; o >>= 1) {
        s  += __shfl_xor_sync(~0u, s, o);
        ss += __shfl_xor_sync(~0u, ss, o);
    }
    __shared__ float shs[4], shss[4];
    if ((tid & 31) == 0) { shs[tid >> 5] = s; shss[tid >> 5] = ss; }
    __syncthreads();
    s  = shs[0] + shs[1] + shs[2] + shs[3];
    ss = shss[0] + shss[1] + shss[2] + shss[3];
    float mu  = s * (1.f / Dv);
    float var = ss * (1.f / Dv) - mu * mu;
    float inv = rsqrtf(var + 1e-5f);
    float m = seq_mask[row];
    float* out = g_xn + (size_t)row * Dv;
    #pragma unroll
    for (int u = 0; u < 4; u++) {
        int d = tid + u * 128;
        float v = (xr[d] - mu) * inv * gamma[d];
        out[d] = (v * (g_scale[b * Dv + d] + 1.f) + g_shift[b * Dv + d]) * m;
    }
}

// ---------------- K3: QKV projections (fp16 mma + ldmatrix) ----------------
__global__ __launch_bounds__(256) void qkv_kernel(const float* __restrict__ x,
                                                  const float* __restrict__ Wq,
                                                  const float* __restrict__ Wkv) {
    int c0 = blockIdx.x * 128;
    int m0 = blockIdx.y * 128;
    int seg = c0 >> 9;            // 0:q 1:k 2:v
    const float* A = (seg == 0) ? g_xn : x;
    const float* W = (seg == 0) ? (Wq + (size_t)c0 * Dv)
                                : (Wkv + (size_t)(c0 - 512) * Dv);
    __shared__ __half Ah[128 * 64], Wh[128 * 64];
    int tid = threadIdx.x;
    int lane = tid & 31, w = tid >> 5;
    int wm = w & 3, wn = w >> 2;
    int r = lane >> 2, cc = lane & 3;
    int g = lane >> 3, l8 = lane & 7;
    unsigned abase = sptr(Ah), wbase = sptr(Wh);
    float acc[2][8][4] = {};
    int rowA0 = wm * 32 + ((g & 1) << 3) + l8;
    int cA = (g >> 1) << 3;
    int rowB0 = wn * 64 + ((g >> 1) << 3) + l8;
    int cB = (g & 1) << 3;

    for (int kk = 0; kk < Dv; kk += 64) {
        __syncthreads();
        #pragma unroll
        for (int it = 0; it < 4; it++) {
            int idx = it * 256 + tid;
            int rr = idx >> 3, c8 = (idx & 7) << 3;
            const float* as = A + (size_t)(m0 + rr) * Dv + kk + c8;
            float4 a0 = *(const float4*)as, a1 = *(const float4*)(as + 4);
            *(uint4*)&Ah[swzi(rr, c8)] =
                make_uint4(cvt2h2(a0.x, a0.y), cvt2h2(a0.z, a0.w),
                           cvt2h2(a1.x, a1.y), cvt2h2(a1.z, a1.w));
            const float* ws = W + (size_t)rr * Dv + kk + c8;
            float4 w0 = *(const float4*)ws, w1 = *(const float4*)(ws + 4);
            *(uint4*)&Wh[swzi(rr, c8)] =
                make_uint4(cvt2h2(w0.x, w0.y), cvt2h2(w0.z, w0.w),
                           cvt2h2(w1.x, w1.y), cvt2h2(w1.z, w1.w));
        }
        __syncthreads();
        #pragma unroll
        for (int ks = 0; ks < 64; ks += 16) {
            unsigned a[2][4];
            ldsm4(a[0][0], a[0][1], a[0][2], a[0][3], abase + swzi(rowA0, ks + cA) * 2);
            ldsm4(a[1][0], a[1][1], a[1][2], a[1][3], abase + swzi(rowA0 + 16, ks + cA) * 2);
            #pragma unroll
            for (int n16 = 0; n16 < 4; n16++) {
                unsigned b0, b1, b2, b3;
                ldsm4(b0, b1, b2, b3, wbase + swzi(rowB0 + n16 * 16, ks + cB) * 2);
                unsigned lo[2] = {b0, b1}, hi[2] = {b2, b3};
                mma16(acc[0][n16 * 2], a[0], lo); mma16(acc[0][n16 * 2 + 1], a[0], hi);
                mma16(acc[1][n16 * 2], a[1], lo); mma16(acc[1][n16 * 2 + 1], a[1], hi);
            }
        }
    }
    __half* dst = (seg == 0) ? g_qh : (seg == 1) ? g_kh : g_vh;
    float qs = (seg == 0) ? 0.125f : 1.0f;
    int colbase = (c0 & 511) + wn * 64;
    int h = colbase >> 6;
    #pragma unroll
    for (int f = 0; f < 2; f++) {
        int row0 = m0 + wm * 32 + f * 16 + r;
        int b0i = row0 >> 10, n0 = row0 & 1023;
        int b1i = (row0 + 8) >> 10, n1 = (row0 + 8) & 1023;
        #pragma unroll
        for (int nt = 0; nt < 8; nt++) {
            int dh = nt * 8 + 2 * cc;
            *(unsigned*)&dst[(((size_t)b0i * Hv + h) * Nv + n0) * DHv + dh] =
                cvt2h2(acc[f][nt][0] * qs, acc[f][nt][1] * qs);
            *(unsigned*)&dst[(((size_t)b1i * Hv + h) * Nv + n1) * DHv + dh] =
                cvt2h2(acc[f][nt][2] * qs, acc[f][nt][3] * qs);
        }
    }
}

// ---------------- K4: bias projection + mask penalty -> g_sim (float2) -----
__global__ void bias_kernel(const float* __restrict__ ab,
                            const float* __restrict__ seq_mask,
                            const float* __restrict__ Wb,
                            const float* __restrict__ bb) {
    __shared__ float wb[Hv * ABv];
    __shared__ float sbb[Hv];
    if (threadIdx.x < Hv * ABv) wb[threadIdx.x] = Wb[threadIdx.x];
    if (threadIdx.x < Hv) sbb[threadIdx.x] = bb[threadIdx.x];
    __syncthreads();
    size_t idx = (size_t)blockIdx.x * blockDim.x + threadIdx.x;
    int j = (int)(idx & 511) << 1;
    int i = (int)((idx >> 9) & 1023);
    int b = (int)(idx >> 19);
    const float* p = ab + ((size_t)b * ABv * Nv + i) * Nv + j;
    float2 a[ABv];
    #pragma unroll
    for (int aa = 0; aa < ABv; aa++) a[aa] = *(const float2*)(p + (size_t)aa * Nv * Nv);
    float smi = seq_mask[b * Nv + i];
    float2 smj = *(const float2*)&seq_mask[b * Nv + j];
    float pen0 = -(1.f - smi * smj.x) * 1e6f;
    float pen1 = -(1.f - smi * smj.y) * 1e6f;
    #pragma unroll
    for (int h = 0; h < Hv; h++) {
        float ax = sbb[h] + pen0, ay = sbb[h] + pen1;
        #pragma unroll
        for (int aa = 0; aa < ABv; aa++) {
            ax = fmaf(a[aa].x, wb[h * ABv + aa], ax);
            ay = fmaf(a[aa].y, wb[h * ABv + aa], ay);
        }
        *(float2*)&g_sim[(((size_t)b * Hv + h) * Nv + i) * Nv + j] = make_float2(ax, ay);
    }
}

// ---------------- K5: fused flash QK + softmax + AV (fp16 mma) -------------
// 128 threads / 4 warps; i-tile 64 (16 rows/warp), j-tile 64. 24 KB smem.
__global__ __launch_bounds__(128) void flash_kernel() {
    __shared__ __half Qh[4096], KPh[4096], Vh[4096];
    int tid = threadIdx.x;
    int lane = tid & 31, w = tid >> 5;
    int w16 = w * 16;
    int r = lane >> 2, cc = lane & 3;
    int g = lane >> 3, l8 = lane & 7;
    int i0 = blockIdx.x * 64;
    int h = blockIdx.y, b = blockIdx.z;
    int bh = b * Hv + h;
    const __half* qp = g_qh + ((size_t)bh * Nv + i0) * DHv;
    const __half* kp = g_kh + (size_t)bh * Nv * DHv;
    const __half* vp = g_vh + (size_t)bh * Nv * DHv;
    const float* simp = g_sim + ((size_t)bh * Nv + i0) * Nv;
    unsigned qbase = sptr(Qh), kbase = sptr(KPh), vbase = sptr(Vh);

    // Q tile load (once)
    #pragma unroll
    for (int it = 0; it < 4; it++) {
        int idx = it * 128 + tid;
        int rr = idx >> 3, c8 = (idx & 7) << 3;
        *(uint4*)&Qh[swzi(rr, c8)] = *(const uint4*)(qp + rr * DHv + c8);
    }

    float m_run[2] = {-3.0e38f, -3.0e38f};
    float l_run[2] = {0.f, 0.f};
    float accO[8][4] = {};
    int rowA = w16 + ((g & 1) << 3) + l8;       // A-frag rows (Q and P)
    int cA = (g >> 1) << 3;
    int rowBb = ((g >> 1) << 3) + l8;           // B-frag rows (K)
    int cB = (g & 1) << 3;
    int rowVg = ((g & 1) << 3) + l8;            // V trans rows (k=j)
    int cV = (g >> 1) << 3;                     // V trans col group (n=dh)

    for (int jt = 0; jt < 16; jt++) {
        int j0 = jt * 64;
        __syncthreads();   // prior AV reads of KPh/Vh done
        #pragma unroll
        for (int it = 0; it < 4; it++) {
            int idx = it * 128 + tid;
            int rr = idx >> 3, c8 = (idx & 7) << 3;
            *(uint4*)&KPh[swzi(rr, c8)] = *(const uint4*)(kp + (size_t)(j0 + rr) * DHv + c8);
            *(uint4*)&Vh[swzi(rr, c8)] = *(const uint4*)(vp + (size_t)(j0 + rr) * DHv + c8);
        }
        // bias prefetch (fragment layout) — latency hidden under QK
        float2 bias0[8], bias1[8];
        #pragma unroll
        for (int nt = 0; nt < 8; nt++) {
            bias0[nt] = *(const float2*)(simp + (size_t)(w16 + r) * Nv + j0 + nt * 8 + 2 * cc);
            bias1[nt] = *(const float2*)(simp + (size_t)(w16 + r + 8) * Nv + j0 + nt * 8 + 2 * cc);
        }
        __syncthreads();
        // ---- QK ----
        float accS[8][4] = {};
        #pragma unroll
        for (int ks = 0; ks < 64; ks += 16) {
            unsigned a[4];
            ldsm4(a[0], a[1], a[2], a[3], qbase + swzi(rowA, ks + cA) * 2);
            #pragma unroll
            for (int n16 = 0; n16 < 4; n16++) {
                unsigned b0, b1, b2, b3;
                ldsm4(b0, b1, b2, b3, kbase + swzi(n16 * 16 + rowBb, ks + cB) * 2);
                unsigned lo[2] = {b0, b1}, hi[2] = {b2, b3};
                mma16(accS[n16 * 2], a, lo);
                mma16(accS[n16 * 2 + 1], a, hi);
            }
        }
        // ---- bias add + online softmax (rows r, r+8; 4-lane reduce) ----
        float mx0 = -3.0e38f, mx1 = -3.0e38f;
        #pragma unroll
        for (int nt = 0; nt < 8; nt++) {
            accS[nt][0] += bias0[nt].x; accS[nt][1] += bias0[nt].y;
            accS[nt][2] += bias1[nt].x; accS[nt][3] += bias1[nt].y;
            mx0 = fmaxf(mx0, fmaxf(accS[nt][0], accS[nt][1]));
            mx1 = fmaxf(mx1, fmaxf(accS[nt][2], accS[nt][3]));
        }
        mx0 = fmaxf(mx0, __shfl_xor_sync(~0u, mx0, 1));
        mx0 = fmaxf(mx0, __shfl_xor_sync(~0u, mx0, 2));
        mx1 = fmaxf(mx1, __shfl_xor_sync(~0u, mx1, 1));
        mx1 = fmaxf(mx1, __shfl_xor_sync(~0u, mx1, 2));
        float nm0 = fmaxf(m_run[0], mx0), nm1 = fmaxf(m_run[1], mx1);
        float al0 = __expf(m_run[0] - nm0), al1 = __expf(m_run[1] - nm1);
        m_run[0] = nm0; m_run[1] = nm1;
        float s0 = 0.f, s1 = 0.f;
        #pragma unroll
        for (int nt = 0; nt < 8; nt++) {
            accS[nt][0] = __expf(accS[nt][0] - nm0); s0 += accS[nt][0];
            accS[nt][1] = __expf(accS[nt][1] - nm0); s0 += accS[nt][1];
            accS[nt][2] = __expf(accS[nt][2] - nm1); s1 += accS[nt][2];
            accS[nt][3] = __expf(accS[nt][3] - nm1); s1 += accS[nt][3];
        }
        s0 += __shfl_xor_sync(~0u, s0, 1); s0 += __shfl_xor_sync(~0u, s0, 2);
        s1 += __shfl_xor_sync(~0u, s1, 1); s1 += __shfl_xor_sync(~0u, s1, 2);
        l_run[0] = l_run[0] * al0 + s0;
        l_run[1] = l_run[1] * al1 + s1;
        #pragma unroll
        for (int nt = 0; nt < 8; nt++) {
            accO[nt][0] *= al0; accO[nt][1] *= al0;
            accO[nt][2] *= al1; accO[nt][3] *= al1;
        }
        __syncthreads();   // all QK reads of KPh done -> reuse as P
        #pragma unroll
        for (int nt = 0; nt < 8; nt++) {
            *(unsigned*)&KPh[swzi(w16 + r, nt * 8 + 2 * cc)] =
                cvt2h2(accS[nt][0], accS[nt][1]);
            *(unsigned*)&KPh[swzi(w16 + r + 8, nt * 8 + 2 * cc)] =
                cvt2h2(accS[nt][2], accS[nt][3]);
        }
        __syncwarp();      // P rows are warp-private
        // ---- AV ----
        #pragma unroll
        for (int ksj = 0; ksj < 64; ksj += 16) {
            unsigned a[4];
            ldsm4(a[0], a[1], a[2], a[3], kbase + swzi(rowA, ksj + cA) * 2);
            #pragma unroll
            for (int nd = 0; nd < 4; nd++) {
                unsigned b0, b1, b2, b3;
                ldsm4t(b0, b1, b2, b3, vbase + swzi(ksj + rowVg, nd * 16 + cV) * 2);
                unsigned lo[2] = {b0, b1}, hi[2] = {b2, b3};
                mma16(accO[nd * 2], a, lo);
                mma16(accO[nd * 2 + 1], a, hi);
            }
        }
    }
    float inv0 = 1.f / l_run[0], inv1 = 1.f / l_run[1];
    #pragma unroll
    for (int nt = 0; nt < 8; nt++) {
        int dh = nt * 8 + 2 * cc;
        *(float2*)&g_att[((size_t)b * Nv + i0 + w16 + r) * (Hv * DHv) + h * DHv + dh] =
            make_float2(accO[nt][0] * inv0, accO[nt][1] * inv0);
        *(float2*)&g_att[((size_t)b * Nv + i0 + w16 + r + 8) * (Hv * DHv) + h * DHv + dh] =
            make_float2(accO[nt][2] * inv1, accO[nt][3] * inv1);
    }
}

// ---------------- K6: final out = att @ Wo^T, * seq_mask (fp16 mma) --------
__global__ __launch_bounds__(256) void out_kernel(const float* __restrict__ Wo,
                                                  const float* __restrict__ seq_mask,
                                                  float* __restrict__ out) {
    int c0 = blockIdx.x * 128;
    int m0 = blockIdx.y * 128;
    const float* W = Wo + (size_t)c0 * (Hv * DHv);
    __shared__ __half Ah[128 * 64], Wh[128 * 64];
    int tid = threadIdx.x;
    int lane = tid & 31, w = tid >> 5;
    int wm = w & 3, wn = w >> 2;
    int r = lane >> 2, cc = lane & 3;
    int g = lane >> 3, l8 = lane & 7;
    unsigned abase = sptr(Ah), wbase = sptr(Wh);
    float acc[2][8][4] = {};
    int rowA0 = wm * 32 + ((g & 1) << 3) + l8;
    int cA = (g >> 1) << 3;
    int rowB0 = wn * 64 + ((g >> 1) << 3) + l8;
    int cB = (g & 1) << 3;
    const int K = Hv * DHv;

    for (int kk = 0; kk < K; kk += 64) {
        __syncthreads();
        #pragma unroll
        for (int it = 0; it < 4; it++) {
            int idx = it * 256 + tid;
            int rr = idx >> 3, c8 = (idx & 7) << 3;
            const float* as = g_att + (size_t)(m0 + rr) * K + kk + c8;
            float4 a0 = *(const float4*)as, a1 = *(const float4*)(as + 4);
            *(uint4*)&Ah[swzi(rr, c8)] =
                make_uint4(cvt2h2(a0.x, a0.y), cvt2h2(a0.z, a0.w),
                           cvt2h2(a1.x, a1.y), cvt2h2(a1.z, a1.w));
            const float* ws = W + (size_t)rr * K + kk + c8;
            float4 w0 = *(const float4*)ws, w1 = *(const float4*)(ws + 4);
            *(uint4*)&Wh[swzi(rr, c8)] =
                make_uint4(cvt2h2(w0.x, w0.y), cvt2h2(w0.z, w0.w),
                           cvt2h2(w1.x, w1.y), cvt2h2(w1.z, w1.w));
        }
        __syncthreads();
        #pragma unroll
        for (int ks = 0; ks < 64; ks += 16) {
            unsigned a[2][4];
            ldsm4(a[0][0], a[0][1], a[0][2], a[0][3], abase + swzi(rowA0, ks + cA) * 2);
            ldsm4(a[1][0], a[1][1], a[1][2], a[1][3], abase + swzi(rowA0 + 16, ks + cA) * 2);
            #pragma unroll
            for (int n16 = 0; n16 < 4; n16++) {
                unsigned b0, b1, b2, b3;
                ldsm4(b0, b1, b2, b3, wbase + swzi(rowB0 + n16 * 16, ks + cB) * 2);
                unsigned lo[2] = {b0, b1}, hi[2] = {b2, b3};
                mma16(acc[0][n16 * 2], a[0], lo); mma16(acc[0][n16 * 2 + 1], a[0], hi);
                mma16(acc[1][n16 * 2], a[1], lo); mma16(acc[1][n16 * 2 + 1], a[1], hi);
            }
        }
    }
    #pragma unroll
    for (int f = 0; f < 2; f++) {
        int row0 = m0 + wm * 32 + f * 16 + r;
        float mk0 = seq_mask[row0];
        float mk1 = seq_mask[row0 + 8];
        #pragma unroll
        for (int nt = 0; nt < 8; nt++) {
            int col = c0 + wn * 64 + nt * 8 + 2 * cc;
            *(float2*)&out[(size_t)row0 * Dv + col] =
                make_float2(acc[f][nt][0] * mk0, acc[f][nt][1] * mk0);
            *(float2*)&out[(size_t)(row0 + 8) * Dv + col] =
                make_float2(acc[f][nt][2] * mk1, acc[f][nt][3] * mk1);
        }
    }
}

// ---------------- launch ---------------------------------------------------
extern "C" void kernel_launch(void* const* d_in, const int* in_sizes, int n_in,
                              void* d_out, int out_size) {
    const float* x        = (const float*)d_in[0];
    const float* time_in  = (const float*)d_in[1];
    const float* ab       = (const float*)d_in[2];
    const float* seq_mask = (const float*)d_in[3];
    const float* gamma    = (const float*)d_in[4];
    const float* Wt       = (const float*)d_in[5];
    const float* bt       = (const float*)d_in[6];
    const float* Wq       = (const float*)d_in[7];
    const float* Wkv      = (const float*)d_in[8];
    const float* Wo       = (const float*)d_in[9];
    const float* Wb       = (const float*)d_in[10];
    const float* bb       = (const float*)d_in[11];
    float* out = (float*)d_out;

    film_kernel<<<dim3(Bv, 8), 128>>>(time_in, Wt, bt);
    ln_film_kernel<<<Bv * Nv, 128>>>(x, seq_mask, gamma);
    qkv_kernel<<<dim3(12, 32), 256>>>(x, Wq, Wkv);
    bias_kernel<<<(Bv * Nv * Nv / 2) / 256, 256>>>(ab, seq_mask, Wb, bb);
    flash_kernel<<<dim3(16, Hv, Bv), 128>>>();
    out_kernel<<<dim3(4, 32), 256>>>(Wo, seq_mask, out);
}

// round 8
// speedup vs baseline: 4.1154x; 1.0327x over previous
#include <cuda_runtime.h>
#include <cuda_fp16.h>
#include <cuda_bf16.h>
#include <math.h>

#define Bv 4
#define Nv 1024
#define Dv 512
#define Hv 8
#define DHv 64
#define TCv 512
#define ABv 16

// ---------------- scratch -------------------------------------------------
__device__ float g_scale[Bv * Dv];
__device__ float g_shift[Bv * Dv];
__device__ float g_xn[(size_t)Bv * Nv * Dv];
__device__ __half g_qh[(size_t)Bv * Hv * Nv * DHv];   // pre-scaled by DH^-0.5
__device__ __half g_kh[(size_t)Bv * Hv * Nv * DHv];
__device__ __half g_vh[(size_t)Bv * Hv * Nv * DHv];
__device__ __nv_bfloat16 g_sim[(size_t)Bv * Hv * Nv * Nv];  // bias + penalty (bf16)
__device__ float g_att[(size_t)Bv * Nv * Hv * DHv];

// ---------------- helpers ---------------------------------------------------
__device__ __forceinline__ unsigned sptr(const void* p) {
    return (unsigned)__cvta_generic_to_shared(p);
}
__device__ __forceinline__ unsigned cvt2h2(float lo, float hi) {
    __half2 h = __floats2half2_rn(lo, hi);
    return *reinterpret_cast<unsigned*>(&h);
}
// swizzled half index within a [rows][64] half tile (128B rows, 16B chunks)
__device__ __forceinline__ int swzi(int r, int c) {
    return (r << 6) + ((((c >> 3) ^ (r & 7))) << 3) + (c & 7);
}
__device__ __forceinline__ void mma16(float* c, const unsigned* a, const unsigned* b) {
    asm volatile("mma.sync.aligned.m16n8k16.row.col.f32.f16.f16.f32 "
        "{%0,%1,%2,%3}, {%4,%5,%6,%7}, {%8,%9}, {%0,%1,%2,%3};"
        : "+f"(c[0]), "+f"(c[1]), "+f"(c[2]), "+f"(c[3])
        : "r"(a[0]), "r"(a[1]), "r"(a[2]), "r"(a[3]), "r"(b[0]), "r"(b[1]));
}
__device__ __forceinline__ void ldsm4(unsigned& r0, unsigned& r1, unsigned& r2,
                                      unsigned& r3, unsigned addr) {
    asm volatile("ldmatrix.sync.aligned.m8n8.x4.shared.b16 {%0,%1,%2,%3}, [%4];"
        : "=r"(r0), "=r"(r1), "=r"(r2), "=r"(r3) : "r"(addr));
}
__device__ __forceinline__ void ldsm4t(unsigned& r0, unsigned& r1, unsigned& r2,
                                       unsigned& r3, unsigned addr) {
    asm volatile("ldmatrix.sync.aligned.m8n8.x4.trans.shared.b16 {%0,%1,%2,%3}, [%4];"
        : "=r"(r0), "=r"(r1), "=r"(r2), "=r"(r3) : "r"(addr));
}
__device__ __forceinline__ float2 bf2f2(unsigned u) {
    __nv_bfloat162 b = *reinterpret_cast<__nv_bfloat162*>(&u);
    return __bfloat1622float2(b);
}

// ---------------- K1: FiLM params ------------------------------------------
__global__ void film_kernel(const float* __restrict__ time,
                            const float* __restrict__ Wt,
                            const float* __restrict__ bt) {
    int b = blockIdx.x;
    int o = blockIdx.y * 128 + threadIdx.x;
    __shared__ float st[TCv];
    for (int i = threadIdx.x; i < TCv; i += 128) {
        float v = time[b * TCv + i];
        st[i] = v / (1.f + __expf(-v));
    }
    __syncthreads();
    const float* w = Wt + (size_t)o * TCv;
    float acc = bt[o];
    #pragma unroll 8
    for (int t = 0; t < TCv; t++) acc = fmaf(st[t], w[t], acc);
    if (o < Dv) g_scale[b * Dv + o] = acc;
    else        g_shift[b * Dv + (o - Dv)] = acc;
}

// ---------------- K2: LayerNorm + FiLM + seq mask -> g_xn ------------------
__global__ void ln_film_kernel(const float* __restrict__ x,
                               const float* __restrict__ seq_mask,
                               const float* __restrict__ gamma) {
    int row = blockIdx.x;
    int b = row >> 10;
    const float* xr = x + (size_t)row * Dv;
    int tid = threadIdx.x;
    float s = 0.f, ss = 0.f;
    #pragma unroll
    for (int u = 0; u < 4; u++) {
        float v = xr[tid + u * 128];
        s += v; ss += v * v;
    }
    #pragma unroll
    for (int o = 16; o > 0; o >>= 1) {
        s  += __shfl_xor_sync(~0u, s, o);
        ss += __shfl_xor_sync(~0u, ss, o);
    }
    __shared__ float shs[4], shss[4];
    if ((tid & 31) == 0) { shs[tid >> 5] = s; shss[tid >> 5] = ss; }
    __syncthreads();
    s  = shs[0] + shs[1] + shs[2] + shs[3];
    ss = shss[0] + shss[1] + shss[2] + shss[3];
    float mu  = s * (1.f / Dv);
    float var = ss * (1.f / Dv) - mu * mu;
    float inv = rsqrtf(var + 1e-5f);
    float m = seq_mask[row];
    float* out = g_xn + (size_t)row * Dv;
    #pragma unroll
    for (int u = 0; u < 4; u++) {
        int d = tid + u * 128;
        float v = (xr[d] - mu) * inv * gamma[d];
        out[d] = (v * (g_scale[b * Dv + d] + 1.f) + g_shift[b * Dv + d]) * m;
    }
}

// ---------------- K3: QKV projections (fp16 mma + ldmatrix) ----------------
__global__ __launch_bounds__(256) void qkv_kernel(const float* __restrict__ x,
                                                  const float* __restrict__ Wq,
                                                  const float* __restrict__ Wkv) {
    int c0 = blockIdx.x * 128;
    int m0 = blockIdx.y * 128;
    int seg = c0 >> 9;            // 0:q 1:k 2:v
    const float* A = (seg == 0) ? g_xn : x;
    const float* W = (seg == 0) ? (Wq + (size_t)c0 * Dv)
                                : (Wkv + (size_t)(c0 - 512) * Dv);
    __shared__ __half Ah[128 * 64], Wh[128 * 64];
    int tid = threadIdx.x;
    int lane = tid & 31, w = tid >> 5;
    int wm = w & 3, wn = w >> 2;
    int r = lane >> 2, cc = lane & 3;
    int g = lane >> 3, l8 = lane & 7;
    unsigned abase = sptr(Ah), wbase = sptr(Wh);
    float acc[2][8][4] = {};
    int rowA0 = wm * 32 + ((g & 1) << 3) + l8;
    int cA = (g >> 1) << 3;
    int rowB0 = wn * 64 + ((g >> 1) << 3) + l8;
    int cB = (g & 1) << 3;

    for (int kk = 0; kk < Dv; kk += 64) {
        __syncthreads();
        #pragma unroll
        for (int it = 0; it < 4; it++) {
            int idx = it * 256 + tid;
            int rr = idx >> 3, c8 = (idx & 7) << 3;
            const float* as = A + (size_t)(m0 + rr) * Dv + kk + c8;
            float4 a0 = *(const float4*)as, a1 = *(const float4*)(as + 4);
            *(uint4*)&Ah[swzi(rr, c8)] =
                make_uint4(cvt2h2(a0.x, a0.y), cvt2h2(a0.z, a0.w),
                           cvt2h2(a1.x, a1.y), cvt2h2(a1.z, a1.w));
            const float* ws = W + (size_t)rr * Dv + kk + c8;
            float4 w0 = *(const float4*)ws, w1 = *(const float4*)(ws + 4);
            *(uint4*)&Wh[swzi(rr, c8)] =
                make_uint4(cvt2h2(w0.x, w0.y), cvt2h2(w0.z, w0.w),
                           cvt2h2(w1.x, w1.y), cvt2h2(w1.z, w1.w));
        }
        __syncthreads();
        #pragma unroll
        for (int ks = 0; ks < 64; ks += 16) {
            unsigned a[2][4];
            ldsm4(a[0][0], a[0][1], a[0][2], a[0][3], abase + swzi(rowA0, ks + cA) * 2);
            ldsm4(a[1][0], a[1][1], a[1][2], a[1][3], abase + swzi(rowA0 + 16, ks + cA) * 2);
            #pragma unroll
            for (int n16 = 0; n16 < 4; n16++) {
                unsigned b0, b1, b2, b3;
                ldsm4(b0, b1, b2, b3, wbase + swzi(rowB0 + n16 * 16, ks + cB) * 2);
                unsigned lo[2] = {b0, b1}, hi[2] = {b2, b3};
                mma16(acc[0][n16 * 2], a[0], lo); mma16(acc[0][n16 * 2 + 1], a[0], hi);
                mma16(acc[1][n16 * 2], a[1], lo); mma16(acc[1][n16 * 2 + 1], a[1], hi);
            }
        }
    }
    __half* dst = (seg == 0) ? g_qh : (seg == 1) ? g_kh : g_vh;
    float qs = (seg == 0) ? 0.125f : 1.0f;
    int colbase = (c0 & 511) + wn * 64;
    int h = colbase >> 6;
    #pragma unroll
    for (int f = 0; f < 2; f++) {
        int row0 = m0 + wm * 32 + f * 16 + r;
        int b0i = row0 >> 10, n0 = row0 & 1023;
        int b1i = (row0 + 8) >> 10, n1 = (row0 + 8) & 1023;
        #pragma unroll
        for (int nt = 0; nt < 8; nt++) {
            int dh = nt * 8 + 2 * cc;
            *(unsigned*)&dst[(((size_t)b0i * Hv + h) * Nv + n0) * DHv + dh] =
                cvt2h2(acc[f][nt][0] * qs, acc[f][nt][1] * qs);
            *(unsigned*)&dst[(((size_t)b1i * Hv + h) * Nv + n1) * DHv + dh] =
                cvt2h2(acc[f][nt][2] * qs, acc[f][nt][3] * qs);
        }
    }
}

// ---------------- K4: bias projection + mask penalty -> g_sim (bf16) -------
__global__ void bias_kernel(const float* __restrict__ ab,
                            const float* __restrict__ seq_mask,
                            const float* __restrict__ Wb,
                            const float* __restrict__ bb) {
    __shared__ float wb[Hv * ABv];
    __shared__ float sbb[Hv];
    if (threadIdx.x < Hv * ABv) wb[threadIdx.x] = Wb[threadIdx.x];
    if (threadIdx.x < Hv) sbb[threadIdx.x] = bb[threadIdx.x];
    __syncthreads();
    size_t idx = (size_t)blockIdx.x * blockDim.x + threadIdx.x;
    int j = (int)(idx & 511) << 1;
    int i = (int)((idx >> 9) & 1023);
    int b = (int)(idx >> 19);
    const float* p = ab + ((size_t)b * ABv * Nv + i) * Nv + j;
    float2 a[ABv];
    #pragma unroll
    for (int aa = 0; aa < ABv; aa++) a[aa] = *(const float2*)(p + (size_t)aa * Nv * Nv);
    float smi = seq_mask[b * Nv + i];
    float2 smj = *(const float2*)&seq_mask[b * Nv + j];
    float pen0 = -(1.f - smi * smj.x) * 1e6f;
    float pen1 = -(1.f - smi * smj.y) * 1e6f;
    #pragma unroll
    for (int h = 0; h < Hv; h++) {
        float ax = sbb[h] + pen0, ay = sbb[h] + pen1;
        #pragma unroll
        for (int aa = 0; aa < ABv; aa++) {
            ax = fmaf(a[aa].x, wb[h * ABv + aa], ax);
            ay = fmaf(a[aa].y, wb[h * ABv + aa], ay);
        }
        __nv_bfloat162 o = __floats2bfloat162_rn(ax, ay);
        *(__nv_bfloat162*)&g_sim[(((size_t)b * Hv + h) * Nv + i) * Nv + j] = o;
    }
}

// ---------------- K5: fused flash QK + softmax + AV (fp16 mma) -------------
// 128 threads / 4 warps; i-tile 64 (16 rows/warp), j-tile 64. 24 KB smem.
__global__ __launch_bounds__(128) void flash_kernel() {
    __shared__ __half Qh[4096], KPh[4096], Vh[4096];
    int tid = threadIdx.x;
    int lane = tid & 31, w = tid >> 5;
    int w16 = w * 16;
    int r = lane >> 2, cc = lane & 3;
    int g = lane >> 3, l8 = lane & 7;
    int i0 = blockIdx.x * 64;
    int h = blockIdx.y, b = blockIdx.z;
    int bh = b * Hv + h;
    const __half* qp = g_qh + ((size_t)bh * Nv + i0) * DHv;
    const __half* kp = g_kh + (size_t)bh * Nv * DHv;
    const __half* vp = g_vh + (size_t)bh * Nv * DHv;
    const __nv_bfloat16* simp = g_sim + ((size_t)bh * Nv + i0) * Nv;
    unsigned qbase = sptr(Qh), kbase = sptr(KPh), vbase = sptr(Vh);

    // Q tile load (once)
    #pragma unroll
    for (int it = 0; it < 4; it++) {
        int idx = it * 128 + tid;
        int rr = idx >> 3, c8 = (idx & 7) << 3;
        *(uint4*)&Qh[swzi(rr, c8)] = *(const uint4*)(qp + rr * DHv + c8);
    }

    float m_run[2] = {-3.0e38f, -3.0e38f};
    float l_run[2] = {0.f, 0.f};
    float accO[8][4] = {};
    int rowA = w16 + ((g & 1) << 3) + l8;       // A-frag rows (Q and P)
    int cA = (g >> 1) << 3;
    int rowBb = ((g >> 1) << 3) + l8;           // B-frag rows (K)
    int cB = (g & 1) << 3;
    int rowVg = ((g & 1) << 3) + l8;            // V trans rows (k=j)
    int cV = (g >> 1) << 3;                     // V trans col group (n=dh)

    for (int jt = 0; jt < 16; jt++) {
        int j0 = jt * 64;
        __syncthreads();   // prior AV reads of KPh/Vh done
        #pragma unroll
        for (int it = 0; it < 4; it++) {
            int idx = it * 128 + tid;
            int rr = idx >> 3, c8 = (idx & 7) << 3;
            *(uint4*)&KPh[swzi(rr, c8)] = *(const uint4*)(kp + (size_t)(j0 + rr) * DHv + c8);
            *(uint4*)&Vh[swzi(rr, c8)] = *(const uint4*)(vp + (size_t)(j0 + rr) * DHv + c8);
        }
        // bias prefetch (fragment layout, bf16x2) — latency hidden under QK
        unsigned biasu0[8], biasu1[8];
        #pragma unroll
        for (int nt = 0; nt < 8; nt++) {
            biasu0[nt] = *(const unsigned*)(simp + (size_t)(w16 + r) * Nv + j0 + nt * 8 + 2 * cc);
            biasu1[nt] = *(const unsigned*)(simp + (size_t)(w16 + r + 8) * Nv + j0 + nt * 8 + 2 * cc);
        }
        __syncthreads();
        // ---- QK ----
        float accS[8][4] = {};
        #pragma unroll
        for (int ks = 0; ks < 64; ks += 16) {
            unsigned a[4];
            ldsm4(a[0], a[1], a[2], a[3], qbase + swzi(rowA, ks + cA) * 2);
            #pragma unroll
            for (int n16 = 0; n16 < 4; n16++) {
                unsigned b0, b1, b2, b3;
                ldsm4(b0, b1, b2, b3, kbase + swzi(n16 * 16 + rowBb, ks + cB) * 2);
                unsigned lo[2] = {b0, b1}, hi[2] = {b2, b3};
                mma16(accS[n16 * 2], a, lo);
                mma16(accS[n16 * 2 + 1], a, hi);
            }
        }
        // ---- bias add + online softmax (rows r, r+8; 4-lane reduce) ----
        float mx0 = -3.0e38f, mx1 = -3.0e38f;
        #pragma unroll
        for (int nt = 0; nt < 8; nt++) {
            float2 bias0 = bf2f2(biasu0[nt]);
            float2 bias1 = bf2f2(biasu1[nt]);
            accS[nt][0] += bias0.x; accS[nt][1] += bias0.y;
            accS[nt][2] += bias1.x; accS[nt][3] += bias1.y;
            mx0 = fmaxf(mx0, fmaxf(accS[nt][0], accS[nt][1]));
            mx1 = fmaxf(mx1, fmaxf(accS[nt][2], accS[nt][3]));
        }
        mx0 = fmaxf(mx0, __shfl_xor_sync(~0u, mx0, 1));
        mx0 = fmaxf(mx0, __shfl_xor_sync(~0u, mx0, 2));
        mx1 = fmaxf(mx1, __shfl_xor_sync(~0u, mx1, 1));
        mx1 = fmaxf(mx1, __shfl_xor_sync(~0u, mx1, 2));
        float nm0 = fmaxf(m_run[0], mx0), nm1 = fmaxf(m_run[1], mx1);
        float al0 = __expf(m_run[0] - nm0), al1 = __expf(m_run[1] - nm1);
        m_run[0] = nm0; m_run[1] = nm1;
        float s0 = 0.f, s1 = 0.f;
        #pragma unroll
        for (int nt = 0; nt < 8; nt++) {
            accS[nt][0] = __expf(accS[nt][0] - nm0); s0 += accS[nt][0];
            accS[nt][1] = __expf(accS[nt][1] - nm0); s0 += accS[nt][1];
            accS[nt][2] = __expf(accS[nt][2] - nm1); s1 += accS[nt][2];
            accS[nt][3] = __expf(accS[nt][3] - nm1); s1 += accS[nt][3];
        }
        s0 += __shfl_xor_sync(~0u, s0, 1); s0 += __shfl_xor_sync(~0u, s0, 2);
        s1 += __shfl_xor_sync(~0u, s1, 1); s1 += __shfl_xor_sync(~0u, s1, 2);
        l_run[0] = l_run[0] * al0 + s0;
        l_run[1] = l_run[1] * al1 + s1;
        #pragma unroll
        for (int nt = 0; nt < 8; nt++) {
            accO[nt][0] *= al0; accO[nt][1] *= al0;
            accO[nt][2] *= al1; accO[nt][3] *= al1;
        }
        __syncthreads();   // all QK reads of KPh done -> reuse as P
        #pragma unroll
        for (int nt = 0; nt < 8; nt++) {
            *(unsigned*)&KPh[swzi(w16 + r, nt * 8 + 2 * cc)] =
                cvt2h2(accS[nt][0], accS[nt][1]);
            *(unsigned*)&KPh[swzi(w16 + r + 8, nt * 8 + 2 * cc)] =
                cvt2h2(accS[nt][2], accS[nt][3]);
        }
        __syncwarp();      // P rows are warp-private
        // ---- AV ----
        #pragma unroll
        for (int ksj = 0; ksj < 64; ksj += 16) {
            unsigned a[4];
            ldsm4(a[0], a[1], a[2], a[3], kbase + swzi(rowA, ksj + cA) * 2);
            #pragma unroll
            for (int nd = 0; nd < 4; nd++) {
                unsigned b0, b1, b2, b3;
                ldsm4t(b0, b1, b2, b3, vbase + swzi(ksj + rowVg, nd * 16 + cV) * 2);
                unsigned lo[2] = {b0, b1}, hi[2] = {b2, b3};
                mma16(accO[nd * 2], a, lo);
                mma16(accO[nd * 2 + 1], a, hi);
            }
        }
    }
    float inv0 = 1.f / l_run[0], inv1 = 1.f / l_run[1];
    #pragma unroll
    for (int nt = 0; nt < 8; nt++) {
        int dh = nt * 8 + 2 * cc;
        *(float2*)&g_att[((size_t)b * Nv + i0 + w16 + r) * (Hv * DHv) + h * DHv + dh] =
            make_float2(accO[nt][0] * inv0, accO[nt][1] * inv0);
        *(float2*)&g_att[((size_t)b * Nv + i0 + w16 + r + 8) * (Hv * DHv) + h * DHv + dh] =
            make_float2(accO[nt][2] * inv1, accO[nt][3] * inv1);
    }
}

// ---------------- K6: final out = att @ Wo^T, * seq_mask (fp16 mma) --------
__global__ __launch_bounds__(256) void out_kernel(const float* __restrict__ Wo,
                                                  const float* __restrict__ seq_mask,
                                                  float* __restrict__ out) {
    int c0 = blockIdx.x * 128;
    int m0 = blockIdx.y * 128;
    const float* W = Wo + (size_t)c0 * (Hv * DHv);
    __shared__ __half Ah[128 * 64], Wh[128 * 64];
    int tid = threadIdx.x;
    int lane = tid & 31, w = tid >> 5;
    int wm = w & 3, wn = w >> 2;
    int r = lane >> 2, cc = lane & 3;
    int g = lane >> 3, l8 = lane & 7;
    unsigned abase = sptr(Ah), wbase = sptr(Wh);
    float acc[2][8][4] = {};
    int rowA0 = wm * 32 + ((g & 1) << 3) + l8;
    int cA = (g >> 1) << 3;
    int rowB0 = wn * 64 + ((g >> 1) << 3) + l8;
    int cB = (g & 1) << 3;
    const int K = Hv * DHv;

    for (int kk = 0; kk < K; kk += 64) {
        __syncthreads();
        #pragma unroll
        for (int it = 0; it < 4; it++) {
            int idx = it * 256 + tid;
            int rr = idx >> 3, c8 = (idx & 7) << 3;
            const float* as = g_att + (size_t)(m0 + rr) * K + kk + c8;
            float4 a0 = *(const float4*)as, a1 = *(const float4*)(as + 4);
            *(uint4*)&Ah[swzi(rr, c8)] =
                make_uint4(cvt2h2(a0.x, a0.y), cvt2h2(a0.z, a0.w),
                           cvt2h2(a1.x, a1.y), cvt2h2(a1.z, a1.w));
            const float* ws = W + (size_t)rr * K + kk + c8;
            float4 w0 = *(const float4*)ws, w1 = *(const float4*)(ws + 4);
            *(uint4*)&Wh[swzi(rr, c8)] =
                make_uint4(cvt2h2(w0.x, w0.y), cvt2h2(w0.z, w0.w),
                           cvt2h2(w1.x, w1.y), cvt2h2(w1.z, w1.w));
        }
        __syncthreads();
        #pragma unroll
        for (int ks = 0; ks < 64; ks += 16) {
            unsigned a[2][4];
            ldsm4(a[0][0], a[0][1], a[0][2], a[0][3], abase + swzi(rowA0, ks + cA) * 2);
            ldsm4(a[1][0], a[1][1], a[1][2], a[1][3], abase + swzi(rowA0 + 16, ks + cA) * 2);
            #pragma unroll
            for (int n16 = 0; n16 < 4; n16++) {
                unsigned b0, b1, b2, b3;
                ldsm4(b0, b1, b2, b3, wbase + swzi(rowB0 + n16 * 16, ks + cB) * 2);
                unsigned lo[2] = {b0, b1}, hi[2] = {b2, b3};
                mma16(acc[0][n16 * 2], a[0], lo); mma16(acc[0][n16 * 2 + 1], a[0], hi);
                mma16(acc[1][n16 * 2], a[1], lo); mma16(acc[1][n16 * 2 + 1], a[1], hi);
            }
        }
    }
    #pragma unroll
    for (int f = 0; f < 2; f++) {
        int row0 = m0 + wm * 32 + f * 16 + r;
        float mk0 = seq_mask[row0];
        float mk1 = seq_mask[row0 + 8];
        #pragma unroll
        for (int nt = 0; nt < 8; nt++) {
            int col = c0 + wn * 64 + nt * 8 + 2 * cc;
            *(float2*)&out[(size_t)row0 * Dv + col] =
                make_float2(acc[f][nt][0] * mk0, acc[f][nt][1] * mk0);
            *(float2*)&out[(size_t)(row0 + 8) * Dv + col] =
                make_float2(acc[f][nt][2] * mk1, acc[f][nt][3] * mk1);
        }
    }
}

// ---------------- launch ---------------------------------------------------
extern "C" void kernel_launch(void* const* d_in, const int* in_sizes, int n_in,
                              void* d_out, int out_size) {
    const float* x        = (const float*)d_in[0];
    const float* time_in  = (const float*)d_in[1];
    const float* ab       = (const float*)d_in[2];
    const float* seq_mask = (const float*)d_in[3];
    const float* gamma    = (const float*)d_in[4];
    const float* Wt       = (const float*)d_in[5];
    const float* bt       = (const float*)d_in[6];
    const float* Wq       = (const float*)d_in[7];
    const float* Wkv      = (const float*)d_in[8];
    const float* Wo       = (const float*)d_in[9];
    const float* Wb       = (const float*)d_in[10];
    const float* bb       = (const float*)d_in[11];
    float* out = (float*)d_out;

    film_kernel<<<dim3(Bv, 8), 128>>>(time_in, Wt, bt);
    ln_film_kernel<<<Bv * Nv, 128>>>(x, seq_mask, gamma);
    qkv_kernel<<<dim3(12, 32), 256>>>(x, Wq, Wkv);
    bias_kernel<<<(Bv * Nv * Nv / 2) / 256, 256>>>(ab, seq_mask, Wb, bb);
    flash_kernel<<<dim3(16, Hv, Bv), 128>>>();
    out_kernel<<<dim3(4, 32), 256>>>(Wo, seq_mask, out);
}

// round 9
// speedup vs baseline: 4.4382x; 1.0784x over previous
#include <cuda_runtime.h>
#include <cuda_fp16.h>
#include <cuda_bf16.h>
#include <math.h>

#define Bv 4
#define Nv 1024
#define Dv 512
#define Hv 8
#define DHv 64
#define TCv 512
#define ABv 16

// ---------------- scratch -------------------------------------------------
__device__ float g_scale[Bv * Dv];
__device__ float g_shift[Bv * Dv];
__device__ float g_xn[(size_t)Bv * Nv * Dv];
__device__ __half g_qh[(size_t)Bv * Hv * Nv * DHv];   // pre-scaled by DH^-0.5
__device__ __half g_kh[(size_t)Bv * Hv * Nv * DHv];
__device__ __half g_vh[(size_t)Bv * Hv * Nv * DHv];
__device__ __nv_bfloat16 g_sim[(size_t)Bv * Hv * Nv * Nv];  // bias + penalty (bf16)
__device__ float g_att[(size_t)Bv * Nv * Hv * DHv];

// ---------------- helpers ---------------------------------------------------
__device__ __forceinline__ unsigned sptr(const void* p) {
    return (unsigned)__cvta_generic_to_shared(p);
}
__device__ __forceinline__ unsigned cvt2h2(float lo, float hi) {
    __half2 h = __floats2half2_rn(lo, hi);
    return *reinterpret_cast<unsigned*>(&h);
}
// swizzled half index within a [rows][64] half tile (128B rows, 16B chunks)
__device__ __forceinline__ int swzi(int r, int c) {
    return (r << 6) + ((((c >> 3) ^ (r & 7))) << 3) + (c & 7);
}
__device__ __forceinline__ void mma16(float* c, const unsigned* a, const unsigned* b) {
    asm volatile("mma.sync.aligned.m16n8k16.row.col.f32.f16.f16.f32 "
        "{%0,%1,%2,%3}, {%4,%5,%6,%7}, {%8,%9}, {%0,%1,%2,%3};"
        : "+f"(c[0]), "+f"(c[1]), "+f"(c[2]), "+f"(c[3])
        : "r"(a[0]), "r"(a[1]), "r"(a[2]), "r"(a[3]), "r"(b[0]), "r"(b[1]));
}
__device__ __forceinline__ void ldsm4(unsigned& r0, unsigned& r1, unsigned& r2,
                                      unsigned& r3, unsigned addr) {
    asm volatile("ldmatrix.sync.aligned.m8n8.x4.shared.b16 {%0,%1,%2,%3}, [%4];"
        : "=r"(r0), "=r"(r1), "=r"(r2), "=r"(r3) : "r"(addr));
}
__device__ __forceinline__ void ldsm4t(unsigned& r0, unsigned& r1, unsigned& r2,
                                       unsigned& r3, unsigned addr) {
    asm volatile("ldmatrix.sync.aligned.m8n8.x4.trans.shared.b16 {%0,%1,%2,%3}, [%4];"
        : "=r"(r0), "=r"(r1), "=r"(r2), "=r"(r3) : "r"(addr));
}
__device__ __forceinline__ float2 bf2f2(unsigned u) {
    __nv_bfloat162 b = *reinterpret_cast<__nv_bfloat162*>(&u);
    return __bfloat1622float2(b);
}

// ---------------- K1: FiLM params ------------------------------------------
__global__ void film_kernel(const float* __restrict__ time,
                            const float* __restrict__ Wt,
                            const float* __restrict__ bt) {
    int b = blockIdx.x;
    int o = blockIdx.y * 128 + threadIdx.x;
    __shared__ float st[TCv];
    for (int i = threadIdx.x; i < TCv; i += 128) {
        float v = time[b * TCv + i];
        st[i] = v / (1.f + __expf(-v));
    }
    __syncthreads();
    const float* w = Wt + (size_t)o * TCv;
    float acc = bt[o];
    #pragma unroll 8
    for (int t = 0; t < TCv; t++) acc = fmaf(st[t], w[t], acc);
    if (o < Dv) g_scale[b * Dv + o] = acc;
    else        g_shift[b * Dv + (o - Dv)] = acc;
}

// ---------------- K2: LayerNorm + FiLM + seq mask -> g_xn ------------------
__global__ void ln_film_kernel(const float* __restrict__ x,
                               const float* __restrict__ seq_mask,
                               const float* __restrict__ gamma) {
    int row = blockIdx.x;
    int b = row >> 10;
    const float* xr = x + (size_t)row * Dv;
    int tid = threadIdx.x;
    float s = 0.f, ss = 0.f;
    #pragma unroll
    for (int u = 0; u < 4; u++) {
        float v = xr[tid + u * 128];
        s += v; ss += v * v;
    }
    #pragma unroll
    for (int o = 16; o > 0; o >>= 1) {
        s  += __shfl_xor_sync(~0u, s, o);
        ss += __shfl_xor_sync(~0u, ss, o);
    }
    __shared__ float shs[4], shss[4];
    if ((tid & 31) == 0) { shs[tid >> 5] = s; shss[tid >> 5] = ss; }
    __syncthreads();
    s  = shs[0] + shs[1] + shs[2] + shs[3];
    ss = shss[0] + shss[1] + shss[2] + shss[3];
    float mu  = s * (1.f / Dv);
    float var = ss * (1.f / Dv) - mu * mu;
    float inv = rsqrtf(var + 1e-5f);
    float m = seq_mask[row];
    float* out = g_xn + (size_t)row * Dv;
    #pragma unroll
    for (int u = 0; u < 4; u++) {
        int d = tid + u * 128;
        float v = (xr[d] - mu) * inv * gamma[d];
        out[d] = (v * (g_scale[b * Dv + d] + 1.f) + g_shift[b * Dv + d]) * m;
    }
}

// ---------------- K3: QKV projections (fp16 mma + ldmatrix) ----------------
__global__ __launch_bounds__(256) void qkv_kernel(const float* __restrict__ x,
                                                  const float* __restrict__ Wq,
                                                  const float* __restrict__ Wkv) {
    int c0 = blockIdx.x * 128;
    int m0 = blockIdx.y * 128;
    int seg = c0 >> 9;            // 0:q 1:k 2:v
    const float* A = (seg == 0) ? g_xn : x;
    const float* W = (seg == 0) ? (Wq + (size_t)c0 * Dv)
                                : (Wkv + (size_t)(c0 - 512) * Dv);
    __shared__ __half Ah[128 * 64], Wh[128 * 64];
    int tid = threadIdx.x;
    int lane = tid & 31, w = tid >> 5;
    int wm = w & 3, wn = w >> 2;
    int r = lane >> 2, cc = lane & 3;
    int g = lane >> 3, l8 = lane & 7;
    unsigned abase = sptr(Ah), wbase = sptr(Wh);
    float acc[2][8][4] = {};
    int rowA0 = wm * 32 + ((g & 1) << 3) + l8;
    int cA = (g >> 1) << 3;
    int rowB0 = wn * 64 + ((g >> 1) << 3) + l8;
    int cB = (g & 1) << 3;

    for (int kk = 0; kk < Dv; kk += 64) {
        __syncthreads();
        #pragma unroll
        for (int it = 0; it < 4; it++) {
            int idx = it * 256 + tid;
            int rr = idx >> 3, c8 = (idx & 7) << 3;
            const float* as = A + (size_t)(m0 + rr) * Dv + kk + c8;
            float4 a0 = *(const float4*)as, a1 = *(const float4*)(as + 4);
            *(uint4*)&Ah[swzi(rr, c8)] =
                make_uint4(cvt2h2(a0.x, a0.y), cvt2h2(a0.z, a0.w),
                           cvt2h2(a1.x, a1.y), cvt2h2(a1.z, a1.w));
            const float* ws = W + (size_t)rr * Dv + kk + c8;
            float4 w0 = *(const float4*)ws, w1 = *(const float4*)(ws + 4);
            *(uint4*)&Wh[swzi(rr, c8)] =
                make_uint4(cvt2h2(w0.x, w0.y), cvt2h2(w0.z, w0.w),
                           cvt2h2(w1.x, w1.y), cvt2h2(w1.z, w1.w));
        }
        __syncthreads();
        #pragma unroll
        for (int ks = 0; ks < 64; ks += 16) {
            unsigned a[2][4];
            ldsm4(a[0][0], a[0][1], a[0][2], a[0][3], abase + swzi(rowA0, ks + cA) * 2);
            ldsm4(a[1][0], a[1][1], a[1][2], a[1][3], abase + swzi(rowA0 + 16, ks + cA) * 2);
            #pragma unroll
            for (int n16 = 0; n16 < 4; n16++) {
                unsigned b0, b1, b2, b3;
                ldsm4(b0, b1, b2, b3, wbase + swzi(rowB0 + n16 * 16, ks + cB) * 2);
                unsigned lo[2] = {b0, b1}, hi[2] = {b2, b3};
                mma16(acc[0][n16 * 2], a[0], lo); mma16(acc[0][n16 * 2 + 1], a[0], hi);
                mma16(acc[1][n16 * 2], a[1], lo); mma16(acc[1][n16 * 2 + 1], a[1], hi);
            }
        }
    }
    __half* dst = (seg == 0) ? g_qh : (seg == 1) ? g_kh : g_vh;
    float qs = (seg == 0) ? 0.125f : 1.0f;
    int colbase = (c0 & 511) + wn * 64;
    int h = colbase >> 6;
    #pragma unroll
    for (int f = 0; f < 2; f++) {
        int row0 = m0 + wm * 32 + f * 16 + r;
        int b0i = row0 >> 10, n0 = row0 & 1023;
        int b1i = (row0 + 8) >> 10, n1 = (row0 + 8) & 1023;
        #pragma unroll
        for (int nt = 0; nt < 8; nt++) {
            int dh = nt * 8 + 2 * cc;
            *(unsigned*)&dst[(((size_t)b0i * Hv + h) * Nv + n0) * DHv + dh] =
                cvt2h2(acc[f][nt][0] * qs, acc[f][nt][1] * qs);
            *(unsigned*)&dst[(((size_t)b1i * Hv + h) * Nv + n1) * DHv + dh] =
                cvt2h2(acc[f][nt][2] * qs, acc[f][nt][3] * qs);
        }
    }
}

// ---------------- K4: bias projection + mask penalty -> g_sim (bf16) -------
__global__ void bias_kernel(const float* __restrict__ ab,
                            const float* __restrict__ seq_mask,
                            const float* __restrict__ Wb,
                            const float* __restrict__ bb) {
    __shared__ float wb[Hv * ABv];
    __shared__ float sbb[Hv];
    if (threadIdx.x < Hv * ABv) wb[threadIdx.x] = Wb[threadIdx.x];
    if (threadIdx.x < Hv) sbb[threadIdx.x] = bb[threadIdx.x];
    __syncthreads();
    size_t idx = (size_t)blockIdx.x * blockDim.x + threadIdx.x;
    int j = (int)(idx & 511) << 1;
    int i = (int)((idx >> 9) & 1023);
    int b = (int)(idx >> 19);
    const float* p = ab + ((size_t)b * ABv * Nv + i) * Nv + j;
    float2 a[ABv];
    #pragma unroll
    for (int aa = 0; aa < ABv; aa++) a[aa] = *(const float2*)(p + (size_t)aa * Nv * Nv);
    float smi = seq_mask[b * Nv + i];
    float2 smj = *(const float2*)&seq_mask[b * Nv + j];
    float pen0 = -(1.f - smi * smj.x) * 1e6f;
    float pen1 = -(1.f - smi * smj.y) * 1e6f;
    #pragma unroll
    for (int h = 0; h < Hv; h++) {
        float ax = sbb[h] + pen0, ay = sbb[h] + pen1;
        #pragma unroll
        for (int aa = 0; aa < ABv; aa++) {
            ax = fmaf(a[aa].x, wb[h * ABv + aa], ax);
            ay = fmaf(a[aa].y, wb[h * ABv + aa], ay);
        }
        __nv_bfloat162 o = __floats2bfloat162_rn(ax, ay);
        *(__nv_bfloat162*)&g_sim[(((size_t)b * Hv + h) * Nv + i) * Nv + j] = o;
    }
}

// ---------------- K5: fused flash QK + softmax + AV (fp16 mma) -------------
// 256 threads / 8 warps; i-tile 128 (16 rows/warp), j-tile 64. 48 KB smem.
__global__ __launch_bounds__(256) void flash_kernel() {
    __shared__ __half Qh[8192], Kh[4096], Vh[4096], Ph[8192];
    int tid = threadIdx.x;
    int lane = tid & 31, w = tid >> 5;      // w 0..7
    int w16 = w * 16;
    int r = lane >> 2, cc = lane & 3;
    int g = lane >> 3, l8 = lane & 7;
    int i0 = blockIdx.x * 128;
    int h = blockIdx.y, b = blockIdx.z;
    int bh = b * Hv + h;
    const __half* qp = g_qh + ((size_t)bh * Nv + i0) * DHv;
    const __half* kp = g_kh + (size_t)bh * Nv * DHv;
    const __half* vp = g_vh + (size_t)bh * Nv * DHv;
    const __nv_bfloat16* simp = g_sim + ((size_t)bh * Nv + i0) * Nv;
    unsigned qbase = sptr(Qh), kbase = sptr(Kh), vbase = sptr(Vh), pbase = sptr(Ph);

    // Q tile load (once): 128 x 64
    #pragma unroll
    for (int it = 0; it < 4; it++) {
        int idx = it * 256 + tid;
        int rr = idx >> 3, c8 = (idx & 7) << 3;
        *(uint4*)&Qh[swzi(rr, c8)] = *(const uint4*)(qp + rr * DHv + c8);
    }

    float m_run[2] = {-3.0e38f, -3.0e38f};
    float l_run[2] = {0.f, 0.f};
    float accO[8][4] = {};
    int rowA = w16 + ((g & 1) << 3) + l8;       // A-frag rows (Q and P), warp-private
    int cA = (g >> 1) << 3;
    int rowBb = ((g >> 1) << 3) + l8;           // B-frag rows (K)
    int cB = (g & 1) << 3;
    int rowVg = ((g & 1) << 3) + l8;            // V trans rows (k=j)
    int cV = (g >> 1) << 3;                     // V trans col group (n=dh)

    for (int jt = 0; jt < 16; jt++) {
        int j0 = jt * 64;
        __syncthreads();   // prior AV reads of Vh + prior K reads done
        #pragma unroll
        for (int it = 0; it < 2; it++) {
            int idx = it * 256 + tid;
            int rr = idx >> 3, c8 = (idx & 7) << 3;
            *(uint4*)&Kh[swzi(rr, c8)] = *(const uint4*)(kp + (size_t)(j0 + rr) * DHv + c8);
            *(uint4*)&Vh[swzi(rr, c8)] = *(const uint4*)(vp + (size_t)(j0 + rr) * DHv + c8);
        }
        // bias prefetch (fragment layout, bf16x2) — latency hidden under QK
        unsigned biasu0[8], biasu1[8];
        #pragma unroll
        for (int nt = 0; nt < 8; nt++) {
            biasu0[nt] = *(const unsigned*)(simp + (size_t)(w16 + r) * Nv + j0 + nt * 8 + 2 * cc);
            biasu1[nt] = *(const unsigned*)(simp + (size_t)(w16 + r + 8) * Nv + j0 + nt * 8 + 2 * cc);
        }
        __syncthreads();
        // ---- QK ----
        float accS[8][4] = {};
        #pragma unroll
        for (int ks = 0; ks < 64; ks += 16) {
            unsigned a[4];
            ldsm4(a[0], a[1], a[2], a[3], qbase + swzi(rowA, ks + cA) * 2);
            #pragma unroll
            for (int n16 = 0; n16 < 4; n16++) {
                unsigned b0, b1, b2, b3;
                ldsm4(b0, b1, b2, b3, kbase + swzi(n16 * 16 + rowBb, ks + cB) * 2);
                unsigned lo[2] = {b0, b1}, hi[2] = {b2, b3};
                mma16(accS[n16 * 2], a, lo);
                mma16(accS[n16 * 2 + 1], a, hi);
            }
        }
        // ---- bias add + online softmax (rows r, r+8; 4-lane reduce) ----
        float mx0 = -3.0e38f, mx1 = -3.0e38f;
        #pragma unroll
        for (int nt = 0; nt < 8; nt++) {
            float2 bias0 = bf2f2(biasu0[nt]);
            float2 bias1 = bf2f2(biasu1[nt]);
            accS[nt][0] += bias0.x; accS[nt][1] += bias0.y;
            accS[nt][2] += bias1.x; accS[nt][3] += bias1.y;
            mx0 = fmaxf(mx0, fmaxf(accS[nt][0], accS[nt][1]));
            mx1 = fmaxf(mx1, fmaxf(accS[nt][2], accS[nt][3]));
        }
        mx0 = fmaxf(mx0, __shfl_xor_sync(~0u, mx0, 1));
        mx0 = fmaxf(mx0, __shfl_xor_sync(~0u, mx0, 2));
        mx1 = fmaxf(mx1, __shfl_xor_sync(~0u, mx1, 1));
        mx1 = fmaxf(mx1, __shfl_xor_sync(~0u, mx1, 2));
        float nm0 = fmaxf(m_run[0], mx0), nm1 = fmaxf(m_run[1], mx1);
        float al0 = __expf(m_run[0] - nm0), al1 = __expf(m_run[1] - nm1);
        m_run[0] = nm0; m_run[1] = nm1;
        float s0 = 0.f, s1 = 0.f;
        #pragma unroll
        for (int nt = 0; nt < 8; nt++) {
            accS[nt][0] = __expf(accS[nt][0] - nm0); s0 += accS[nt][0];
            accS[nt][1] = __expf(accS[nt][1] - nm0); s0 += accS[nt][1];
            accS[nt][2] = __expf(accS[nt][2] - nm1); s1 += accS[nt][2];
            accS[nt][3] = __expf(accS[nt][3] - nm1); s1 += accS[nt][3];
        }
        s0 += __shfl_xor_sync(~0u, s0, 1); s0 += __shfl_xor_sync(~0u, s0, 2);
        s1 += __shfl_xor_sync(~0u, s1, 1); s1 += __shfl_xor_sync(~0u, s1, 2);
        l_run[0] = l_run[0] * al0 + s0;
        l_run[1] = l_run[1] * al1 + s1;
        #pragma unroll
        for (int nt = 0; nt < 8; nt++) {
            accO[nt][0] *= al0; accO[nt][1] *= al0;
            accO[nt][2] *= al1; accO[nt][3] *= al1;
        }
        // ---- P store (warp-private rows of Ph) ----
        #pragma unroll
        for (int nt = 0; nt < 8; nt++) {
            *(unsigned*)&Ph[swzi(w16 + r, nt * 8 + 2 * cc)] =
                cvt2h2(accS[nt][0], accS[nt][1]);
            *(unsigned*)&Ph[swzi(w16 + r + 8, nt * 8 + 2 * cc)] =
                cvt2h2(accS[nt][2], accS[nt][3]);
        }
        __syncwarp();      // P rows consumed only by this warp
        // ---- AV ----
        #pragma unroll
        for (int ksj = 0; ksj < 64; ksj += 16) {
            unsigned a[4];
            ldsm4(a[0], a[1], a[2], a[3], pbase + swzi(rowA, ksj + cA) * 2);
            #pragma unroll
            for (int nd = 0; nd < 4; nd++) {
                unsigned b0, b1, b2, b3;
                ldsm4t(b0, b1, b2, b3, vbase + swzi(ksj + rowVg, nd * 16 + cV) * 2);
                unsigned lo[2] = {b0, b1}, hi[2] = {b2, b3};
                mma16(accO[nd * 2], a, lo);
                mma16(accO[nd * 2 + 1], a, hi);
            }
        }
    }
    float inv0 = 1.f / l_run[0], inv1 = 1.f / l_run[1];
    #pragma unroll
    for (int nt = 0; nt < 8; nt++) {
        int dh = nt * 8 + 2 * cc;
        *(float2*)&g_att[((size_t)b * Nv + i0 + w16 + r) * (Hv * DHv) + h * DHv + dh] =
            make_float2(accO[nt][0] * inv0, accO[nt][1] * inv0);
        *(float2*)&g_att[((size_t)b * Nv + i0 + w16 + r + 8) * (Hv * DHv) + h * DHv + dh] =
            make_float2(accO[nt][2] * inv1, accO[nt][3] * inv1);
    }
}

// ---------------- K6: final out = att @ Wo^T, * seq_mask (fp16 mma) --------
__global__ __launch_bounds__(256) void out_kernel(const float* __restrict__ Wo,
                                                  const float* __restrict__ seq_mask,
                                                  float* __restrict__ out) {
    int c0 = blockIdx.x * 128;
    int m0 = blockIdx.y * 128;
    const float* W = Wo + (size_t)c0 * (Hv * DHv);
    __shared__ __half Ah[128 * 64], Wh[128 * 64];
    int tid = threadIdx.x;
    int lane = tid & 31, w = tid >> 5;
    int wm = w & 3, wn = w >> 2;
    int r = lane >> 2, cc = lane & 3;
    int g = lane >> 3, l8 = lane & 7;
    unsigned abase = sptr(Ah), wbase = sptr(Wh);
    float acc[2][8][4] = {};
    int rowA0 = wm * 32 + ((g & 1) << 3) + l8;
    int cA = (g >> 1) << 3;
    int rowB0 = wn * 64 + ((g >> 1) << 3) + l8;
    int cB = (g & 1) << 3;
    const int K = Hv * DHv;

    for (int kk = 0; kk < K; kk += 64) {
        __syncthreads();
        #pragma unroll
        for (int it = 0; it < 4; it++) {
            int idx = it * 256 + tid;
            int rr = idx >> 3, c8 = (idx & 7) << 3;
            const float* as = g_att + (size_t)(m0 + rr) * K + kk + c8;
            float4 a0 = *(const float4*)as, a1 = *(const float4*)(as + 4);
            *(uint4*)&Ah[swzi(rr, c8)] =
                make_uint4(cvt2h2(a0.x, a0.y), cvt2h2(a0.z, a0.w),
                           cvt2h2(a1.x, a1.y), cvt2h2(a1.z, a1.w));
            const float* ws = W + (size_t)rr * K + kk + c8;
            float4 w0 = *(const float4*)ws, w1 = *(const float4*)(ws + 4);
            *(uint4*)&Wh[swzi(rr, c8)] =
                make_uint4(cvt2h2(w0.x, w0.y), cvt2h2(w0.z, w0.w),
                           cvt2h2(w1.x, w1.y), cvt2h2(w1.z, w1.w));
        }
        __syncthreads();
        #pragma unroll
        for (int ks = 0; ks < 64; ks += 16) {
            unsigned a[2][4];
            ldsm4(a[0][0], a[0][1], a[0][2], a[0][3], abase + swzi(rowA0, ks + cA) * 2);
            ldsm4(a[1][0], a[1][1], a[1][2], a[1][3], abase + swzi(rowA0 + 16, ks + cA) * 2);
            #pragma unroll
            for (int n16 = 0; n16 < 4; n16++) {
                unsigned b0, b1, b2, b3;
                ldsm4(b0, b1, b2, b3, wbase + swzi(rowB0 + n16 * 16, ks + cB) * 2);
                unsigned lo[2] = {b0, b1}, hi[2] = {b2, b3};
                mma16(acc[0][n16 * 2], a[0], lo); mma16(acc[0][n16 * 2 + 1], a[0], hi);
                mma16(acc[1][n16 * 2], a[1], lo); mma16(acc[1][n16 * 2 + 1], a[1], hi);
            }
        }
    }
    #pragma unroll
    for (int f = 0; f < 2; f++) {
        int row0 = m0 + wm * 32 + f * 16 + r;
        float mk0 = seq_mask[row0];
        float mk1 = seq_mask[row0 + 8];
        #pragma unroll
        for (int nt = 0; nt < 8; nt++) {
            int col = c0 + wn * 64 + nt * 8 + 2 * cc;
            *(float2*)&out[(size_t)row0 * Dv + col] =
                make_float2(acc[f][nt][0] * mk0, acc[f][nt][1] * mk0);
            *(float2*)&out[(size_t)(row0 + 8) * Dv + col] =
                make_float2(acc[f][nt][2] * mk1, acc[f][nt][3] * mk1);
        }
    }
}

// ---------------- launch ---------------------------------------------------
extern "C" void kernel_launch(void* const* d_in, const int* in_sizes, int n_in,
                              void* d_out, int out_size) {
    const float* x        = (const float*)d_in[0];
    const float* time_in  = (const float*)d_in[1];
    const float* ab       = (const float*)d_in[2];
    const float* seq_mask = (const float*)d_in[3];
    const float* gamma    = (const float*)d_in[4];
    const float* Wt       = (const float*)d_in[5];
    const float* bt       = (const float*)d_in[6];
    const float* Wq       = (const float*)d_in[7];
    const float* Wkv      = (const float*)d_in[8];
    const float* Wo       = (const float*)d_in[9];
    const float* Wb       = (const float*)d_in[10];
    const float* bb       = (const float*)d_in[11];
    float* out = (float*)d_out;

    film_kernel<<<dim3(Bv, 8), 128>>>(time_in, Wt, bt);
    ln_film_kernel<<<Bv * Nv, 128>>>(x, seq_mask, gamma);
    qkv_kernel<<<dim3(12, 32), 256>>>(x, Wq, Wkv);
    bias_kernel<<<(Bv * Nv * Nv / 2) / 256, 256>>>(ab, seq_mask, Wb, bb);
    flash_kernel<<<dim3(8, Hv, Bv), 256>>>();
    out_kernel<<<dim3(4, 32), 256>>>(Wo, seq_mask, out);
}

// round 10
// speedup vs baseline: 4.7153x; 1.0624x over previous
#include <cuda_runtime.h>
#include <cuda_fp16.h>
#include <cuda_bf16.h>
#include <math.h>

#define Bv 4
#define Nv 1024
#define Dv 512
#define Hv 8
#define DHv 64
#define TCv 512
#define ABv 16

// ---------------- scratch -------------------------------------------------
__device__ float g_scale[Bv * Dv];
__device__ float g_shift[Bv * Dv];
__device__ float g_xn[(size_t)Bv * Nv * Dv];
__device__ __half g_qh[(size_t)Bv * Hv * Nv * DHv];   // pre-scaled by DH^-0.5
__device__ __half g_kh[(size_t)Bv * Hv * Nv * DHv];
__device__ __half g_vh[(size_t)Bv * Hv * Nv * DHv];
__device__ __nv_bfloat16 g_sim[(size_t)Bv * Hv * Nv * Nv];  // bias + penalty (bf16)
__device__ float g_att[(size_t)Bv * Nv * Hv * DHv];

// ---------------- helpers ---------------------------------------------------
__device__ __forceinline__ unsigned sptr(const void* p) {
    return (unsigned)__cvta_generic_to_shared(p);
}
__device__ __forceinline__ unsigned cvt2h2(float lo, float hi) {
    __half2 h = __floats2half2_rn(lo, hi);
    return *reinterpret_cast<unsigned*>(&h);
}
// swizzled half index within a [rows][64] half tile (128B rows, 16B chunks)
__device__ __forceinline__ int swzi(int r, int c) {
    return (r << 6) + ((((c >> 3) ^ (r & 7))) << 3) + (c & 7);
}
__device__ __forceinline__ void mma16(float* c, const unsigned* a, const unsigned* b) {
    asm volatile("mma.sync.aligned.m16n8k16.row.col.f32.f16.f16.f32 "
        "{%0,%1,%2,%3}, {%4,%5,%6,%7}, {%8,%9}, {%0,%1,%2,%3};"
        : "+f"(c[0]), "+f"(c[1]), "+f"(c[2]), "+f"(c[3])
        : "r"(a[0]), "r"(a[1]), "r"(a[2]), "r"(a[3]), "r"(b[0]), "r"(b[1]));
}
__device__ __forceinline__ void ldsm4(unsigned& r0, unsigned& r1, unsigned& r2,
                                      unsigned& r3, unsigned addr) {
    asm volatile("ldmatrix.sync.aligned.m8n8.x4.shared.b16 {%0,%1,%2,%3}, [%4];"
        : "=r"(r0), "=r"(r1), "=r"(r2), "=r"(r3) : "r"(addr));
}
__device__ __forceinline__ void ldsm4t(unsigned& r0, unsigned& r1, unsigned& r2,
                                       unsigned& r3, unsigned addr) {
    asm volatile("ldmatrix.sync.aligned.m8n8.x4.trans.shared.b16 {%0,%1,%2,%3}, [%4];"
        : "=r"(r0), "=r"(r1), "=r"(r2), "=r"(r3) : "r"(addr));
}
__device__ __forceinline__ float2 bf2f2(unsigned u) {
    __nv_bfloat162 b = *reinterpret_cast<__nv_bfloat162*>(&u);
    return __bfloat1622float2(b);
}
__device__ __forceinline__ void cpa16(unsigned dst, const void* src) {
    asm volatile("cp.async.cg.shared.global [%0], [%1], 16;" :: "r"(dst), "l"(src));
}

// ---------------- K1: FiLM params ------------------------------------------
__global__ void film_kernel(const float* __restrict__ time,
                            const float* __restrict__ Wt,
                            const float* __restrict__ bt) {
    int b = blockIdx.x;
    int o = blockIdx.y * 128 + threadIdx.x;
    __shared__ float st[TCv];
    for (int i = threadIdx.x; i < TCv; i += 128) {
        float v = time[b * TCv + i];
        st[i] = v / (1.f + __expf(-v));
    }
    __syncthreads();
    const float* w = Wt + (size_t)o * TCv;
    float acc = bt[o];
    #pragma unroll 8
    for (int t = 0; t < TCv; t++) acc = fmaf(st[t], w[t], acc);
    if (o < Dv) g_scale[b * Dv + o] = acc;
    else        g_shift[b * Dv + (o - Dv)] = acc;
}

// ---------------- K2: LayerNorm + FiLM + seq mask -> g_xn ------------------
__global__ void ln_film_kernel(const float* __restrict__ x,
                               const float* __restrict__ seq_mask,
                               const float* __restrict__ gamma) {
    int row = blockIdx.x;
    int b = row >> 10;
    const float* xr = x + (size_t)row * Dv;
    int tid = threadIdx.x;
    float s = 0.f, ss = 0.f;
    #pragma unroll
    for (int u = 0; u < 4; u++) {
        float v = xr[tid + u * 128];
        s += v; ss += v * v;
    }
    #pragma unroll
    for (int o = 16; o > 0; o >>= 1) {
        s  += __shfl_xor_sync(~0u, s, o);
        ss += __shfl_xor_sync(~0u, ss, o);
    }
    __shared__ float shs[4], shss[4];
    if ((tid & 31) == 0) { shs[tid >> 5] = s; shss[tid >> 5] = ss; }
    __syncthreads();
    s  = shs[0] + shs[1] + shs[2] + shs[3];
    ss = shss[0] + shss[1] + shss[2] + shss[3];
    float mu  = s * (1.f / Dv);
    float var = ss * (1.f / Dv) - mu * mu;
    float inv = rsqrtf(var + 1e-5f);
    float m = seq_mask[row];
    float* out = g_xn + (size_t)row * Dv;
    #pragma unroll
    for (int u = 0; u < 4; u++) {
        int d = tid + u * 128;
        float v = (xr[d] - mu) * inv * gamma[d];
        out[d] = (v * (g_scale[b * Dv + d] + 1.f) + g_shift[b * Dv + d]) * m;
    }
}

// ---------------- K3: merged QKV projections + bias projection -------------
// blocks [0,384): qkv fp16 mma GEMM; blocks [384, 8576): bias proj + penalty.
// qkv blocks first so they start in wave 1 and overlap with bias traffic.
__global__ __launch_bounds__(256) void qkv_bias_kernel(
        const float* __restrict__ x,
        const float* __restrict__ Wq,
        const float* __restrict__ Wkv,
        const float* __restrict__ ab,
        const float* __restrict__ seq_mask,
        const float* __restrict__ Wb,
        const float* __restrict__ bb) {
    int bid = blockIdx.x;
    int tid = threadIdx.x;
    if (bid < 384) {
        // ======== QKV GEMM part ========
        int c0 = (bid % 12) * 128;
        int m0 = (bid / 12) * 128;
        int seg = c0 >> 9;            // 0:q 1:k 2:v
        const float* A = (seg == 0) ? g_xn : x;
        const float* W = (seg == 0) ? (Wq + (size_t)c0 * Dv)
                                    : (Wkv + (size_t)(c0 - 512) * Dv);
        __shared__ __half Ah[128 * 64], Wh[128 * 64];
        int lane = tid & 31, w = tid >> 5;
        int wm = w & 3, wn = w >> 2;
        int r = lane >> 2, cc = lane & 3;
        int g = lane >> 3, l8 = lane & 7;
        unsigned abase = sptr(Ah), wbase = sptr(Wh);
        float acc[2][8][4] = {};
        int rowA0 = wm * 32 + ((g & 1) << 3) + l8;
        int cA = (g >> 1) << 3;
        int rowB0 = wn * 64 + ((g >> 1) << 3) + l8;
        int cB = (g & 1) << 3;

        for (int kk = 0; kk < Dv; kk += 64) {
            __syncthreads();
            #pragma unroll
            for (int it = 0; it < 4; it++) {
                int idx = it * 256 + tid;
                int rr = idx >> 3, c8 = (idx & 7) << 3;
                const float* as = A + (size_t)(m0 + rr) * Dv + kk + c8;
                float4 a0 = *(const float4*)as, a1 = *(const float4*)(as + 4);
                *(uint4*)&Ah[swzi(rr, c8)] =
                    make_uint4(cvt2h2(a0.x, a0.y), cvt2h2(a0.z, a0.w),
                               cvt2h2(a1.x, a1.y), cvt2h2(a1.z, a1.w));
                const float* ws = W + (size_t)rr * Dv + kk + c8;
                float4 w0 = *(const float4*)ws, w1 = *(const float4*)(ws + 4);
                *(uint4*)&Wh[swzi(rr, c8)] =
                    make_uint4(cvt2h2(w0.x, w0.y), cvt2h2(w0.z, w0.w),
                               cvt2h2(w1.x, w1.y), cvt2h2(w1.z, w1.w));
            }
            __syncthreads();
            #pragma unroll
            for (int ks = 0; ks < 64; ks += 16) {
                unsigned a[2][4];
                ldsm4(a[0][0], a[0][1], a[0][2], a[0][3], abase + swzi(rowA0, ks + cA) * 2);
                ldsm4(a[1][0], a[1][1], a[1][2], a[1][3], abase + swzi(rowA0 + 16, ks + cA) * 2);
                #pragma unroll
                for (int n16 = 0; n16 < 4; n16++) {
                    unsigned b0, b1, b2, b3;
                    ldsm4(b0, b1, b2, b3, wbase + swzi(rowB0 + n16 * 16, ks + cB) * 2);
                    unsigned lo[2] = {b0, b1}, hi[2] = {b2, b3};
                    mma16(acc[0][n16 * 2], a[0], lo); mma16(acc[0][n16 * 2 + 1], a[0], hi);
                    mma16(acc[1][n16 * 2], a[1], lo); mma16(acc[1][n16 * 2 + 1], a[1], hi);
                }
            }
        }
        __half* dst = (seg == 0) ? g_qh : (seg == 1) ? g_kh : g_vh;
        float qs = (seg == 0) ? 0.125f : 1.0f;
        int colbase = (c0 & 511) + wn * 64;
        int h = colbase >> 6;
        #pragma unroll
        for (int f = 0; f < 2; f++) {
            int row0 = m0 + wm * 32 + f * 16 + r;
            int b0i = row0 >> 10, n0 = row0 & 1023;
            int b1i = (row0 + 8) >> 10, n1 = (row0 + 8) & 1023;
            #pragma unroll
            for (int nt = 0; nt < 8; nt++) {
                int dh = nt * 8 + 2 * cc;
                *(unsigned*)&dst[(((size_t)b0i * Hv + h) * Nv + n0) * DHv + dh] =
                    cvt2h2(acc[f][nt][0] * qs, acc[f][nt][1] * qs);
                *(unsigned*)&dst[(((size_t)b1i * Hv + h) * Nv + n1) * DHv + dh] =
                    cvt2h2(acc[f][nt][2] * qs, acc[f][nt][3] * qs);
            }
        }
    } else {
        // ======== bias projection + penalty part ========
        __shared__ float wb[Hv * ABv];
        __shared__ float sbb[Hv];
        if (tid < Hv * ABv) wb[tid] = Wb[tid];
        if (tid < Hv) sbb[tid] = bb[tid];
        __syncthreads();
        size_t idx = (size_t)(bid - 384) * 256 + tid;
        int j = (int)(idx & 511) << 1;
        int i = (int)((idx >> 9) & 1023);
        int b = (int)(idx >> 19);
        const float* p = ab + ((size_t)b * ABv * Nv + i) * Nv + j;
        float2 a[ABv];
        #pragma unroll
        for (int aa = 0; aa < ABv; aa++) a[aa] = *(const float2*)(p + (size_t)aa * Nv * Nv);
        float smi = seq_mask[b * Nv + i];
        float2 smj = *(const float2*)&seq_mask[b * Nv + j];
        float pen0 = -(1.f - smi * smj.x) * 1e6f;
        float pen1 = -(1.f - smi * smj.y) * 1e6f;
        #pragma unroll
        for (int h = 0; h < Hv; h++) {
            float ax = sbb[h] + pen0, ay = sbb[h] + pen1;
            #pragma unroll
            for (int aa = 0; aa < ABv; aa++) {
                ax = fmaf(a[aa].x, wb[h * ABv + aa], ax);
                ay = fmaf(a[aa].y, wb[h * ABv + aa], ay);
            }
            __nv_bfloat162 o = __floats2bfloat162_rn(ax, ay);
            *(__nv_bfloat162*)&g_sim[(((size_t)b * Hv + h) * Nv + i) * Nv + j] = o;
        }
    }
}

// ---------------- K5: fused flash QK + softmax + AV (fp16 mma, cp.async) ---
// 256 threads / 8 warps; i-tile 128, j-tile 64 double-buffered. 64 KB dyn smem.
__global__ __launch_bounds__(256) void flash_kernel() {
    extern __shared__ __half smf[];
    __half* Qh = smf;                 // [0, 8192)
    __half* Ph = smf + 24576;         // [24576, 32768)
    int tid = threadIdx.x;
    int lane = tid & 31, w = tid >> 5;      // w 0..7
    int w16 = w * 16;
    int r = lane >> 2, cc = lane & 3;
    int g = lane >> 3, l8 = lane & 7;
    int i0 = blockIdx.x * 128;
    int h = blockIdx.y, b = blockIdx.z;
    int bh = b * Hv + h;
    const __half* qp = g_qh + ((size_t)bh * Nv + i0) * DHv;
    const __half* kp = g_kh + (size_t)bh * Nv * DHv;
    const __half* vp = g_vh + (size_t)bh * Nv * DHv;
    const __nv_bfloat16* simp = g_sim + ((size_t)bh * Nv + i0) * Nv;
    unsigned qbase = sptr(Qh), pbase = sptr(Ph);
    unsigned kb0 = sptr(smf + 8192);      // K buffers: 8192 B each
    unsigned vb0 = sptr(smf + 16384);     // V buffers: 8192 B each

    // Q tile load (once): 128 x 64
    #pragma unroll
    for (int it = 0; it < 4; it++) {
        int idx = it * 256 + tid;
        int rr = idx >> 3, c8 = (idx & 7) << 3;
        *(uint4*)&Qh[swzi(rr, c8)] = *(const uint4*)(qp + rr * DHv + c8);
    }

    // prologue: async K/V loads for jt=0 into buffer 0
    {
        #pragma unroll
        for (int it = 0; it < 2; it++) {
            int idx = it * 256 + tid;
            int rr = idx >> 3, c8 = (idx & 7) << 3;
            cpa16(kb0 + swzi(rr, c8) * 2, kp + (size_t)rr * DHv + c8);
            cpa16(vb0 + swzi(rr, c8) * 2, vp + (size_t)rr * DHv + c8);
        }
        asm volatile("cp.async.commit_group;" ::: "memory");
    }

    float m_run[2] = {-3.0e38f, -3.0e38f};
    float l_run[2] = {0.f, 0.f};
    float accO[8][4] = {};
    int rowA = w16 + ((g & 1) << 3) + l8;       // A-frag rows (Q and P), warp-private
    int cA = (g >> 1) << 3;
    int rowBb = ((g >> 1) << 3) + l8;           // B-frag rows (K)
    int cB = (g & 1) << 3;
    int rowVg = ((g & 1) << 3) + l8;            // V trans rows (k=j)
    int cV = (g >> 1) << 3;                     // V trans col group (n=dh)

    for (int jt = 0; jt < 16; jt++) {
        int j0 = jt * 64;
        int bi = jt & 1;
        unsigned kbase = kb0 + bi * 8192;
        unsigned vbase = vb0 + bi * 8192;
        // bias prefetch (fragment layout, bf16x2) — consumed after QK
        unsigned biasu0[8], biasu1[8];
        #pragma unroll
        for (int nt = 0; nt < 8; nt++) {
            biasu0[nt] = *(const unsigned*)(simp + (size_t)(w16 + r) * Nv + j0 + nt * 8 + 2 * cc);
            biasu1[nt] = *(const unsigned*)(simp + (size_t)(w16 + r + 8) * Nv + j0 + nt * 8 + 2 * cc);
        }
        asm volatile("cp.async.wait_group 0;" ::: "memory");
        __syncthreads();   // jt data visible everywhere; all warps past jt-1 compute
        if (jt < 15) {     // async loads for jt+1 into the other buffer
            unsigned kn = kb0 + (bi ^ 1) * 8192;
            unsigned vn = vb0 + (bi ^ 1) * 8192;
            const __half* kpn = kp + (size_t)(j0 + 64) * DHv;
            const __half* vpn = vp + (size_t)(j0 + 64) * DHv;
            #pragma unroll
            for (int it = 0; it < 2; it++) {
                int idx = it * 256 + tid;
                int rr = idx >> 3, c8 = (idx & 7) << 3;
                cpa16(kn + swzi(rr, c8) * 2, kpn + (size_t)rr * DHv + c8);
                cpa16(vn + swzi(rr, c8) * 2, vpn + (size_t)rr * DHv + c8);
            }
            asm volatile("cp.async.commit_group;" ::: "memory");
        }
        // ---- QK ----
        float accS[8][4] = {};
        #pragma unroll
        for (int ks = 0; ks < 64; ks += 16) {
            unsigned a[4];
            ldsm4(a[0], a[1], a[2], a[3], qbase + swzi(rowA, ks + cA) * 2);
            #pragma unroll
            for (int n16 = 0; n16 < 4; n16++) {
                unsigned b0, b1, b2, b3;
                ldsm4(b0, b1, b2, b3, kbase + swzi(n16 * 16 + rowBb, ks + cB) * 2);
                unsigned lo[2] = {b0, b1}, hi[2] = {b2, b3};
                mma16(accS[n16 * 2], a, lo);
                mma16(accS[n16 * 2 + 1], a, hi);
            }
        }
        // ---- bias add + online softmax (rows r, r+8; 4-lane reduce) ----
        float mx0 = -3.0e38f, mx1 = -3.0e38f;
        #pragma unroll
        for (int nt = 0; nt < 8; nt++) {
            float2 bias0 = bf2f2(biasu0[nt]);
            float2 bias1 = bf2f2(biasu1[nt]);
            accS[nt][0] += bias0.x; accS[nt][1] += bias0.y;
            accS[nt][2] += bias1.x; accS[nt][3] += bias1.y;
            mx0 = fmaxf(mx0, fmaxf(accS[nt][0], accS[nt][1]));
            mx1 = fmaxf(mx1, fmaxf(accS[nt][2], accS[nt][3]));
        }
        mx0 = fmaxf(mx0, __shfl_xor_sync(~0u, mx0, 1));
        mx0 = fmaxf(mx0, __shfl_xor_sync(~0u, mx0, 2));
        mx1 = fmaxf(mx1, __shfl_xor_sync(~0u, mx1, 1));
        mx1 = fmaxf(mx1, __shfl_xor_sync(~0u, mx1, 2));
        float nm0 = fmaxf(m_run[0], mx0), nm1 = fmaxf(m_run[1], mx1);
        float al0 = __expf(m_run[0] - nm0), al1 = __expf(m_run[1] - nm1);
        m_run[0] = nm0; m_run[1] = nm1;
        float s0 = 0.f, s1 = 0.f;
        #pragma unroll
        for (int nt = 0; nt < 8; nt++) {
            accS[nt][0] = __expf(accS[nt][0] - nm0); s0 += accS[nt][0];
            accS[nt][1] = __expf(accS[nt][1] - nm0); s0 += accS[nt][1];
            accS[nt][2] = __expf(accS[nt][2] - nm1); s1 += accS[nt][2];
            accS[nt][3] = __expf(accS[nt][3] - nm1); s1 += accS[nt][3];
        }
        s0 += __shfl_xor_sync(~0u, s0, 1); s0 += __shfl_xor_sync(~0u, s0, 2);
        s1 += __shfl_xor_sync(~0u, s1, 1); s1 += __shfl_xor_sync(~0u, s1, 2);
        l_run[0] = l_run[0] * al0 + s0;
        l_run[1] = l_run[1] * al1 + s1;
        #pragma unroll
        for (int nt = 0; nt < 8; nt++) {
            accO[nt][0] *= al0; accO[nt][1] *= al0;
            accO[nt][2] *= al1; accO[nt][3] *= al1;
        }
        // ---- P store (warp-private rows of Ph) ----
        #pragma unroll
        for (int nt = 0; nt < 8; nt++) {
            *(unsigned*)&Ph[swzi(w16 + r, nt * 8 + 2 * cc)] =
                cvt2h2(accS[nt][0], accS[nt][1]);
            *(unsigned*)&Ph[swzi(w16 + r + 8, nt * 8 + 2 * cc)] =
                cvt2h2(accS[nt][2], accS[nt][3]);
        }
        __syncwarp();      // P rows consumed only by this warp
        // ---- AV ----
        #pragma unroll
        for (int ksj = 0; ksj < 64; ksj += 16) {
            unsigned a[4];
            ldsm4(a[0], a[1], a[2], a[3], pbase + swzi(rowA, ksj + cA) * 2);
            #pragma unroll
            for (int nd = 0; nd < 4; nd++) {
                unsigned b0, b1, b2, b3;
                ldsm4t(b0, b1, b2, b3, vbase + swzi(ksj + rowVg, nd * 16 + cV) * 2);
                unsigned lo[2] = {b0, b1}, hi[2] = {b2, b3};
                mma16(accO[nd * 2], a, lo);
                mma16(accO[nd * 2 + 1], a, hi);
            }
        }
    }
    float inv0 = 1.f / l_run[0], inv1 = 1.f / l_run[1];
    #pragma unroll
    for (int nt = 0; nt < 8; nt++) {
        int dh = nt * 8 + 2 * cc;
        *(float2*)&g_att[((size_t)b * Nv + i0 + w16 + r) * (Hv * DHv) + h * DHv + dh] =
            make_float2(accO[nt][0] * inv0, accO[nt][1] * inv0);
        *(float2*)&g_att[((size_t)b * Nv + i0 + w16 + r + 8) * (Hv * DHv) + h * DHv + dh] =
            make_float2(accO[nt][2] * inv1, accO[nt][3] * inv1);
    }
}

// ---------------- K6: final out = att @ Wo^T, * seq_mask (fp16 mma) --------
__global__ __launch_bounds__(256) void out_kernel(const float* __restrict__ Wo,
                                                  const float* __restrict__ seq_mask,
                                                  float* __restrict__ out) {
    int c0 = blockIdx.x * 128;
    int m0 = blockIdx.y * 128;
    const float* W = Wo + (size_t)c0 * (Hv * DHv);
    __shared__ __half Ah[128 * 64], Wh[128 * 64];
    int tid = threadIdx.x;
    int lane = tid & 31, w = tid >> 5;
    int wm = w & 3, wn = w >> 2;
    int r = lane >> 2, cc = lane & 3;
    int g = lane >> 3, l8 = lane & 7;
    unsigned abase = sptr(Ah), wbase = sptr(Wh);
    float acc[2][8][4] = {};
    int rowA0 = wm * 32 + ((g & 1) << 3) + l8;
    int cA = (g >> 1) << 3;
    int rowB0 = wn * 64 + ((g >> 1) << 3) + l8;
    int cB = (g & 1) << 3;
    const int K = Hv * DHv;

    for (int kk = 0; kk < K; kk += 64) {
        __syncthreads();
        #pragma unroll
        for (int it = 0; it < 4; it++) {
            int idx = it * 256 + tid;
            int rr = idx >> 3, c8 = (idx & 7) << 3;
            const float* as = g_att + (size_t)(m0 + rr) * K + kk + c8;
            float4 a0 = *(const float4*)as, a1 = *(const float4*)(as + 4);
            *(uint4*)&Ah[swzi(rr, c8)] =
                make_uint4(cvt2h2(a0.x, a0.y), cvt2h2(a0.z, a0.w),
                           cvt2h2(a1.x, a1.y), cvt2h2(a1.z, a1.w));
            const float* ws = W + (size_t)rr * K + kk + c8;
            float4 w0 = *(const float4*)ws, w1 = *(const float4*)(ws + 4);
            *(uint4*)&Wh[swzi(rr, c8)] =
                make_uint4(cvt2h2(w0.x, w0.y), cvt2h2(w0.z, w0.w),
                           cvt2h2(w1.x, w1.y), cvt2h2(w1.z, w1.w));
        }
        __syncthreads();
        #pragma unroll
        for (int ks = 0; ks < 64; ks += 16) {
            unsigned a[2][4];
            ldsm4(a[0][0], a[0][1], a[0][2], a[0][3], abase + swzi(rowA0, ks + cA) * 2);
            ldsm4(a[1][0], a[1][1], a[1][2], a[1][3], abase + swzi(rowA0 + 16, ks + cA) * 2);
            #pragma unroll
            for (int n16 = 0; n16 < 4; n16++) {
                unsigned b0, b1, b2, b3;
                ldsm4(b0, b1, b2, b3, wbase + swzi(rowB0 + n16 * 16, ks + cB) * 2);
                unsigned lo[2] = {b0, b1}, hi[2] = {b2, b3};
                mma16(acc[0][n16 * 2], a[0], lo); mma16(acc[0][n16 * 2 + 1], a[0], hi);
                mma16(acc[1][n16 * 2], a[1], lo); mma16(acc[1][n16 * 2 + 1], a[1], hi);
            }
        }
    }
    #pragma unroll
    for (int f = 0; f < 2; f++) {
        int row0 = m0 + wm * 32 + f * 16 + r;
        float mk0 = seq_mask[row0];
        float mk1 = seq_mask[row0 + 8];
        #pragma unroll
        for (int nt = 0; nt < 8; nt++) {
            int col = c0 + wn * 64 + nt * 8 + 2 * cc;
            *(float2*)&out[(size_t)row0 * Dv + col] =
                make_float2(acc[f][nt][0] * mk0, acc[f][nt][1] * mk0);
            *(float2*)&out[(size_t)(row0 + 8) * Dv + col] =
                make_float2(acc[f][nt][2] * mk1, acc[f][nt][3] * mk1);
        }
    }
}

// ---------------- launch ---------------------------------------------------
extern "C" void kernel_launch(void* const* d_in, const int* in_sizes, int n_in,
                              void* d_out, int out_size) {
    const float* x        = (const float*)d_in[0];
    const float* time_in  = (const float*)d_in[1];
    const float* ab       = (const float*)d_in[2];
    const float* seq_mask = (const float*)d_in[3];
    const float* gamma    = (const float*)d_in[4];
    const float* Wt       = (const float*)d_in[5];
    const float* bt       = (const float*)d_in[6];
    const float* Wq       = (const float*)d_in[7];
    const float* Wkv      = (const float*)d_in[8];
    const float* Wo       = (const float*)d_in[9];
    const float* Wb       = (const float*)d_in[10];
    const float* bb       = (const float*)d_in[11];
    float* out = (float*)d_out;

    static bool attr_set = false;
    if (!attr_set) {
        cudaFuncSetAttribute(flash_kernel,
                             cudaFuncAttributeMaxDynamicSharedMemorySize, 65536);
        attr_set = true;
    }

    film_kernel<<<dim3(Bv, 8), 128>>>(time_in, Wt, bt);
    ln_film_kernel<<<Bv * Nv, 128>>>(x, seq_mask, gamma);
    qkv_bias_kernel<<<384 + 8192, 256>>>(x, Wq, Wkv, ab, seq_mask, Wb, bb);
    flash_kernel<<<dim3(8, Hv, Bv), 256, 65536>>>();
    out_kernel<<<dim3(4, 32), 256>>>(Wo, seq_mask, out);
}

// round 13
// speedup vs baseline: 5.0069x; 1.0618x over previous
#include <cuda_runtime.h>
#include <cuda_fp16.h>
#include <cuda_bf16.h>
#include <math.h>

#define Bv 4
#define Nv 1024
#define Dv 512
#define Hv 8
#define DHv 64
#define TCv 512
#define ABv 16

// ---------------- scratch -------------------------------------------------
__device__ float g_scale[Bv * Dv];
__device__ float g_shift[Bv * Dv];
__device__ __half g_xnh[(size_t)Bv * Nv * Dv];        // LN+FiLM output (fp16)
__device__ __half g_qh[(size_t)Bv * Hv * Nv * DHv];   // pre-scaled by DH^-0.5
__device__ __half g_kh[(size_t)Bv * Hv * Nv * DHv];
__device__ __half g_vh[(size_t)Bv * Hv * Nv * DHv];
__device__ __nv_bfloat16 g_sim[(size_t)Bv * Hv * Nv * Nv];  // bias + penalty (bf16)
__device__ __half g_atth[(size_t)Bv * Nv * Hv * DHv]; // attention output (fp16)

// ---------------- helpers ---------------------------------------------------
__device__ __forceinline__ unsigned sptr(const void* p) {
    return (unsigned)__cvta_generic_to_shared(p);
}
__device__ __forceinline__ unsigned cvt2h2(float lo, float hi) {
    __half2 h = __floats2half2_rn(lo, hi);
    return *reinterpret_cast<unsigned*>(&h);
}
// swizzled half index within a [rows][64] half tile (128B rows, 16B chunks)
__device__ __forceinline__ int swzi(int r, int c) {
    return (r << 6) + ((((c >> 3) ^ (r & 7))) << 3) + (c & 7);
}
__device__ __forceinline__ void mma16(float* c, const unsigned* a, const unsigned* b) {
    asm volatile("mma.sync.aligned.m16n8k16.row.col.f32.f16.f16.f32 "
        "{%0,%1,%2,%3}, {%4,%5,%6,%7}, {%8,%9}, {%0,%1,%2,%3};"
        : "+f"(c[0]), "+f"(c[1]), "+f"(c[2]), "+f"(c[3])
        : "r"(a[0]), "r"(a[1]), "r"(a[2]), "r"(a[3]), "r"(b[0]), "r"(b[1]));
}
__device__ __forceinline__ void ldsm4(unsigned& r0, unsigned& r1, unsigned& r2,
                                      unsigned& r3, unsigned addr) {
    asm volatile("ldmatrix.sync.aligned.m8n8.x4.shared.b16 {%0,%1,%2,%3}, [%4];"
        : "=r"(r0), "=r"(r1), "=r"(r2), "=r"(r3) : "r"(addr));
}
__device__ __forceinline__ void ldsm4t(unsigned& r0, unsigned& r1, unsigned& r2,
                                       unsigned& r3, unsigned addr) {
    asm volatile("ldmatrix.sync.aligned.m8n8.x4.trans.shared.b16 {%0,%1,%2,%3}, [%4];"
        : "=r"(r0), "=r"(r1), "=r"(r2), "=r"(r3) : "r"(addr));
}
__device__ __forceinline__ float2 bf2f2(unsigned u) {
    __nv_bfloat162 b = *reinterpret_cast<__nv_bfloat162*>(&u);
    return __bfloat1622float2(b);
}
__device__ __forceinline__ void cpa16(unsigned dst, const void* src) {
    asm volatile("cp.async.cg.shared.global [%0], [%1], 16;" :: "r"(dst), "l"(src));
}

// ---------------- K1: FiLM params ------------------------------------------
__global__ void film_kernel(const float* __restrict__ time,
                            const float* __restrict__ Wt,
                            const float* __restrict__ bt) {
    int b = blockIdx.x;
    int o = blockIdx.y * 128 + threadIdx.x;
    __shared__ float st[TCv];
    for (int i = threadIdx.x; i < TCv; i += 128) {
        float v = time[b * TCv + i];
        st[i] = v / (1.f + __expf(-v));
    }
    __syncthreads();
    const float* w = Wt + (size_t)o * TCv;
    float acc = bt[o];
    #pragma unroll 8
    for (int t = 0; t < TCv; t++) acc = fmaf(st[t], w[t], acc);
    if (o < Dv) g_scale[b * Dv + o] = acc;
    else        g_shift[b * Dv + (o - Dv)] = acc;
}

// ---------------- K2: LayerNorm + FiLM + seq mask -> g_xnh (fp16) ----------
__global__ void ln_film_kernel(const float* __restrict__ x,
                               const float* __restrict__ seq_mask,
                               const float* __restrict__ gamma) {
    int row = blockIdx.x;
    int b = row >> 10;
    const float* xr = x + (size_t)row * Dv;
    int tid = threadIdx.x;
    float s = 0.f, ss = 0.f;
    #pragma unroll
    for (int u = 0; u < 4; u++) {
        float v = xr[tid + u * 128];
        s += v; ss += v * v;
    }
    #pragma unroll
    for (int o = 16; o > 0; o >>= 1) {
        s  += __shfl_xor_sync(~0u, s, o);
        ss += __shfl_xor_sync(~0u, ss, o);
    }
    __shared__ float shs[4], shss[4];
    if ((tid & 31) == 0) { shs[tid >> 5] = s; shss[tid >> 5] = ss; }
    __syncthreads();
    s  = shs[0] + shs[1] + shs[2] + shs[3];
    ss = shss[0] + shss[1] + shss[2] + shss[3];
    float mu  = s * (1.f / Dv);
    float var = ss * (1.f / Dv) - mu * mu;
    float inv = rsqrtf(var + 1e-5f);
    float m = seq_mask[row];
    __half* out = g_xnh + (size_t)row * Dv;
    #pragma unroll
    for (int u = 0; u < 4; u++) {
        int d = tid + u * 128;
        float v = (xr[d] - mu) * inv * gamma[d];
        out[d] = __float2half((v * (g_scale[b * Dv + d] + 1.f) + g_shift[b * Dv + d]) * m);
    }
}

// ---------------- K3: merged QKV projections + bias projection -------------
__global__ __launch_bounds__(256) void qkv_bias_kernel(
        const float* __restrict__ x,
        const float* __restrict__ Wq,
        const float* __restrict__ Wkv,
        const float* __restrict__ ab,
        const float* __restrict__ seq_mask,
        const float* __restrict__ Wb,
        const float* __restrict__ bb) {
    int bid = blockIdx.x;
    int tid = threadIdx.x;
    if (bid < 384) {
        // ======== QKV GEMM part ========
        int c0 = (bid % 12) * 128;
        int m0 = (bid / 12) * 128;
        int seg = c0 >> 9;            // 0:q 1:k 2:v
        const float* W = (seg == 0) ? (Wq + (size_t)c0 * Dv)
                                    : (Wkv + (size_t)(c0 - 512) * Dv);
        __shared__ __half Ah[128 * 64], Wh[128 * 64];
        int lane = tid & 31, w = tid >> 5;
        int wm = w & 3, wn = w >> 2;
        int r = lane >> 2, cc = lane & 3;
        int g = lane >> 3, l8 = lane & 7;
        unsigned abase = sptr(Ah), wbase = sptr(Wh);
        float acc[2][8][4] = {};
        int rowA0 = wm * 32 + ((g & 1) << 3) + l8;
        int cA = (g >> 1) << 3;
        int rowB0 = wn * 64 + ((g >> 1) << 3) + l8;
        int cB = (g & 1) << 3;

        for (int kk = 0; kk < Dv; kk += 64) {
            __syncthreads();
            #pragma unroll
            for (int it = 0; it < 4; it++) {
                int idx = it * 256 + tid;
                int rr = idx >> 3, c8 = (idx & 7) << 3;
                if (seg == 0) {
                    *(uint4*)&Ah[swzi(rr, c8)] =
                        *(const uint4*)(g_xnh + (size_t)(m0 + rr) * Dv + kk + c8);
                } else {
                    const float* as = x + (size_t)(m0 + rr) * Dv + kk + c8;
                    float4 a0 = *(const float4*)as, a1 = *(const float4*)(as + 4);
                    *(uint4*)&Ah[swzi(rr, c8)] =
                        make_uint4(cvt2h2(a0.x, a0.y), cvt2h2(a0.z, a0.w),
                                   cvt2h2(a1.x, a1.y), cvt2h2(a1.z, a1.w));
                }
                const float* ws = W + (size_t)rr * Dv + kk + c8;
                float4 w0 = *(const float4*)ws, w1 = *(const float4*)(ws + 4);
                *(uint4*)&Wh[swzi(rr, c8)] =
                    make_uint4(cvt2h2(w0.x, w0.y), cvt2h2(w0.z, w0.w),
                               cvt2h2(w1.x, w1.y), cvt2h2(w1.z, w1.w));
            }
            __syncthreads();
            #pragma unroll
            for (int ks = 0; ks < 64; ks += 16) {
                unsigned a[2][4];
                ldsm4(a[0][0], a[0][1], a[0][2], a[0][3], abase + swzi(rowA0, ks + cA) * 2);
                ldsm4(a[1][0], a[1][1], a[1][2], a[1][3], abase + swzi(rowA0 + 16, ks + cA) * 2);
                #pragma unroll
                for (int n16 = 0; n16 < 4; n16++) {
                    unsigned b0, b1, b2, b3;
                    ldsm4(b0, b1, b2, b3, wbase + swzi(rowB0 + n16 * 16, ks + cB) * 2);
                    unsigned lo[2] = {b0, b1}, hi[2] = {b2, b3};
                    mma16(acc[0][n16 * 2], a[0], lo); mma16(acc[0][n16 * 2 + 1], a[0], hi);
                    mma16(acc[1][n16 * 2], a[1], lo); mma16(acc[1][n16 * 2 + 1], a[1], hi);
                }
            }
        }
        __half* dst = (seg == 0) ? g_qh : (seg == 1) ? g_kh : g_vh;
        float qs = (seg == 0) ? 0.125f : 1.0f;
        int colbase = (c0 & 511) + wn * 64;
        int h = colbase >> 6;
        #pragma unroll
        for (int f = 0; f < 2; f++) {
            int row0 = m0 + wm * 32 + f * 16 + r;
            int b0i = row0 >> 10, n0 = row0 & 1023;
            int b1i = (row0 + 8) >> 10, n1 = (row0 + 8) & 1023;
            #pragma unroll
            for (int nt = 0; nt < 8; nt++) {
                int dh = nt * 8 + 2 * cc;
                *(unsigned*)&dst[(((size_t)b0i * Hv + h) * Nv + n0) * DHv + dh] =
                    cvt2h2(acc[f][nt][0] * qs, acc[f][nt][1] * qs);
                *(unsigned*)&dst[(((size_t)b1i * Hv + h) * Nv + n1) * DHv + dh] =
                    cvt2h2(acc[f][nt][2] * qs, acc[f][nt][3] * qs);
            }
        }
    } else {
        // ======== bias projection + penalty part ========
        __shared__ float wb[Hv * ABv];
        __shared__ float sbb[Hv];
        if (tid < Hv * ABv) wb[tid] = Wb[tid];
        if (tid < Hv) sbb[tid] = bb[tid];
        __syncthreads();
        size_t idx = (size_t)(bid - 384) * 256 + tid;
        int j = (int)(idx & 511) << 1;
        int i = (int)((idx >> 9) & 1023);
        int b = (int)(idx >> 19);
        const float* p = ab + ((size_t)b * ABv * Nv + i) * Nv + j;
        float2 a[ABv];
        #pragma unroll
        for (int aa = 0; aa < ABv; aa++) a[aa] = *(const float2*)(p + (size_t)aa * Nv * Nv);
        float smi = seq_mask[b * Nv + i];
        float2 smj = *(const float2*)&seq_mask[b * Nv + j];
        float pen0 = -(1.f - smi * smj.x) * 1e6f;
        float pen1 = -(1.f - smi * smj.y) * 1e6f;
        #pragma unroll
        for (int h = 0; h < Hv; h++) {
            float ax = sbb[h] + pen0, ay = sbb[h] + pen1;
            #pragma unroll
            for (int aa = 0; aa < ABv; aa++) {
                ax = fmaf(a[aa].x, wb[h * ABv + aa], ax);
                ay = fmaf(a[aa].y, wb[h * ABv + aa], ay);
            }
            __nv_bfloat162 o = __floats2bfloat162_rn(ax, ay);
            *(__nv_bfloat162*)&g_sim[(((size_t)b * Hv + h) * Nv + i) * Nv + j] = o;
        }
    }
}

// ---------------- K5: fused flash (fp16 mma, cp.async, register P) ---------
// 256 threads / 8 warps; i-tile 128, j-tile 64 double-buffered. 32 KB dyn smem.
// Q fragments hoisted to registers; P stays in registers (C-frag == A-frag).
__global__ __launch_bounds__(256, 2) void flash_kernel() {
    extern __shared__ __half smf[];
    int tid = threadIdx.x;
    int lane = tid & 31, w = tid >> 5;      // w 0..7
    int w16 = w * 16;
    int r = lane >> 2, cc = lane & 3;
    int g = lane >> 3, l8 = lane & 7;
    int i0 = blockIdx.x * 128;
    int h = blockIdx.y, b = blockIdx.z;
    int bh = b * Hv + h;
    const __half* qp = g_qh + ((size_t)bh * Nv + i0) * DHv;
    const __half* kp = g_kh + (size_t)bh * Nv * DHv;
    const __half* vp = g_vh + (size_t)bh * Nv * DHv;
    const __nv_bfloat16* simp = g_sim + ((size_t)bh * Nv + i0) * Nv;
    unsigned kb0 = sptr(smf);             // K buffers: 2 x 8192 B
    unsigned vb0 = sptr(smf + 8192);      // V buffers: 2 x 8192 B (byte 16384)

    // Q fragments: direct half2 LDGs in A-fragment layout (jt-invariant)
    unsigned qfrag[4][4];
    #pragma unroll
    for (int t = 0; t < 4; t++) {
        int ks = t * 16;
        qfrag[t][0] = *(const unsigned*)(qp + (w16 + r) * DHv + ks + 2 * cc);
        qfrag[t][1] = *(const unsigned*)(qp + (w16 + r + 8) * DHv + ks + 2 * cc);
        qfrag[t][2] = *(const unsigned*)(qp + (w16 + r) * DHv + ks + 8 + 2 * cc);
        qfrag[t][3] = *(const unsigned*)(qp + (w16 + r + 8) * DHv + ks + 8 + 2 * cc);
    }

    // prologue: async K/V loads for jt=0 into buffer 0
    #pragma unroll
    for (int it = 0; it < 2; it++) {
        int idx = it * 256 + tid;
        int rr = idx >> 3, c8 = (idx & 7) << 3;
        cpa16(kb0 + swzi(rr, c8) * 2, kp + (size_t)rr * DHv + c8);
        cpa16(vb0 + swzi(rr, c8) * 2, vp + (size_t)rr * DHv + c8);
    }
    asm volatile("cp.async.commit_group;" ::: "memory");

    float m_run[2] = {-3.0e38f, -3.0e38f};
    float l_run[2] = {0.f, 0.f};
    float accO[8][4] = {};
    int rowBb = ((g >> 1) << 3) + l8;           // B-frag rows (K)
    int cB = (g & 1) << 3;
    int rowVg = ((g & 1) << 3) + l8;            // V trans rows (k=j)
    int cV = (g >> 1) << 3;                     // V trans col group (n=dh)

    for (int jt = 0; jt < 16; jt++) {
        int j0 = jt * 64;
        int bi = jt & 1;
        unsigned kbase = kb0 + bi * 8192;
        unsigned vbase = vb0 + bi * 8192;
        // bias prefetch (fragment layout, bf16x2) — consumed after QK
        unsigned biasu0[8], biasu1[8];
        #pragma unroll
        for (int nt = 0; nt < 8; nt++) {
            biasu0[nt] = *(const unsigned*)(simp + (size_t)(w16 + r) * Nv + j0 + nt * 8 + 2 * cc);
            biasu1[nt] = *(const unsigned*)(simp + (size_t)(w16 + r + 8) * Nv + j0 + nt * 8 + 2 * cc);
        }
        asm volatile("cp.async.wait_group 0;" ::: "memory");
        __syncthreads();
        if (jt < 15) {     // async loads for jt+1 into the other buffer
            unsigned kn = kb0 + (bi ^ 1) * 8192;
            unsigned vn = vb0 + (bi ^ 1) * 8192;
            const __half* kpn = kp + (size_t)(j0 + 64) * DHv;
            const __half* vpn = vp + (size_t)(j0 + 64) * DHv;
            #pragma unroll
            for (int it = 0; it < 2; it++) {
                int idx = it * 256 + tid;
                int rr = idx >> 3, c8 = (idx & 7) << 3;
                cpa16(kn + swzi(rr, c8) * 2, kpn + (size_t)rr * DHv + c8);
                cpa16(vn + swzi(rr, c8) * 2, vpn + (size_t)rr * DHv + c8);
            }
            asm volatile("cp.async.commit_group;" ::: "memory");
        }
        // ---- QK ----
        float accS[8][4] = {};
        #pragma unroll
        for (int t = 0; t < 4; t++) {
            int ks = t * 16;
            #pragma unroll
            for (int n16 = 0; n16 < 4; n16++) {
                unsigned b0, b1, b2, b3;
                ldsm4(b0, b1, b2, b3, kbase + swzi(n16 * 16 + rowBb, ks + cB) * 2);
                unsigned lo[2] = {b0, b1}, hi[2] = {b2, b3};
                mma16(accS[n16 * 2], qfrag[t], lo);
                mma16(accS[n16 * 2 + 1], qfrag[t], hi);
            }
        }
        // ---- bias add + online softmax (rows r, r+8; 4-lane reduce) ----
        float mx0 = -3.0e38f, mx1 = -3.0e38f;
        #pragma unroll
        for (int nt = 0; nt < 8; nt++) {
            float2 bias0 = bf2f2(biasu0[nt]);
            float2 bias1 = bf2f2(biasu1[nt]);
            accS[nt][0] += bias0.x; accS[nt][1] += bias0.y;
            accS[nt][2] += bias1.x; accS[nt][3] += bias1.y;
            mx0 = fmaxf(mx0, fmaxf(accS[nt][0], accS[nt][1]));
            mx1 = fmaxf(mx1, fmaxf(accS[nt][2], accS[nt][3]));
        }
        mx0 = fmaxf(mx0, __shfl_xor_sync(~0u, mx0, 1));
        mx0 = fmaxf(mx0, __shfl_xor_sync(~0u, mx0, 2));
        mx1 = fmaxf(mx1, __shfl_xor_sync(~0u, mx1, 1));
        mx1 = fmaxf(mx1, __shfl_xor_sync(~0u, mx1, 2));
        float nm0 = fmaxf(m_run[0], mx0), nm1 = fmaxf(m_run[1], mx1);
        float al0 = __expf(m_run[0] - nm0), al1 = __expf(m_run[1] - nm1);
        m_run[0] = nm0; m_run[1] = nm1;
        float s0 = 0.f, s1 = 0.f;
        #pragma unroll
        for (int nt = 0; nt < 8; nt++) {
            accS[nt][0] = __expf(accS[nt][0] - nm0); s0 += accS[nt][0];
            accS[nt][1] = __expf(accS[nt][1] - nm0); s0 += accS[nt][1];
            accS[nt][2] = __expf(accS[nt][2] - nm1); s1 += accS[nt][2];
            accS[nt][3] = __expf(accS[nt][3] - nm1); s1 += accS[nt][3];
        }
        s0 += __shfl_xor_sync(~0u, s0, 1); s0 += __shfl_xor_sync(~0u, s0, 2);
        s1 += __shfl_xor_sync(~0u, s1, 1); s1 += __shfl_xor_sync(~0u, s1, 2);
        l_run[0] = l_run[0] * al0 + s0;
        l_run[1] = l_run[1] * al1 + s1;
        #pragma unroll
        for (int nt = 0; nt < 8; nt++) {
            accO[nt][0] *= al0; accO[nt][1] *= al0;
            accO[nt][2] *= al1; accO[nt][3] *= al1;
        }
        // ---- AV: P stays in registers (C-frag == A-frag layout, j -> k) ----
        #pragma unroll
        for (int t = 0; t < 4; t++) {
            unsigned a[4];
            a[0] = cvt2h2(accS[2 * t][0],     accS[2 * t][1]);
            a[1] = cvt2h2(accS[2 * t][2],     accS[2 * t][3]);
            a[2] = cvt2h2(accS[2 * t + 1][0], accS[2 * t + 1][1]);
            a[3] = cvt2h2(accS[2 * t + 1][2], accS[2 * t + 1][3]);
            int ksj = t * 16;
            #pragma unroll
            for (int nd = 0; nd < 4; nd++) {
                unsigned b0, b1, b2, b3;
                ldsm4t(b0, b1, b2, b3, vbase + swzi(ksj + rowVg, nd * 16 + cV) * 2);
                unsigned lo[2] = {b0, b1}, hi[2] = {b2, b3};
                mma16(accO[nd * 2], a, lo);
                mma16(accO[nd * 2 + 1], a, hi);
            }
        }
    }
    float inv0 = 1.f / l_run[0], inv1 = 1.f / l_run[1];
    #pragma unroll
    for (int nt = 0; nt < 8; nt++) {
        int dh = nt * 8 + 2 * cc;
        *(unsigned*)&g_atth[((size_t)b * Nv + i0 + w16 + r) * (Hv * DHv) + h * DHv + dh] =
            cvt2h2(accO[nt][0] * inv0, accO[nt][1] * inv0);
        *(unsigned*)&g_atth[((size_t)b * Nv + i0 + w16 + r + 8) * (Hv * DHv) + h * DHv + dh] =
            cvt2h2(accO[nt][2] * inv1, accO[nt][3] * inv1);
    }
}

// ---------------- K6: final out = att @ Wo^T, * seq_mask (fp16 mma) --------
__global__ __launch_bounds__(256) void out_kernel(const float* __restrict__ Wo,
                                                  const float* __restrict__ seq_mask,
                                                  float* __restrict__ out) {
    int c0 = blockIdx.x * 128;
    int m0 = blockIdx.y * 128;
    const float* W = Wo + (size_t)c0 * (Hv * DHv);
    __shared__ __half Ah[128 * 64], Wh[128 * 64];
    int tid = threadIdx.x;
    int lane = tid & 31, w = tid >> 5;
    int wm = w & 3, wn = w >> 2;
    int r = lane >> 2, cc = lane & 3;
    int g = lane >> 3, l8 = lane & 7;
    unsigned abase = sptr(Ah), wbase = sptr(Wh);
    float acc[2][8][4] = {};
    int rowA0 = wm * 32 + ((g & 1) << 3) + l8;
    int cA = (g >> 1) << 3;
    int rowB0 = wn * 64 + ((g >> 1) << 3) + l8;
    int cB = (g & 1) << 3;
    const int K = Hv * DHv;

    for (int kk = 0; kk < K; kk += 64) {
        __syncthreads();
        #pragma unroll
        for (int it = 0; it < 4; it++) {
            int idx = it * 256 + tid;
            int rr = idx >> 3, c8 = (idx & 7) << 3;
            *(uint4*)&Ah[swzi(rr, c8)] =
                *(const uint4*)(g_atth + (size_t)(m0 + rr) * K + kk + c8);
            const float* ws = W + (size_t)rr * K + kk + c8;
            float4 w0 = *(const float4*)ws, w1 = *(const float4*)(ws + 4);
            *(uint4*)&Wh[swzi(rr, c8)] =
                make_uint4(cvt2h2(w0.x, w0.y), cvt2h2(w0.z, w0.w),
                           cvt2h2(w1.x, w1.y), cvt2h2(w1.z, w1.w));
        }
        __syncthreads();
        #pragma unroll
        for (int ks = 0; ks < 64; ks += 16) {
            unsigned a[2][4];
            ldsm4(a[0][0], a[0][1], a[0][2], a[0][3], abase + swzi(rowA0, ks + cA) * 2);
            ldsm4(a[1][0], a[1][1], a[1][2], a[1][3], abase + swzi(rowA0 + 16, ks + cA) * 2);
            #pragma unroll
            for (int n16 = 0; n16 < 4; n16++) {
                unsigned b0, b1, b2, b3;
                ldsm4(b0, b1, b2, b3, wbase + swzi(rowB0 + n16 * 16, ks + cB) * 2);
                unsigned lo[2] = {b0, b1}, hi[2] = {b2, b3};
                mma16(acc[0][n16 * 2], a[0], lo); mma16(acc[0][n16 * 2 + 1], a[0], hi);
                mma16(acc[1][n16 * 2], a[1], lo); mma16(acc[1][n16 * 2 + 1], a[1], hi);
            }
        }
    }
    #pragma unroll
    for (int f = 0; f < 2; f++) {
        int row0 = m0 + wm * 32 + f * 16 + r;
        float mk0 = seq_mask[row0];
        float mk1 = seq_mask[row0 + 8];
        #pragma unroll
        for (int nt = 0; nt < 8; nt++) {
            int col = c0 + wn * 64 + nt * 8 + 2 * cc;
            *(float2*)&out[(size_t)row0 * Dv + col] =
                make_float2(acc[f][nt][0] * mk0, acc[f][nt][1] * mk0);
            *(float2*)&out[(size_t)(row0 + 8) * Dv + col] =
                make_float2(acc[f][nt][2] * mk1, acc[f][nt][3] * mk1);
        }
    }
}

// ---------------- launch ---------------------------------------------------
extern "C" void kernel_launch(void* const* d_in, const int* in_sizes, int n_in,
                              void* d_out, int out_size) {
    const float* x        = (const float*)d_in[0];
    const float* time_in  = (const float*)d_in[1];
    const float* ab       = (const float*)d_in[2];
    const float* seq_mask = (const float*)d_in[3];
    const float* gamma    = (const float*)d_in[4];
    const float* Wt       = (const float*)d_in[5];
    const float* bt       = (const float*)d_in[6];
    const float* Wq       = (const float*)d_in[7];
    const float* Wkv      = (const float*)d_in[8];
    const float* Wo       = (const float*)d_in[9];
    const float* Wb       = (const float*)d_in[10];
    const float* bb       = (const float*)d_in[11];
    float* out = (float*)d_out;

    static bool attr_set = false;
    if (!attr_set) {
        cudaFuncSetAttribute(flash_kernel,
                             cudaFuncAttributeMaxDynamicSharedMemorySize, 32768);
        attr_set = true;
    }

    film_kernel<<<dim3(Bv, 8), 128>>>(time_in, Wt, bt);
    ln_film_kernel<<<Bv * Nv, 128>>>(x, seq_mask, gamma);
    qkv_bias_kernel<<<384 + 8192, 256>>>(x, Wq, Wkv, ab, seq_mask, Wb, bb);
    flash_kernel<<<dim3(8, Hv, Bv), 256, 32768>>>();
    out_kernel<<<dim3(4, 32), 256>>>(Wo, seq_mask, out);
}

// round 15
// speedup vs baseline: 5.0471x; 1.0080x over previous
#include <cuda_runtime.h>
#include <cuda_fp16.h>
#include <cuda_bf16.h>
#include <math.h>

#define Bv 4
#define Nv 1024
#define Dv 512
#define Hv 8
#define DHv 64
#define TCv 512
#define ABv 16

// ---------------- scratch -------------------------------------------------
__device__ float g_scale[Bv * Dv];
__device__ float g_shift[Bv * Dv];
__device__ __half g_xnh[(size_t)Bv * Nv * Dv];        // LN+FiLM output (fp16)
__device__ __half g_qh[(size_t)Bv * Hv * Nv * DHv];   // pre-scaled by DH^-0.5
__device__ __half g_kh[(size_t)Bv * Hv * Nv * DHv];
__device__ __half g_vh[(size_t)Bv * Hv * Nv * DHv];
__device__ __nv_bfloat16 g_sim[(size_t)Bv * Hv * Nv * Nv];  // bias + penalty (bf16)
__device__ __half g_atth[(size_t)Bv * Nv * Hv * DHv]; // attention output (fp16)

// ---------------- helpers ---------------------------------------------------
__device__ __forceinline__ unsigned sptr(const void* p) {
    return (unsigned)__cvta_generic_to_shared(p);
}
__device__ __forceinline__ unsigned cvt2h2(float lo, float hi) {
    __half2 h = __floats2half2_rn(lo, hi);
    return *reinterpret_cast<unsigned*>(&h);
}
// swizzled half index within a [rows][64] half tile (128B rows, 16B chunks)
__device__ __forceinline__ int swzi(int r, int c) {
    return (r << 6) + ((((c >> 3) ^ (r & 7))) << 3) + (c & 7);
}
__device__ __forceinline__ void mma16(float* c, const unsigned* a, const unsigned* b) {
    asm volatile("mma.sync.aligned.m16n8k16.row.col.f32.f16.f16.f32 "
        "{%0,%1,%2,%3}, {%4,%5,%6,%7}, {%8,%9}, {%0,%1,%2,%3};"
        : "+f"(c[0]), "+f"(c[1]), "+f"(c[2]), "+f"(c[3])
        : "r"(a[0]), "r"(a[1]), "r"(a[2]), "r"(a[3]), "r"(b[0]), "r"(b[1]));
}
__device__ __forceinline__ void ldsm4(unsigned& r0, unsigned& r1, unsigned& r2,
                                      unsigned& r3, unsigned addr) {
    asm volatile("ldmatrix.sync.aligned.m8n8.x4.shared.b16 {%0,%1,%2,%3}, [%4];"
        : "=r"(r0), "=r"(r1), "=r"(r2), "=r"(r3) : "r"(addr));
}
__device__ __forceinline__ void ldsm4t(unsigned& r0, unsigned& r1, unsigned& r2,
                                       unsigned& r3, unsigned addr) {
    asm volatile("ldmatrix.sync.aligned.m8n8.x4.trans.shared.b16 {%0,%1,%2,%3}, [%4];"
        : "=r"(r0), "=r"(r1), "=r"(r2), "=r"(r3) : "r"(addr));
}
__device__ __forceinline__ float2 bf2f2(unsigned u) {
    __nv_bfloat162 b = *reinterpret_cast<__nv_bfloat162*>(&u);
    return __bfloat1622float2(b);
}
__device__ __forceinline__ void cpa16(unsigned dst, const void* src) {
    asm volatile("cp.async.cg.shared.global [%0], [%1], 16;" :: "r"(dst), "l"(src));
}

// ---------------- K1: FiLM params ------------------------------------------
__global__ void film_kernel(const float* __restrict__ time,
                            const float* __restrict__ Wt,
                            const float* __restrict__ bt) {
    int b = blockIdx.x;
    int o = blockIdx.y * 128 + threadIdx.x;
    __shared__ float st[TCv];
    for (int i = threadIdx.x; i < TCv; i += 128) {
        float v = time[b * TCv + i];
        st[i] = v / (1.f + __expf(-v));
    }
    __syncthreads();
    const float* w = Wt + (size_t)o * TCv;
    float acc = bt[o];
    #pragma unroll 8
    for (int t = 0; t < TCv; t++) acc = fmaf(st[t], w[t], acc);
    if (o < Dv) g_scale[b * Dv + o] = acc;
    else        g_shift[b * Dv + (o - Dv)] = acc;
}

// ---------------- K2: LayerNorm + FiLM + seq mask -> g_xnh (fp16) ----------
__global__ void ln_film_kernel(const float* __restrict__ x,
                               const float* __restrict__ seq_mask,
                               const float* __restrict__ gamma) {
    int row = blockIdx.x;
    int b = row >> 10;
    const float* xr = x + (size_t)row * Dv;
    int tid = threadIdx.x;
    float s = 0.f, ss = 0.f;
    #pragma unroll
    for (int u = 0; u < 4; u++) {
        float v = xr[tid + u * 128];
        s += v; ss += v * v;
    }
    #pragma unroll
    for (int o = 16; o > 0; o >>= 1) {
        s  += __shfl_xor_sync(~0u, s, o);
        ss += __shfl_xor_sync(~0u, ss, o);
    }
    __shared__ float shs[4], shss[4];
    if ((tid & 31) == 0) { shs[tid >> 5] = s; shss[tid >> 5] = ss; }
    __syncthreads();
    s  = shs[0] + shs[1] + shs[2] + shs[3];
    ss = shss[0] + shss[1] + shss[2] + shss[3];
    float mu  = s * (1.f / Dv);
    float var = ss * (1.f / Dv) - mu * mu;
    float inv = rsqrtf(var + 1e-5f);
    float m = seq_mask[row];
    __half* out = g_xnh + (size_t)row * Dv;
    #pragma unroll
    for (int u = 0; u < 4; u++) {
        int d = tid + u * 128;
        float v = (xr[d] - mu) * inv * gamma[d];
        out[d] = __float2half((v * (g_scale[b * Dv + d] + 1.f) + g_shift[b * Dv + d]) * m);
    }
}

// ---------------- K3: merged QKV projections + bias projection -------------
__global__ __launch_bounds__(256) void qkv_bias_kernel(
        const float* __restrict__ x,
        const float* __restrict__ Wq,
        const float* __restrict__ Wkv,
        const float* __restrict__ ab,
        const float* __restrict__ seq_mask,
        const float* __restrict__ Wb,
        const float* __restrict__ bb) {
    int bid = blockIdx.x;
    int tid = threadIdx.x;
    if (bid < 384) {
        // ======== QKV GEMM part ========
        int c0 = (bid % 12) * 128;
        int m0 = (bid / 12) * 128;
        int seg = c0 >> 9;            // 0:q 1:k 2:v
        const float* W = (seg == 0) ? (Wq + (size_t)c0 * Dv)
                                    : (Wkv + (size_t)(c0 - 512) * Dv);
        __shared__ __half Ah[128 * 64], Wh[128 * 64];
        int lane = tid & 31, w = tid >> 5;
        int wm = w & 3, wn = w >> 2;
        int r = lane >> 2, cc = lane & 3;
        int g = lane >> 3, l8 = lane & 7;
        unsigned abase = sptr(Ah), wbase = sptr(Wh);
        float acc[2][8][4] = {};
        int rowA0 = wm * 32 + ((g & 1) << 3) + l8;
        int cA = (g >> 1) << 3;
        int rowB0 = wn * 64 + ((g >> 1) << 3) + l8;
        int cB = (g & 1) << 3;

        for (int kk = 0; kk < Dv; kk += 64) {
            __syncthreads();
            #pragma unroll
            for (int it = 0; it < 4; it++) {
                int idx = it * 256 + tid;
                int rr = idx >> 3, c8 = (idx & 7) << 3;
                if (seg == 0) {
                    *(uint4*)&Ah[swzi(rr, c8)] =
                        *(const uint4*)(g_xnh + (size_t)(m0 + rr) * Dv + kk + c8);
                } else {
                    const float* as = x + (size_t)(m0 + rr) * Dv + kk + c8;
                    float4 a0 = *(const float4*)as, a1 = *(const float4*)(as + 4);
                    *(uint4*)&Ah[swzi(rr, c8)] =
                        make_uint4(cvt2h2(a0.x, a0.y), cvt2h2(a0.z, a0.w),
                                   cvt2h2(a1.x, a1.y), cvt2h2(a1.z, a1.w));
                }
                const float* ws = W + (size_t)rr * Dv + kk + c8;
                float4 w0 = *(const float4*)ws, w1 = *(const float4*)(ws + 4);
                *(uint4*)&Wh[swzi(rr, c8)] =
                    make_uint4(cvt2h2(w0.x, w0.y), cvt2h2(w0.z, w0.w),
                               cvt2h2(w1.x, w1.y), cvt2h2(w1.z, w1.w));
            }
            __syncthreads();
            #pragma unroll
            for (int ks = 0; ks < 64; ks += 16) {
                unsigned a[2][4];
                ldsm4(a[0][0], a[0][1], a[0][2], a[0][3], abase + swzi(rowA0, ks + cA) * 2);
                ldsm4(a[1][0], a[1][1], a[1][2], a[1][3], abase + swzi(rowA0 + 16, ks + cA) * 2);
                #pragma unroll
                for (int n16 = 0; n16 < 4; n16++) {
                    unsigned b0, b1, b2, b3;
                    ldsm4(b0, b1, b2, b3, wbase + swzi(rowB0 + n16 * 16, ks + cB) * 2);
                    unsigned lo[2] = {b0, b1}, hi[2] = {b2, b3};
                    mma16(acc[0][n16 * 2], a[0], lo); mma16(acc[0][n16 * 2 + 1], a[0], hi);
                    mma16(acc[1][n16 * 2], a[1], lo); mma16(acc[1][n16 * 2 + 1], a[1], hi);
                }
            }
        }
        __half* dst = (seg == 0) ? g_qh : (seg == 1) ? g_kh : g_vh;
        float qs = (seg == 0) ? 0.125f : 1.0f;
        int colbase = (c0 & 511) + wn * 64;
        int h = colbase >> 6;
        #pragma unroll
        for (int f = 0; f < 2; f++) {
            int row0 = m0 + wm * 32 + f * 16 + r;
            int b0i = row0 >> 10, n0 = row0 & 1023;
            int b1i = (row0 + 8) >> 10, n1 = (row0 + 8) & 1023;
            #pragma unroll
            for (int nt = 0; nt < 8; nt++) {
                int dh = nt * 8 + 2 * cc;
                *(unsigned*)&dst[(((size_t)b0i * Hv + h) * Nv + n0) * DHv + dh] =
                    cvt2h2(acc[f][nt][0] * qs, acc[f][nt][1] * qs);
                *(unsigned*)&dst[(((size_t)b1i * Hv + h) * Nv + n1) * DHv + dh] =
                    cvt2h2(acc[f][nt][2] * qs, acc[f][nt][3] * qs);
            }
        }
    } else {
        // ======== bias projection + penalty part ========
        __shared__ float wb[Hv * ABv];
        __shared__ float sbb[Hv];
        if (tid < Hv * ABv) wb[tid] = Wb[tid];
        if (tid < Hv) sbb[tid] = bb[tid];
        __syncthreads();
        size_t idx = (size_t)(bid - 384) * 256 + tid;
        int j = (int)(idx & 511) << 1;
        int i = (int)((idx >> 9) & 1023);
        int b = (int)(idx >> 19);
        const float* p = ab + ((size_t)b * ABv * Nv + i) * Nv + j;
        float2 a[ABv];
        #pragma unroll
        for (int aa = 0; aa < ABv; aa++) a[aa] = *(const float2*)(p + (size_t)aa * Nv * Nv);
        float smi = seq_mask[b * Nv + i];
        float2 smj = *(const float2*)&seq_mask[b * Nv + j];
        float pen0 = -(1.f - smi * smj.x) * 1e6f;
        float pen1 = -(1.f - smi * smj.y) * 1e6f;
        #pragma unroll
        for (int h = 0; h < Hv; h++) {
            float ax = sbb[h] + pen0, ay = sbb[h] + pen1;
            #pragma unroll
            for (int aa = 0; aa < ABv; aa++) {
                ax = fmaf(a[aa].x, wb[h * ABv + aa], ax);
                ay = fmaf(a[aa].y, wb[h * ABv + aa], ay);
            }
            __nv_bfloat162 o = __floats2bfloat162_rn(ax, ay);
            *(__nv_bfloat162*)&g_sim[(((size_t)b * Hv + h) * Nv + i) * Nv + j] = o;
        }
    }
}

// ---------------- K5: fused flash (fp16 mma, cp.async, register P) ---------
// 128 threads / 4 warps; i-tile 64, j-tile 64 double-buffered. 32 KB dyn smem.
// Q fragments in registers; P stays in registers (C-frag == A-frag).
__global__ __launch_bounds__(128, 4) void flash_kernel() {
    extern __shared__ __half smf[];
    int tid = threadIdx.x;
    int lane = tid & 31, w = tid >> 5;      // w 0..3
    int w16 = w * 16;
    int r = lane >> 2, cc = lane & 3;
    int g = lane >> 3, l8 = lane & 7;
    int i0 = blockIdx.x * 64;
    int h = blockIdx.y, b = blockIdx.z;
    int bh = b * Hv + h;
    const __half* qp = g_qh + ((size_t)bh * Nv + i0) * DHv;
    const __half* kp = g_kh + (size_t)bh * Nv * DHv;
    const __half* vp = g_vh + (size_t)bh * Nv * DHv;
    const __nv_bfloat16* simp = g_sim + ((size_t)bh * Nv + i0) * Nv;
    unsigned kb0 = sptr(smf);             // K buffers: 2 x 8192 B
    unsigned vb0 = sptr(smf + 8192);      // V buffers: 2 x 8192 B (byte 16384)

    // Q fragments: direct half2 LDGs in A-fragment layout (jt-invariant)
    unsigned qfrag[4][4];
    #pragma unroll
    for (int t = 0; t < 4; t++) {
        int ks = t * 16;
        qfrag[t][0] = *(const unsigned*)(qp + (w16 + r) * DHv + ks + 2 * cc);
        qfrag[t][1] = *(const unsigned*)(qp + (w16 + r + 8) * DHv + ks + 2 * cc);
        qfrag[t][2] = *(const unsigned*)(qp + (w16 + r) * DHv + ks + 8 + 2 * cc);
        qfrag[t][3] = *(const unsigned*)(qp + (w16 + r + 8) * DHv + ks + 8 + 2 * cc);
    }

    // prologue: async K/V loads for jt=0 into buffer 0
    #pragma unroll
    for (int it = 0; it < 4; it++) {
        int idx = it * 128 + tid;
        int rr = idx >> 3, c8 = (idx & 7) << 3;
        cpa16(kb0 + swzi(rr, c8) * 2, kp + (size_t)rr * DHv + c8);
        cpa16(vb0 + swzi(rr, c8) * 2, vp + (size_t)rr * DHv + c8);
    }
    asm volatile("cp.async.commit_group;" ::: "memory");

    float m_run[2] = {-3.0e38f, -3.0e38f};
    float l_run[2] = {0.f, 0.f};
    float accO[8][4] = {};
    int rowBb = ((g >> 1) << 3) + l8;           // B-frag rows (K)
    int cB = (g & 1) << 3;
    int rowVg = ((g & 1) << 3) + l8;            // V trans rows (k=j)
    int cV = (g >> 1) << 3;                     // V trans col group (n=dh)

    for (int jt = 0; jt < 16; jt++) {
        int j0 = jt * 64;
        int bi = jt & 1;
        unsigned kbase = kb0 + bi * 8192;
        unsigned vbase = vb0 + bi * 8192;
        // bias prefetch (fragment layout, bf16x2) — consumed after QK
        unsigned biasu0[8], biasu1[8];
        #pragma unroll
        for (int nt = 0; nt < 8; nt++) {
            biasu0[nt] = *(const unsigned*)(simp + (size_t)(w16 + r) * Nv + j0 + nt * 8 + 2 * cc);
            biasu1[nt] = *(const unsigned*)(simp + (size_t)(w16 + r + 8) * Nv + j0 + nt * 8 + 2 * cc);
        }
        asm volatile("cp.async.wait_group 0;" ::: "memory");
        __syncthreads();
        if (jt < 15) {     // async loads for jt+1 into the other buffer
            unsigned kn = kb0 + (bi ^ 1) * 8192;
            unsigned vn = vb0 + (bi ^ 1) * 8192;
            const __half* kpn = kp + (size_t)(j0 + 64) * DHv;
            const __half* vpn = vp + (size_t)(j0 + 64) * DHv;
            #pragma unroll
            for (int it = 0; it < 4; it++) {
                int idx = it * 128 + tid;
                int rr = idx >> 3, c8 = (idx & 7) << 3;
                cpa16(kn + swzi(rr, c8) * 2, kpn + (size_t)rr * DHv + c8);
                cpa16(vn + swzi(rr, c8) * 2, vpn + (size_t)rr * DHv + c8);
            }
            asm volatile("cp.async.commit_group;" ::: "memory");
        }
        // ---- QK ----
        float accS[8][4] = {};
        #pragma unroll
        for (int t = 0; t < 4; t++) {
            int ks = t * 16;
            #pragma unroll
            for (int n16 = 0; n16 < 4; n16++) {
                unsigned b0, b1, b2, b3;
                ldsm4(b0, b1, b2, b3, kbase + swzi(n16 * 16 + rowBb, ks + cB) * 2);
                unsigned lo[2] = {b0, b1}, hi[2] = {b2, b3};
                mma16(accS[n16 * 2], qfrag[t], lo);
                mma16(accS[n16 * 2 + 1], qfrag[t], hi);
            }
        }
        // ---- bias add + online softmax (rows r, r+8; 4-lane reduce) ----
        float mx0 = -3.0e38f, mx1 = -3.0e38f;
        #pragma unroll
        for (int nt = 0; nt < 8; nt++) {
            float2 bias0 = bf2f2(biasu0[nt]);
            float2 bias1 = bf2f2(biasu1[nt]);
            accS[nt][0] += bias0.x; accS[nt][1] += bias0.y;
            accS[nt][2] += bias1.x; accS[nt][3] += bias1.y;
            mx0 = fmaxf(mx0, fmaxf(accS[nt][0], accS[nt][1]));
            mx1 = fmaxf(mx1, fmaxf(accS[nt][2], accS[nt][3]));
        }
        mx0 = fmaxf(mx0, __shfl_xor_sync(~0u, mx0, 1));
        mx0 = fmaxf(mx0, __shfl_xor_sync(~0u, mx0, 2));
        mx1 = fmaxf(mx1, __shfl_xor_sync(~0u, mx1, 1));
        mx1 = fmaxf(mx1, __shfl_xor_sync(~0u, mx1, 2));
        float nm0 = fmaxf(m_run[0], mx0), nm1 = fmaxf(m_run[1], mx1);
        float al0 = __expf(m_run[0] - nm0), al1 = __expf(m_run[1] - nm1);
        m_run[0] = nm0; m_run[1] = nm1;
        float s0 = 0.f, s1 = 0.f;
        #pragma unroll
        for (int nt = 0; nt < 8; nt++) {
            accS[nt][0] = __expf(accS[nt][0] - nm0); s0 += accS[nt][0];
            accS[nt][1] = __expf(accS[nt][1] - nm0); s0 += accS[nt][1];
            accS[nt][2] = __expf(accS[nt][2] - nm1); s1 += accS[nt][2];
            accS[nt][3] = __expf(accS[nt][3] - nm1); s1 += accS[nt][3];
        }
        s0 += __shfl_xor_sync(~0u, s0, 1); s0 += __shfl_xor_sync(~0u, s0, 2);
        s1 += __shfl_xor_sync(~0u, s1, 1); s1 += __shfl_xor_sync(~0u, s1, 2);
        l_run[0] = l_run[0] * al0 + s0;
        l_run[1] = l_run[1] * al1 + s1;
        #pragma unroll
        for (int nt = 0; nt < 8; nt++) {
            accO[nt][0] *= al0; accO[nt][1] *= al0;
            accO[nt][2] *= al1; accO[nt][3] *= al1;
        }
        // ---- AV: P stays in registers (C-frag == A-frag layout, j -> k) ----
        #pragma unroll
        for (int t = 0; t < 4; t++) {
            unsigned a[4];
            a[0] = cvt2h2(accS[2 * t][0],     accS[2 * t][1]);
            a[1] = cvt2h2(accS[2 * t][2],     accS[2 * t][3]);
            a[2] = cvt2h2(accS[2 * t + 1][0], accS[2 * t + 1][1]);
            a[3] = cvt2h2(accS[2 * t + 1][2], accS[2 * t + 1][3]);
            int ksj = t * 16;
            #pragma unroll
            for (int nd = 0; nd < 4; nd++) {
                unsigned b0, b1, b2, b3;
                ldsm4t(b0, b1, b2, b3, vbase + swzi(ksj + rowVg, nd * 16 + cV) * 2);
                unsigned lo[2] = {b0, b1}, hi[2] = {b2, b3};
                mma16(accO[nd * 2], a, lo);
                mma16(accO[nd * 2 + 1], a, hi);
            }
        }
    }
    float inv0 = 1.f / l_run[0], inv1 = 1.f / l_run[1];
    #pragma unroll
    for (int nt = 0; nt < 8; nt++) {
        int dh = nt * 8 + 2 * cc;
        *(unsigned*)&g_atth[((size_t)b * Nv + i0 + w16 + r) * (Hv * DHv) + h * DHv + dh] =
            cvt2h2(accO[nt][0] * inv0, accO[nt][1] * inv0);
        *(unsigned*)&g_atth[((size_t)b * Nv + i0 + w16 + r + 8) * (Hv * DHv) + h * DHv + dh] =
            cvt2h2(accO[nt][2] * inv1, accO[nt][3] * inv1);
    }
}

// ---------------- K6: final out = att @ Wo^T, * seq_mask (fp16 mma) --------
__global__ __launch_bounds__(256) void out_kernel(const float* __restrict__ Wo,
                                                  const float* __restrict__ seq_mask,
                                                  float* __restrict__ out) {
    int c0 = blockIdx.x * 128;
    int m0 = blockIdx.y * 128;
    const float* W = Wo + (size_t)c0 * (Hv * DHv);
    __shared__ __half Ah[128 * 64], Wh[128 * 64];
    int tid = threadIdx.x;
    int lane = tid & 31, w = tid >> 5;
    int wm = w & 3, wn = w >> 2;
    int r = lane >> 2, cc = lane & 3;
    int g = lane >> 3, l8 = lane & 7;
    unsigned abase = sptr(Ah), wbase = sptr(Wh);
    float acc[2][8][4] = {};
    int rowA0 = wm * 32 + ((g & 1) << 3) + l8;
    int cA = (g >> 1) << 3;
    int rowB0 = wn * 64 + ((g >> 1) << 3) + l8;
    int cB = (g & 1) << 3;
    const int K = Hv * DHv;

    for (int kk = 0; kk < K; kk += 64) {
        __syncthreads();
        #pragma unroll
        for (int it = 0; it < 4; it++) {
            int idx = it * 256 + tid;
            int rr = idx >> 3, c8 = (idx & 7) << 3;
            *(uint4*)&Ah[swzi(rr, c8)] =
                *(const uint4*)(g_atth + (size_t)(m0 + rr) * K + kk + c8);
            const float* ws = W + (size_t)rr * K + kk + c8;
            float4 w0 = *(const float4*)ws, w1 = *(const float4*)(ws + 4);
            *(uint4*)&Wh[swzi(rr, c8)] =
                make_uint4(cvt2h2(w0.x, w0.y), cvt2h2(w0.z, w0.w),
                           cvt2h2(w1.x, w1.y), cvt2h2(w1.z, w1.w));
        }
        __syncthreads();
        #pragma unroll
        for (int ks = 0; ks < 64; ks += 16) {
            unsigned a[2][4];
            ldsm4(a[0][0], a[0][1], a[0][2], a[0][3], abase + swzi(rowA0, ks + cA) * 2);
            ldsm4(a[1][0], a[1][1], a[1][2], a[1][3], abase + swzi(rowA0 + 16, ks + cA) * 2);
            #pragma unroll
            for (int n16 = 0; n16 < 4; n16++) {
                unsigned b0, b1, b2, b3;
                ldsm4(b0, b1, b2, b3, wbase + swzi(rowB0 + n16 * 16, ks + cB) * 2);
                unsigned lo[2] = {b0, b1}, hi[2] = {b2, b3};
                mma16(acc[0][n16 * 2], a[0], lo); mma16(acc[0][n16 * 2 + 1], a[0], hi);
                mma16(acc[1][n16 * 2], a[1], lo); mma16(acc[1][n16 * 2 + 1], a[1], hi);
            }
        }
    }
    #pragma unroll
    for (int f = 0; f < 2; f++) {
        int row0 = m0 + wm * 32 + f * 16 + r;
        float mk0 = seq_mask[row0];
        float mk1 = seq_mask[row0 + 8];
        #pragma unroll
        for (int nt = 0; nt < 8; nt++) {
            int col = c0 + wn * 64 + nt * 8 + 2 * cc;
            *(float2*)&out[(size_t)row0 * Dv + col] =
                make_float2(acc[f][nt][0] * mk0, acc[f][nt][1] * mk0);
            *(float2*)&out[(size_t)(row0 + 8) * Dv + col] =
                make_float2(acc[f][nt][2] * mk1, acc[f][nt][3] * mk1);
        }
    }
}

// ---------------- launch ---------------------------------------------------
extern "C" void kernel_launch(void* const* d_in, const int* in_sizes, int n_in,
                              void* d_out, int out_size) {
    const float* x        = (const float*)d_in[0];
    const float* time_in  = (const float*)d_in[1];
    const float* ab       = (const float*)d_in[2];
    const float* seq_mask = (const float*)d_in[3];
    const float* gamma    = (const float*)d_in[4];
    const float* Wt       = (const float*)d_in[5];
    const float* bt       = (const float*)d_in[6];
    const float* Wq       = (const float*)d_in[7];
    const float* Wkv      = (const float*)d_in[8];
    const float* Wo       = (const float*)d_in[9];
    const float* Wb       = (const float*)d_in[10];
    const float* bb       = (const float*)d_in[11];
    float* out = (float*)d_out;

    static bool attr_set = false;
    if (!attr_set) {
        cudaFuncSetAttribute(flash_kernel,
                             cudaFuncAttributeMaxDynamicSharedMemorySize, 32768);
        attr_set = true;
    }

    film_kernel<<<dim3(Bv, 8), 128>>>(time_in, Wt, bt);
    ln_film_kernel<<<Bv * Nv, 128>>>(x, seq_mask, gamma);
    qkv_bias_kernel<<<384 + 8192, 256>>>(x, Wq, Wkv, ab, seq_mask, Wb, bb);
    flash_kernel<<<dim3(16, Hv, Bv), 128, 32768>>>();
    out_kernel<<<dim3(4, 32), 256>>>(Wo, seq_mask, out);
}